// round 5
// baseline (speedup 1.0000x reference)
#include <cuda_runtime.h>
#include <math.h>
#include <float.h>
#include <stdint.h>

// ---------------- problem constants ----------------
#define Bb 2
#define Tt 2048
#define DM 2048
#define Hh 16
#define HD 128
#define KVL 512
#define QL 1024
#define Rr 64
#define MROWS (Bb*Tt)        // 4096
#define BH (Bb*Hh)           // 32

#if defined(__CUDA_ARCH_FEAT_SM103_ALL) || defined(__CUDA_ARCH_FEAT_SM100_ALL)
#define HAS_TCGEN05 1
#else
#define HAS_TCGEN05 0
#endif

// ---------------- scratch (device globals) ----------
__device__ float g_Kc[MROWS * (Hh*HD)];
__device__ float g_V [MROWS * (Hh*HD)];
__device__ float g_Vt[BH * HD * Tt];      // per-head V^T: [bh][d][t]
__device__ float g_cQ[MROWS * QL];
__device__ float g_Qc[MROWS * (Hh*HD)];
__device__ float g_Qr[MROWS * (Hh*Rr)];
__device__ float g_KR[MROWS * Rr];
__device__ float g_AO[MROWS * (Hh*HD)];
__device__ float g_S [(size_t)BH * Tt * Tt];   // scores/probs, 536 MB
// transposed weights (concatenated)
#define O_DKV 0
#define O_UK  (O_DKV + 512*2048)
#define O_UV  (O_UK  + 2048*512)
#define O_KR  (O_UV  + 2048*512)
#define O_DQ  (O_KR  + 64*2048)
#define O_UQ  (O_DQ  + 1024*2048)
#define O_QR  (O_UQ  + 2048*1024)
#define O_O   (O_QR  + 2048*1024)
#define WT_TOTAL (O_O + 2048*2048)
__device__ float g_Wt[WT_TOTAL];

// ---------------- PTX helpers (tcgen05 gated) ----------------
__device__ __forceinline__ uint32_t smem_u32(const void* p) {
    uint32_t a;
    asm("{ .reg .u64 t; cvta.to.shared.u64 t, %1; cvt.u32.u64 %0, t; }"
        : "=r"(a) : "l"(p));
    return a;
}

#if HAS_TCGEN05
__device__ __forceinline__ bool elect1() {
    uint32_t r;
    asm volatile("{\n\t.reg .pred p;\n\telect.sync _|p, 0xFFFFFFFF;\n\t"
                 "selp.b32 %0,1,0,p;\n\t}" : "=r"(r));
    return r != 0;
}
#define MBAR_INIT(a, c) \
    asm volatile("mbarrier.init.shared.b64 [%0], %1;" :: "r"(a), "r"(c) : "memory")
#define MBAR_WAIT(a, ph) do { \
    uint32_t _m = (a), _p = (uint32_t)(ph), _d; \
    asm volatile("{\n\t.reg .pred p;\n\t" \
        "mbarrier.try_wait.parity.acquire.cta.shared::cta.b64 p, [%1], %2;\n\t" \
        "selp.b32 %0,1,0,p;\n\t}" : "=r"(_d) : "r"(_m), "r"(_p) : "memory"); \
    while (!_d) { \
        asm volatile("{\n\t.reg .pred p;\n\t" \
            "mbarrier.try_wait.parity.acquire.cta.shared::cta.b64 p, [%1], %2, 0x989680;\n\t" \
            "selp.b32 %0,1,0,p;\n\t}" : "=r"(_d) : "r"(_m), "r"(_p) : "memory"); \
    } } while (0)
#define T5_COMMIT(a) \
    asm volatile("tcgen05.commit.cta_group::1.mbarrier::arrive::one.shared::cluster.b64 [%0];" \
                 :: "r"(a) : "memory")
#define T5_ALLOC(a, n) \
    asm volatile("tcgen05.alloc.cta_group::1.sync.aligned.shared::cta.b32 [%0], %1;" \
                 :: "r"(a), "r"(n) : "memory")
#define T5_DEALLOC(t, n) \
    asm volatile("tcgen05.dealloc.cta_group::1.sync.aligned.b32 %0, %1;" :: "r"(t), "r"(n))
#define T5_RELINQ() \
    asm volatile("tcgen05.relinquish_alloc_permit.cta_group::1.sync.aligned;")
#define T5_WAIT_LD()   asm volatile("tcgen05.wait::ld.sync.aligned;" ::: "memory")
#define T5_FENCE_AFTER() asm volatile("tcgen05.fence::after_thread_sync;" ::: "memory")
#define FENCE_ASYNC()  asm volatile("fence.proxy.async.shared::cta;" ::: "memory")

#define LDTM_X32(r, addr) \
    asm volatile("tcgen05.ld.sync.aligned.32x32b.x32.b32 " \
        "{%0, %1, %2, %3, %4, %5, %6, %7, %8, %9, %10, %11, %12, %13, %14, %15, " \
        "%16, %17, %18, %19, %20, %21, %22, %23, %24, %25, %26, %27, %28, %29, %30, %31}, [%32];" \
        : "=r"((r)[0]),  "=r"((r)[1]),  "=r"((r)[2]),  "=r"((r)[3]), \
          "=r"((r)[4]),  "=r"((r)[5]),  "=r"((r)[6]),  "=r"((r)[7]), \
          "=r"((r)[8]),  "=r"((r)[9]),  "=r"((r)[10]), "=r"((r)[11]), \
          "=r"((r)[12]), "=r"((r)[13]), "=r"((r)[14]), "=r"((r)[15]), \
          "=r"((r)[16]), "=r"((r)[17]), "=r"((r)[18]), "=r"((r)[19]), \
          "=r"((r)[20]), "=r"((r)[21]), "=r"((r)[22]), "=r"((r)[23]), \
          "=r"((r)[24]), "=r"((r)[25]), "=r"((r)[26]), "=r"((r)[27]), \
          "=r"((r)[28]), "=r"((r)[29]), "=r"((r)[30]), "=r"((r)[31]) \
        : "r"(addr))

__device__ __forceinline__ void mma_tf32(uint32_t d, uint64_t ad, uint64_t bd,
                                         uint32_t idesc, uint32_t en) {
    asm volatile("{\n\t.reg .pred p;\n\tsetp.ne.u32 p, %4, 0;\n\t"
        "tcgen05.mma.cta_group::1.kind::tf32 [%0], %1, %2, %3, p;\n\t}"
        :: "r"(d), "l"(ad), "l"(bd), "r"(idesc), "r"(en) : "memory");
}
__device__ __forceinline__ uint64_t mk_desc(uint32_t addr) {
    // SW128 K-major: layout=2, version=1, SBO=64, LBO=1
    return ((uint64_t)2 << 61) | ((uint64_t)1 << 46) | ((uint64_t)64 << 32)
         | ((uint64_t)1 << 16) | ((addr >> 4) & 0x3FFF);
}
#endif  // HAS_TCGEN05

__device__ __forceinline__ void split2(float v, uint32_t& h, uint32_t& l) {
    uint32_t u = __float_as_uint(v);
    h = u & 0xFFFFE000u;                         // exact tf32 truncation
    l = __float_as_uint(v - __uint_as_float(h)); // exact residual
}
__device__ __forceinline__ void sts128(uint32_t addr, uint32_t a, uint32_t b,
                                       uint32_t c, uint32_t d) {
    asm volatile("st.shared.v4.b32 [%0], {%1,%2,%3,%4};"
                 :: "r"(addr), "r"(a), "r"(b), "r"(c), "r"(d) : "memory");
}

// split a float4 and store hi/lo tiles at swizzled offset
__device__ __forceinline__ void split_sts(uint32_t base_hi, uint32_t base_lo,
                                          int row, int seg, float4 v) {
    uint32_t hx, lx, hy, ly, hz, lz, hw, lw;
    split2(v.x, hx, lx); split2(v.y, hy, ly);
    split2(v.z, hz, lz); split2(v.w, hw, lw);
    uint32_t byte = row * 128 + seg * 16;
    uint32_t sw = byte ^ ((byte >> 3) & 0x70);
    sts128(base_hi + sw, hx, hy, hz, hw);
    sts128(base_lo + sw, lx, ly, lz, lw);
}

// ---------------- weight transpose: Wt[n][k] = W[k][n] ----------------
__global__ __launch_bounds__(256) void transpose_kernel(
    const float* __restrict__ W, float* __restrict__ Wt, int K, int N)
{
    __shared__ float t[32][33];
    int n0 = blockIdx.x * 32, k0 = blockIdx.y * 32;
    #pragma unroll
    for (int i = threadIdx.y; i < 32; i += 8)
        t[i][threadIdx.x] = W[(size_t)(k0 + i) * N + n0 + threadIdx.x];
    __syncthreads();
    #pragma unroll
    for (int i = threadIdx.y; i < 32; i += 8)
        Wt[(size_t)(n0 + i) * K + k0 + threadIdx.x] = t[threadIdx.x][i];
}

// per-head V transpose: Vt[bh][d][t] = V[(b t),(h d)]
__global__ __launch_bounds__(256) void transpose_v_kernel(
    const float* __restrict__ V, float* __restrict__ Vt)
{
    __shared__ float t[32][33];
    int bh = blockIdx.z;
    int b = bh >> 4, h = bh & 15;
    int t0 = blockIdx.x * 32, d0 = blockIdx.y * 32;
    #pragma unroll
    for (int i = threadIdx.y; i < 32; i += 8)
        t[i][threadIdx.x] = V[(size_t)(b * Tt + t0 + i) * (Hh*HD) + h * HD + d0 + threadIdx.x];
    __syncthreads();
    #pragma unroll
    for (int i = threadIdx.y; i < 32; i += 8)
        Vt[((size_t)bh * HD + d0 + i) * Tt + t0 + threadIdx.x] = t[threadIdx.x][i];
}

// ---------------- GEMM: C[M,N] = A[M,K] @ Bt[N,K]^T (tf32x3) ----------------
template<int TN>
__global__ __launch_bounds__(128) void tgemm_kernel(
    const float* __restrict__ A, const float* __restrict__ Bt,
    float* __restrict__ C, int N, int K)
{
#if HAS_TCGEN05
    constexpr int A_BYTES = 128 * 128;
    constexpr int B_BYTES = TN * 128;
    constexpr int STAGE = 2 * A_BYTES + 2 * B_BYTES;
    extern __shared__ char smem[];
    const uint32_t sbase = smem_u32(smem);
    const uint32_t mb_empty = sbase;
    const uint32_t mb_done  = sbase + 24;
    const uint32_t tmem_slot = sbase + 32;
    const uint32_t tiles = (sbase + 64 + 1023) & ~1023u;

    const int tid = threadIdx.x;
    const int bm = blockIdx.y * 128, bn = blockIdx.x * TN;

    if (tid == 0) {
        MBAR_INIT(mb_empty + 0, 1);
        MBAR_INIT(mb_empty + 8, 1);
        MBAR_INIT(mb_empty + 16, 1);
        MBAR_INIT(mb_done, 1);
    }
    if (tid < 32) { T5_ALLOC(tmem_slot, 128); T5_RELINQ(); }
    __syncthreads();
    uint32_t tmem;
    asm volatile("ld.shared.b32 %0, [%1];" : "=r"(tmem) : "r"(tmem_slot));

    const uint32_t idesc = (1u << 4) | (2u << 7) | (2u << 10)
                         | ((uint32_t)(TN / 8) << 17) | (8u << 24);
    const int nc = K >> 5;

    for (int c = 0; c < nc; c++) {
        const int s = c - (c / 3) * 3;
        const uint32_t st = tiles + s * STAGE;
        if (c >= 3) MBAR_WAIT(mb_empty + 8 * s, ((c / 3) - 1) & 1);
        const int k0 = c * 32;
        #pragma unroll
        for (int i = 0; i < 8; i++) {
            int idx = i * 128 + tid;
            int row = idx >> 3, seg = idx & 7;
            float4 v = *reinterpret_cast<const float4*>(
                &A[(size_t)(bm + row) * K + k0 + seg * 4]);
            split_sts(st, st + A_BYTES, row, seg, v);
        }
        #pragma unroll
        for (int i = 0; i < TN / 16; i++) {
            int idx = i * 128 + tid;
            int row = idx >> 3, seg = idx & 7;
            float4 v = *reinterpret_cast<const float4*>(
                &Bt[(size_t)(bn + row) * K + k0 + seg * 4]);
            split_sts(st + 2 * A_BYTES, st + 2 * A_BYTES + B_BYTES, row, seg, v);
        }
        FENCE_ASYNC();
        __syncthreads();
        if (tid < 32 && elect1()) {
            uint64_t ah = mk_desc(st);
            uint64_t al = mk_desc(st + A_BYTES);
            uint64_t bh = mk_desc(st + 2 * A_BYTES);
            uint64_t bl = mk_desc(st + 2 * A_BYTES + B_BYTES);
            #pragma unroll
            for (int q = 0; q < 4; q++)
                mma_tf32(tmem, ah + 2 * q, bh + 2 * q, idesc,
                         (c == 0 && q == 0) ? 0u : 1u);
            #pragma unroll
            for (int q = 0; q < 4; q++)
                mma_tf32(tmem, ah + 2 * q, bl + 2 * q, idesc, 1u);
            #pragma unroll
            for (int q = 0; q < 4; q++)
                mma_tf32(tmem, al + 2 * q, bh + 2 * q, idesc, 1u);
            T5_COMMIT(mb_empty + 8 * s);
        }
    }
    if (tid < 32 && elect1()) T5_COMMIT(mb_done);
    MBAR_WAIT(mb_done, 0);
    T5_FENCE_AFTER();

    const int wid = tid >> 5, lid = tid & 31;
    const size_t rowoff = (size_t)(bm + wid * 32 + lid) * N + bn;
    #pragma unroll
    for (int b2 = 0; b2 < TN / 32; b2++) {
        uint32_t r[32];
        LDTM_X32(r, tmem + b2 * 32);
        T5_WAIT_LD();
        #pragma unroll
        for (int j = 0; j < 32; j += 4) {
            float4 o = make_float4(__uint_as_float(r[j]), __uint_as_float(r[j + 1]),
                                   __uint_as_float(r[j + 2]), __uint_as_float(r[j + 3]));
            *reinterpret_cast<float4*>(&C[rowoff + b2 * 32 + j]) = o;
        }
    }
    __syncthreads();
    if (tid < 32) T5_DEALLOC(tmem, 128);
#else
    // naive fallback (compiles on plain targets; never runs on GB300)
    const int tid = threadIdx.x;
    const int bm = blockIdx.y * 128, bn = blockIdx.x * TN;
    for (int e = tid; e < 128 * TN; e += 128) {
        int r = e / TN, c = e % TN;
        float acc = 0.f;
        for (int k = 0; k < K; k++)
            acc += A[(size_t)(bm + r) * K + k] * Bt[(size_t)(bn + c) * K + k];
        C[(size_t)(bm + r) * N + bn + c] = acc;
    }
#endif
}

// ---------------- S = Q K^T over causal tiles (tf32x3) ----------------
// grid (kt=16, qt=16, bh=32), block 128. K = 192 (128 from Qc/Kc + 64 rope).
__global__ __launch_bounds__(128) void sqk_kernel(
    const float* __restrict__ Qc, const float* __restrict__ Qr,
    const float* __restrict__ Kc, const float* __restrict__ Kr,
    float* __restrict__ S)
{
    const int kt = blockIdx.x, qt = blockIdx.y, bh = blockIdx.z;
    if (kt > qt) return;
#if HAS_TCGEN05
    constexpr int A_BYTES = 128 * 128;
    constexpr int STAGE = 4 * A_BYTES;   // A hi/lo + B hi/lo
    extern __shared__ char smem[];
    const uint32_t sbase = smem_u32(smem);
    const uint32_t mb_empty = sbase;
    const uint32_t mb_done  = sbase + 24;
    const uint32_t tmem_slot = sbase + 32;
    const uint32_t tiles = (sbase + 64 + 1023) & ~1023u;

    const int tid = threadIdx.x;
    const int b = bh >> 4, h = bh & 15;

    if (tid == 0) {
        MBAR_INIT(mb_empty + 0, 1);
        MBAR_INIT(mb_empty + 8, 1);
        MBAR_INIT(mb_empty + 16, 1);
        MBAR_INIT(mb_done, 1);
    }
    if (tid < 32) { T5_ALLOC(tmem_slot, 128); T5_RELINQ(); }
    __syncthreads();
    uint32_t tmem;
    asm volatile("ld.shared.b32 %0, [%1];" : "=r"(tmem) : "r"(tmem_slot));

    const uint32_t idesc = (1u << 4) | (2u << 7) | (2u << 10)
                         | (16u << 17) | (8u << 24);   // N=128, M=128

    const size_t qrow0 = (size_t)(b * Tt + qt * 128);
    const size_t krow0 = (size_t)(b * Tt + kt * 128);

    for (int c = 0; c < 6; c++) {
        const int s = c - (c / 3) * 3;
        const uint32_t st = tiles + s * STAGE;
        if (c >= 3) MBAR_WAIT(mb_empty + 8 * s, ((c / 3) - 1) & 1);
        const int k0 = c * 32;
        const bool rope = (k0 >= 128);
        const float* Ab = rope ? Qr + qrow0 * (Hh*Rr) + h * Rr + (k0 - 128)
                               : Qc + qrow0 * (Hh*HD) + h * HD + k0;
        const float* Bb2 = rope ? Kr + krow0 * Rr + (k0 - 128)
                                : Kc + krow0 * (Hh*HD) + h * HD + k0;
        const int Astr = rope ? (Hh*Rr) : (Hh*HD);
        const int Bstr = rope ? Rr : (Hh*HD);
        #pragma unroll
        for (int i = 0; i < 8; i++) {
            int idx = i * 128 + tid;
            int row = idx >> 3, seg = idx & 7;
            float4 v = *reinterpret_cast<const float4*>(&Ab[(size_t)row * Astr + seg * 4]);
            split_sts(st, st + A_BYTES, row, seg, v);
        }
        #pragma unroll
        for (int i = 0; i < 8; i++) {
            int idx = i * 128 + tid;
            int row = idx >> 3, seg = idx & 7;
            float4 v = *reinterpret_cast<const float4*>(&Bb2[(size_t)row * Bstr + seg * 4]);
            split_sts(st + 2 * A_BYTES, st + 3 * A_BYTES, row, seg, v);
        }
        FENCE_ASYNC();
        __syncthreads();
        if (tid < 32 && elect1()) {
            uint64_t ah = mk_desc(st);
            uint64_t al = mk_desc(st + A_BYTES);
            uint64_t bhd = mk_desc(st + 2 * A_BYTES);
            uint64_t bld = mk_desc(st + 3 * A_BYTES);
            #pragma unroll
            for (int q = 0; q < 4; q++)
                mma_tf32(tmem, ah + 2 * q, bhd + 2 * q, idesc,
                         (c == 0 && q == 0) ? 0u : 1u);
            #pragma unroll
            for (int q = 0; q < 4; q++)
                mma_tf32(tmem, ah + 2 * q, bld + 2 * q, idesc, 1u);
            #pragma unroll
            for (int q = 0; q < 4; q++)
                mma_tf32(tmem, al + 2 * q, bhd + 2 * q, idesc, 1u);
            T5_COMMIT(mb_empty + 8 * s);
        }
    }
    if (tid < 32 && elect1()) T5_COMMIT(mb_done);
    MBAR_WAIT(mb_done, 0);
    T5_FENCE_AFTER();

    const int wid = tid >> 5, lid = tid & 31;
    const size_t rowoff = ((size_t)bh * Tt + qt * 128 + wid * 32 + lid) * Tt + kt * 128;
    #pragma unroll
    for (int b2 = 0; b2 < 4; b2++) {
        uint32_t r[32];
        LDTM_X32(r, tmem + b2 * 32);
        T5_WAIT_LD();
        #pragma unroll
        for (int j = 0; j < 32; j += 4) {
            float4 o = make_float4(__uint_as_float(r[j]), __uint_as_float(r[j + 1]),
                                   __uint_as_float(r[j + 2]), __uint_as_float(r[j + 3]));
            *reinterpret_cast<float4*>(&S[rowoff + b2 * 32 + j]) = o;
        }
    }
    __syncthreads();
    if (tid < 32) T5_DEALLOC(tmem, 128);
#else
    const int tid = threadIdx.x;
    const int b = bh >> 4, h = bh & 15;
    for (int e = tid; e < 128 * 128; e += 128) {
        int r = e >> 7, c = e & 127;
        int q = qt * 128 + r, k = kt * 128 + c;
        float acc = 0.f;
        for (int d = 0; d < 128; d++)
            acc += Qc[(size_t)(b*Tt+q)*(Hh*HD) + h*HD + d] * Kc[(size_t)(b*Tt+k)*(Hh*HD) + h*HD + d];
        for (int d = 0; d < 64; d++)
            acc += Qr[(size_t)(b*Tt+q)*(Hh*Rr) + h*Rr + d] * Kr[(size_t)(b*Tt+k)*Rr + d];
        S[((size_t)bh * Tt + q) * Tt + k] = acc;
    }
#endif
}

// ---------------- softmax over causal rows (normalizes P in place) --------
__global__ __launch_bounds__(256) void softmax_kernel(float* __restrict__ S)
{
    const float scale = 0.07216878364870323f;   // 1/sqrt(192)
    int gw = blockIdx.x * 8 + (threadIdx.x >> 5);
    int bh = gw >> 11, q = gw & 2047;
    int lane = threadIdx.x & 31;
    float* row = S + ((size_t)bh * Tt + q) * Tt;
    const int n = q + 1;
    const int ktE = ((q >> 7) + 1) * 128;   // end of diag tile

    // pass 1: online max+sum
    float m = -1e30f, l = 0.f;
    for (int i = lane * 4; i < ktE; i += 128) {
        float4 v = *reinterpret_cast<const float4*>(&row[i]);
        float vv[4] = {v.x, v.y, v.z, v.w};
        #pragma unroll
        for (int j = 0; j < 4; j++) {
            if (i + j < n) {
                float s = vv[j] * scale;
                if (s > m) { l = l * __expf(m - s) + 1.f; m = s; }
                else l += __expf(s - m);
            }
        }
    }
    #pragma unroll
    for (int off = 16; off >= 1; off >>= 1) {
        float mo = __shfl_xor_sync(0xffffffffu, m, off);
        float lo = __shfl_xor_sync(0xffffffffu, l, off);
        float M = fmaxf(m, mo);
        l = l * __expf(m - M) + lo * __expf(mo - M);
        m = M;
    }
    float invl = 1.0f / l;

    // pass 2: write normalized probs (zeros in diag-tile pad)
    for (int i = lane * 4; i < ktE; i += 128) {
        float4 v = *reinterpret_cast<const float4*>(&row[i]);
        float vv[4] = {v.x, v.y, v.z, v.w};
        float4 o;
        float* oo = &o.x;
        #pragma unroll
        for (int j = 0; j < 4; j++)
            oo[j] = (i + j < n) ? __expf(vv[j] * scale - m) * invl : 0.f;
        *reinterpret_cast<float4*>(&row[i]) = o;
    }
}

// ---------------- O = P @ V (tf32x3) ----------------
// grid (qt=16, bh=32), block 128. K = (qt+1)*128.
__global__ __launch_bounds__(128) void pv_kernel(
    const float* __restrict__ P, const float* __restrict__ Vt,
    float* __restrict__ O)
{
    const int qt = blockIdx.x, bh = blockIdx.y;
#if HAS_TCGEN05
    constexpr int A_BYTES = 128 * 128;
    constexpr int STAGE = 4 * A_BYTES;
    extern __shared__ char smem[];
    const uint32_t sbase = smem_u32(smem);
    const uint32_t mb_empty = sbase;
    const uint32_t mb_done  = sbase + 24;
    const uint32_t tmem_slot = sbase + 32;
    const uint32_t tiles = (sbase + 64 + 1023) & ~1023u;

    const int tid = threadIdx.x;
    const int b = bh >> 4, h = bh & 15;

    if (tid == 0) {
        MBAR_INIT(mb_empty + 0, 1);
        MBAR_INIT(mb_empty + 8, 1);
        MBAR_INIT(mb_empty + 16, 1);
        MBAR_INIT(mb_done, 1);
    }
    if (tid < 32) { T5_ALLOC(tmem_slot, 128); T5_RELINQ(); }
    __syncthreads();
    uint32_t tmem;
    asm volatile("ld.shared.b32 %0, [%1];" : "=r"(tmem) : "r"(tmem_slot));

    const uint32_t idesc = (1u << 4) | (2u << 7) | (2u << 10)
                         | (16u << 17) | (8u << 24);
    const int nc = (qt + 1) * 4;

    const float* Ab0 = P + ((size_t)bh * Tt + qt * 128) * Tt;
    const float* Bb0 = Vt + (size_t)bh * HD * Tt;

    for (int c = 0; c < nc; c++) {
        const int s = c - (c / 3) * 3;
        const uint32_t st = tiles + s * STAGE;
        if (c >= 3) MBAR_WAIT(mb_empty + 8 * s, ((c / 3) - 1) & 1);
        const int k0 = c * 32;
        #pragma unroll
        for (int i = 0; i < 8; i++) {
            int idx = i * 128 + tid;
            int row = idx >> 3, seg = idx & 7;
            float4 v = *reinterpret_cast<const float4*>(&Ab0[(size_t)row * Tt + k0 + seg * 4]);
            split_sts(st, st + A_BYTES, row, seg, v);
        }
        #pragma unroll
        for (int i = 0; i < 8; i++) {
            int idx = i * 128 + tid;
            int row = idx >> 3, seg = idx & 7;
            float4 v = *reinterpret_cast<const float4*>(&Bb0[(size_t)row * Tt + k0 + seg * 4]);
            split_sts(st + 2 * A_BYTES, st + 3 * A_BYTES, row, seg, v);
        }
        FENCE_ASYNC();
        __syncthreads();
        if (tid < 32 && elect1()) {
            uint64_t ah = mk_desc(st);
            uint64_t al = mk_desc(st + A_BYTES);
            uint64_t bhd = mk_desc(st + 2 * A_BYTES);
            uint64_t bld = mk_desc(st + 3 * A_BYTES);
            #pragma unroll
            for (int q = 0; q < 4; q++)
                mma_tf32(tmem, ah + 2 * q, bhd + 2 * q, idesc,
                         (c == 0 && q == 0) ? 0u : 1u);
            #pragma unroll
            for (int q = 0; q < 4; q++)
                mma_tf32(tmem, ah + 2 * q, bld + 2 * q, idesc, 1u);
            #pragma unroll
            for (int q = 0; q < 4; q++)
                mma_tf32(tmem, al + 2 * q, bhd + 2 * q, idesc, 1u);
            T5_COMMIT(mb_empty + 8 * s);
        }
    }
    if (tid < 32 && elect1()) T5_COMMIT(mb_done);
    MBAR_WAIT(mb_done, 0);
    T5_FENCE_AFTER();

    const int wid = tid >> 5, lid = tid & 31;
    const size_t rowoff = (size_t)(b * Tt + qt * 128 + wid * 32 + lid) * (Hh*HD) + h * HD;
    #pragma unroll
    for (int b2 = 0; b2 < 4; b2++) {
        uint32_t r[32];
        LDTM_X32(r, tmem + b2 * 32);
        T5_WAIT_LD();
        #pragma unroll
        for (int j = 0; j < 32; j += 4) {
            float4 o = make_float4(__uint_as_float(r[j]), __uint_as_float(r[j + 1]),
                                   __uint_as_float(r[j + 2]), __uint_as_float(r[j + 3]));
            *reinterpret_cast<float4*>(&O[rowoff + b2 * 32 + j]) = o;
        }
    }
    __syncthreads();
    if (tid < 32) T5_DEALLOC(tmem, 128);
#else
    const int tid = threadIdx.x;
    const int b = bh >> 4, h = bh & 15;
    const int K = (qt + 1) * 128;
    for (int e = tid; e < 128 * 128; e += 128) {
        int r = e >> 7, d = e & 127;
        float acc = 0.f;
        for (int k = 0; k < K; k++)
            acc += P[((size_t)bh * Tt + qt * 128 + r) * Tt + k]
                 * Vt[((size_t)bh * HD + d) * Tt + k];
        O[(size_t)(b * Tt + qt * 128 + r) * (Hh*HD) + h * HD + d] = acc;
    }
#endif
}

// ---------------- rope kernels ----------------
__global__ __launch_bounds__(256) void rope_q_kernel(
    float* __restrict__ Qr, const float* __restrict__ freqs)
{
    int idx = blockIdx.x * 256 + threadIdx.x;
    if (idx >= MROWS * Hh * (Rr / 2)) return;
    int m = idx >> 9;
    int rem = idx & 511;
    int h = rem >> 5;
    int i = rem & 31;
    int t = m & (Tt - 1);
    float f = freqs[t * (Rr / 2) + i];
    float s, c;
    sincosf(f, &s, &c);
    size_t base = (size_t)m * (Hh * Rr) + h * Rr + 2 * i;
    float x0 = Qr[base], x1 = Qr[base + 1];
    Qr[base]     = x0 * c - x1 * s;
    Qr[base + 1] = x0 * s + x1 * c;
}

__global__ __launch_bounds__(256) void rope_k_kernel(
    const float* __restrict__ KRin, const float* __restrict__ freqs,
    float* __restrict__ KRout)
{
    int idx = blockIdx.x * 256 + threadIdx.x;
    if (idx >= MROWS * (Rr / 2)) return;
    int m = idx >> 5;
    int i = idx & 31;
    int t = m & (Tt - 1);
    float f = freqs[t * (Rr / 2) + i];
    float s, c;
    sincosf(f, &s, &c);
    size_t base = (size_t)m * Rr + 2 * i;
    float x0 = KRin[base], x1 = KRin[base + 1];
    KRout[base]     = x0 * c - x1 * s;
    KRout[base + 1] = x0 * s + x1 * c;
}

// ---------------- launch ----------------
#define TG_SMEM(TN) (2048 + 3 * (2 * 128 * 128 + 2 * (TN) * 128))
#define ATT_SMEM    (2048 + 3 * 4 * 128 * 128)

extern "C" void kernel_launch(void* const* d_in, const int* in_sizes, int n_in,
                              void* d_out, int out_size)
{
    const float* x     = (const float*)d_in[0];
    const float* freqs = (const float*)d_in[1];
    const float* W_DKV = (const float*)d_in[2];
    const float* W_UK  = (const float*)d_in[3];
    const float* W_UV  = (const float*)d_in[4];
    const float* W_KR  = (const float*)d_in[5];
    const float* W_DQ  = (const float*)d_in[6];
    const float* W_UQ  = (const float*)d_in[7];
    const float* W_QR  = (const float*)d_in[8];
    const float* W_O   = (const float*)d_in[9];

    float* y   = (float*)d_out;
    float* cKV = y   + (size_t)Bb * Tt * DM;
    float* KRo = cKV + (size_t)Bb * Tt * KVL;

    float *pKc, *pV, *pVt, *pcQ, *pQc, *pQr, *pKR, *pAO, *pWt, *pS;
    cudaGetSymbolAddress((void**)&pKc, g_Kc);
    cudaGetSymbolAddress((void**)&pV,  g_V);
    cudaGetSymbolAddress((void**)&pVt, g_Vt);
    cudaGetSymbolAddress((void**)&pcQ, g_cQ);
    cudaGetSymbolAddress((void**)&pQc, g_Qc);
    cudaGetSymbolAddress((void**)&pQr, g_Qr);
    cudaGetSymbolAddress((void**)&pKR, g_KR);
    cudaGetSymbolAddress((void**)&pAO, g_AO);
    cudaGetSymbolAddress((void**)&pWt, g_Wt);
    cudaGetSymbolAddress((void**)&pS,  g_S);

    cudaFuncSetAttribute(tgemm_kernel<128>,
                         cudaFuncAttributeMaxDynamicSharedMemorySize, TG_SMEM(128));
    cudaFuncSetAttribute(tgemm_kernel<64>,
                         cudaFuncAttributeMaxDynamicSharedMemorySize, TG_SMEM(64));
    cudaFuncSetAttribute(sqk_kernel,
                         cudaFuncAttributeMaxDynamicSharedMemorySize, ATT_SMEM);
    cudaFuncSetAttribute(pv_kernel,
                         cudaFuncAttributeMaxDynamicSharedMemorySize, ATT_SMEM);

    dim3 tb(32, 8);
    transpose_kernel<<<dim3(KVL/32,  DM/32),  tb>>>(W_DKV, pWt + O_DKV, DM, KVL);
    transpose_kernel<<<dim3((Hh*HD)/32, KVL/32), tb>>>(W_UK, pWt + O_UK, KVL, Hh*HD);
    transpose_kernel<<<dim3((Hh*HD)/32, KVL/32), tb>>>(W_UV, pWt + O_UV, KVL, Hh*HD);
    transpose_kernel<<<dim3(Rr/32,   DM/32),  tb>>>(W_KR, pWt + O_KR, DM, Rr);
    transpose_kernel<<<dim3(QL/32,   DM/32),  tb>>>(W_DQ, pWt + O_DQ, DM, QL);
    transpose_kernel<<<dim3((Hh*HD)/32, QL/32), tb>>>(W_UQ, pWt + O_UQ, QL, Hh*HD);
    transpose_kernel<<<dim3((Hh*Rr)/32, QL/32), tb>>>(W_QR, pWt + O_QR, QL, Hh*Rr);
    transpose_kernel<<<dim3(DM/32,   (Hh*HD)/32), tb>>>(W_O, pWt + O_O, Hh*HD, DM);

    // projections
    tgemm_kernel<128><<<dim3(KVL/128, MROWS/128), 128, TG_SMEM(128)>>>(
        x, pWt + O_DKV, cKV, KVL, DM);
    tgemm_kernel<128><<<dim3((Hh*HD)/128, MROWS/128), 128, TG_SMEM(128)>>>(
        cKV, pWt + O_UK, pKc, Hh*HD, KVL);
    tgemm_kernel<128><<<dim3((Hh*HD)/128, MROWS/128), 128, TG_SMEM(128)>>>(
        cKV, pWt + O_UV, pV, Hh*HD, KVL);
    transpose_v_kernel<<<dim3(Tt/32, HD/32, BH), tb>>>(pV, pVt);
    tgemm_kernel<64><<<dim3(1, MROWS/128), 128, TG_SMEM(64)>>>(
        x, pWt + O_KR, pKR, Rr, DM);
    {
        int n = MROWS * (Rr / 2);
        rope_k_kernel<<<(n + 255) / 256, 256>>>(pKR, freqs, KRo);
    }
    tgemm_kernel<128><<<dim3(QL/128, MROWS/128), 128, TG_SMEM(128)>>>(
        x, pWt + O_DQ, pcQ, QL, DM);
    tgemm_kernel<128><<<dim3((Hh*HD)/128, MROWS/128), 128, TG_SMEM(128)>>>(
        pcQ, pWt + O_UQ, pQc, Hh*HD, QL);
    tgemm_kernel<128><<<dim3((Hh*Rr)/128, MROWS/128), 128, TG_SMEM(128)>>>(
        pcQ, pWt + O_QR, pQr, Hh*Rr, QL);
    {
        int n = MROWS * Hh * (Rr / 2);
        rope_q_kernel<<<(n + 255) / 256, 256>>>(pQr, freqs);
    }

    // attention: S = QK^T (causal tiles), softmax, O = P V
    sqk_kernel<<<dim3(16, 16, BH), 128, ATT_SMEM>>>(pQc, pQr, pKc, KRo, pS);
    softmax_kernel<<<(BH * Tt) / 8, 256>>>(pS);
    pv_kernel<<<dim3(16, BH), 128, ATT_SMEM>>>(pS, pVt, pAO);

    // output projection
    tgemm_kernel<128><<<dim3(DM/128, MROWS/128), 128, TG_SMEM(128)>>>(
        pAO, pWt + O_O, y, DM, Hh*HD);
}

// round 6
// speedup vs baseline: 2.1169x; 2.1169x over previous
#include <cuda_runtime.h>
#include <cuda_fp16.h>
#include <math.h>
#include <stdint.h>

#define Bb 2
#define Tt 2048
#define DM 2048
#define Hh 16
#define HD 128
#define KVL 512
#define QL 1024
#define Rr 64
#define MROWS (Bb*Tt)
#define BH (Bb*Hh)
#define HHD (Hh*HD)
#define HRr (Hh*Rr)

#if defined(__CUDA_ARCH_FEAT_SM103_ALL) || defined(__CUDA_ARCH_FEAT_SM100_ALL)
#define HAS_TCGEN05 1
#else
#define HAS_TCGEN05 0
#endif

// ---------------- scratch ----------------
__device__ float g_V [MROWS * HHD];
__device__ float g_Qr[MROWS * HRr];
__device__ float g_KR[MROWS * Rr];
__device__ float g_S [(size_t)BH * Tt * Tt];
__device__ float g_L [BH * Tt];
__device__ __half g_xH[MROWS * DM],  g_xL[MROWS * DM];
__device__ __half g_cKVh[MROWS * KVL], g_cKVl[MROWS * KVL];
__device__ __half g_cQh[MROWS * QL],   g_cQl[MROWS * QL];
__device__ __half g_Qch[MROWS * HHD],  g_Qcl[MROWS * HHD];
__device__ __half g_Qrh[MROWS * HRr],  g_Qrl[MROWS * HRr];
__device__ __half g_Kch[MROWS * HHD],  g_Kcl[MROWS * HHD];
__device__ __half g_Krh[MROWS * Rr],   g_Krl[MROWS * Rr];
__device__ __half g_Vth[BH * HD * Tt], g_Vtl[BH * HD * Tt];
__device__ __half g_AOh[MROWS * HHD],  g_AOl[MROWS * HHD];
__device__ __half g_Ph[(size_t)BH * Tt * Tt], g_Pl[(size_t)BH * Tt * Tt];
#define O_DKV 0
#define O_UK  (O_DKV + 512*2048)
#define O_UV  (O_UK  + 2048*512)
#define O_KR  (O_UV  + 2048*512)
#define O_DQ  (O_KR  + 64*2048)
#define O_UQ  (O_DQ  + 1024*2048)
#define O_QR  (O_UQ  + 2048*1024)
#define O_O   (O_QR  + 2048*1024)
#define WT_TOTAL (O_O + 2048*2048)
__device__ __half g_WtH[WT_TOTAL], g_WtL[WT_TOTAL];

// ---------------- helpers ----------------
__device__ __forceinline__ uint32_t smem_u32(const void* p) {
    uint32_t a;
    asm("{ .reg .u64 t; cvta.to.shared.u64 t, %1; cvt.u32.u64 %0, t; }"
        : "=r"(a) : "l"(p));
    return a;
}
__device__ __forceinline__ void split_pair(float a, float b,
                                           uint32_t& hi, uint32_t& lo) {
    __half ha = __float2half_rn(a), hb = __float2half_rn(b);
    hi = ((uint32_t)__half_as_ushort(hb) << 16) | __half_as_ushort(ha);
    lo = ((uint32_t)__half_as_ushort(__float2half_rn(b - __half2float(hb))) << 16)
       | __half_as_ushort(__float2half_rn(a - __half2float(ha)));
}

#if HAS_TCGEN05
__device__ __forceinline__ bool elect1() {
    uint32_t r;
    asm volatile("{\n\t.reg .pred p;\n\telect.sync _|p, 0xFFFFFFFF;\n\t"
                 "selp.b32 %0,1,0,p;\n\t}" : "=r"(r));
    return r != 0;
}
#define MBAR_INIT(a, c) \
    asm volatile("mbarrier.init.shared.b64 [%0], %1;" :: "r"(a), "r"(c) : "memory")
#define MBAR_WAIT(a, ph) do { \
    uint32_t _m = (a), _p = (uint32_t)(ph), _d; \
    asm volatile("{\n\t.reg .pred p;\n\t" \
        "mbarrier.try_wait.parity.acquire.cta.shared::cta.b64 p, [%1], %2;\n\t" \
        "selp.b32 %0,1,0,p;\n\t}" : "=r"(_d) : "r"(_m), "r"(_p) : "memory"); \
    while (!_d) { \
        asm volatile("{\n\t.reg .pred p;\n\t" \
            "mbarrier.try_wait.parity.acquire.cta.shared::cta.b64 p, [%1], %2, 0x989680;\n\t" \
            "selp.b32 %0,1,0,p;\n\t}" : "=r"(_d) : "r"(_m), "r"(_p) : "memory"); \
    } } while (0)
#define T5_COMMIT(a) \
    asm volatile("tcgen05.commit.cta_group::1.mbarrier::arrive::one.shared::cluster.b64 [%0];" \
                 :: "r"(a) : "memory")
#define T5_ALLOC(a, n) \
    asm volatile("tcgen05.alloc.cta_group::1.sync.aligned.shared::cta.b32 [%0], %1;" \
                 :: "r"(a), "r"(n) : "memory")
#define T5_DEALLOC(t, n) \
    asm volatile("tcgen05.dealloc.cta_group::1.sync.aligned.b32 %0, %1;" :: "r"(t), "r"(n))
#define T5_RELINQ() \
    asm volatile("tcgen05.relinquish_alloc_permit.cta_group::1.sync.aligned;")
#define T5_WAIT_LD()   asm volatile("tcgen05.wait::ld.sync.aligned;" ::: "memory")
#define T5_FENCE_AFTER() asm volatile("tcgen05.fence::after_thread_sync;" ::: "memory")
#define FENCE_ASYNC()  asm volatile("fence.proxy.async.shared::cta;" ::: "memory")

#define LDTM_X32(r, addr) \
    asm volatile("tcgen05.ld.sync.aligned.32x32b.x32.b32 " \
        "{%0, %1, %2, %3, %4, %5, %6, %7, %8, %9, %10, %11, %12, %13, %14, %15, " \
        "%16, %17, %18, %19, %20, %21, %22, %23, %24, %25, %26, %27, %28, %29, %30, %31}, [%32];" \
        : "=r"((r)[0]),  "=r"((r)[1]),  "=r"((r)[2]),  "=r"((r)[3]), \
          "=r"((r)[4]),  "=r"((r)[5]),  "=r"((r)[6]),  "=r"((r)[7]), \
          "=r"((r)[8]),  "=r"((r)[9]),  "=r"((r)[10]), "=r"((r)[11]), \
          "=r"((r)[12]), "=r"((r)[13]), "=r"((r)[14]), "=r"((r)[15]), \
          "=r"((r)[16]), "=r"((r)[17]), "=r"((r)[18]), "=r"((r)[19]), \
          "=r"((r)[20]), "=r"((r)[21]), "=r"((r)[22]), "=r"((r)[23]), \
          "=r"((r)[24]), "=r"((r)[25]), "=r"((r)[26]), "=r"((r)[27]), \
          "=r"((r)[28]), "=r"((r)[29]), "=r"((r)[30]), "=r"((r)[31]) \
        : "r"(addr))

__device__ __forceinline__ void mma_f16(uint32_t d, uint64_t ad, uint64_t bd,
                                        uint32_t idesc, uint32_t en) {
    asm volatile("{\n\t.reg .pred p;\n\tsetp.ne.u32 p, %4, 0;\n\t"
        "tcgen05.mma.cta_group::1.kind::f16 [%0], %1, %2, %3, p;\n\t}"
        :: "r"(d), "l"(ad), "l"(bd), "r"(idesc), "r"(en) : "memory");
}
__device__ __forceinline__ uint64_t mk_desc(uint32_t addr) {
    return ((uint64_t)2 << 61) | ((uint64_t)1 << 46) | ((uint64_t)64 << 32)
         | ((uint64_t)1 << 16) | ((addr >> 4) & 0x3FFF);
}
__device__ __forceinline__ void sts128(uint32_t addr, uint32_t a, uint32_t b,
                                       uint32_t c, uint32_t d) {
    asm volatile("st.shared.v4.b32 [%0], {%1,%2,%3,%4};"
                 :: "r"(addr), "r"(a), "r"(b), "r"(c), "r"(d) : "memory");
}
// shared prologue/epilogue helpers for all MMA kernels
struct MmaCtx { uint32_t mb, mb_done, tmem, tiles; };
__device__ __forceinline__ MmaCtx mma_begin(char* smem) {
    MmaCtx cx;
    uint32_t sbase = smem_u32(smem);
    cx.mb = sbase;
    cx.mb_done = sbase + 24;
    cx.tiles = (sbase + 64 + 1023) & ~1023u;
    if (threadIdx.x == 0) {
        MBAR_INIT(cx.mb + 0, 1);
        MBAR_INIT(cx.mb + 8, 1);
        MBAR_INIT(cx.mb + 16, 1);
        MBAR_INIT(cx.mb_done, 1);
    }
    if (threadIdx.x < 32) { T5_ALLOC(sbase + 32, 128); T5_RELINQ(); }
    __syncthreads();
    asm volatile("ld.shared.b32 %0, [%1];" : "=r"(cx.tmem) : "r"(sbase + 32));
    return cx;
}
// issue 12 MMAs (hh, hl, lh) for one K=64 chunk
__device__ __forceinline__ void mma_chunk(const MmaCtx& cx, uint32_t st,
                                          uint32_t aBytes, uint32_t bBytes,
                                          uint32_t idesc, int s, bool first) {
    if (threadIdx.x < 32 && elect1()) {
        uint64_t ah = mk_desc(st),            al = mk_desc(st + aBytes);
        uint64_t bh = mk_desc(st + 2*aBytes), bl = mk_desc(st + 2*aBytes + bBytes);
        #pragma unroll
        for (int q = 0; q < 4; q++)
            mma_f16(cx.tmem, ah + 2*q, bh + 2*q, idesc, (first && q == 0) ? 0u : 1u);
        #pragma unroll
        for (int q = 0; q < 4; q++)
            mma_f16(cx.tmem, ah + 2*q, bl + 2*q, idesc, 1u);
        #pragma unroll
        for (int q = 0; q < 4; q++)
            mma_f16(cx.tmem, al + 2*q, bh + 2*q, idesc, 1u);
        T5_COMMIT(cx.mb + 8 * s);
    }
}
__device__ __forceinline__ void mma_finish(const MmaCtx& cx) {
    if (threadIdx.x < 32 && elect1()) T5_COMMIT(cx.mb_done);
    MBAR_WAIT(cx.mb_done, 0);
    T5_FENCE_AFTER();
}
#endif

// ---------------- producers ----------------
__global__ __launch_bounds__(256) void split_x_kernel(
    const float* __restrict__ x, __half* __restrict__ xh, __half* __restrict__ xl)
{
    size_t i = (size_t)(blockIdx.x * 256 + threadIdx.x) * 4;
    float4 v = *reinterpret_cast<const float4*>(&x[i]);
    uint32_t h0, l0, h1, l1;
    split_pair(v.x, v.y, h0, l0);
    split_pair(v.z, v.w, h1, l1);
    *reinterpret_cast<uint2*>(&xh[i]) = make_uint2(h0, h1);
    *reinterpret_cast<uint2*>(&xl[i]) = make_uint2(l0, l1);
}

__global__ __launch_bounds__(256) void tsplit_kernel(
    const float* __restrict__ W, __half* __restrict__ WtH,
    __half* __restrict__ WtL, int K, int N)
{
    __shared__ float t[32][33];
    int n0 = blockIdx.x * 32, k0 = blockIdx.y * 32, tx = threadIdx.x;
    #pragma unroll
    for (int i = threadIdx.y; i < 32; i += 8)
        t[i][tx] = W[(size_t)(k0 + i) * N + n0 + tx];
    __syncthreads();
    #pragma unroll
    for (int i = threadIdx.y; i < 32; i += 8) {
        float v = t[tx][i];
        __half h = __float2half_rn(v);
        WtH[(size_t)(n0 + i) * K + k0 + tx] = h;
        WtL[(size_t)(n0 + i) * K + k0 + tx] = __float2half_rn(v - __half2float(h));
    }
}

__global__ __launch_bounds__(256) void transpose_v_kernel(
    const float* __restrict__ V, __half* __restrict__ Vth, __half* __restrict__ Vtl)
{
    __shared__ float t[32][33];
    int bh = blockIdx.z, b = bh >> 4, h = bh & 15;
    int t0 = blockIdx.x * 32, d0 = blockIdx.y * 32, tx = threadIdx.x;
    #pragma unroll
    for (int i = threadIdx.y; i < 32; i += 8)
        t[i][tx] = V[(size_t)(b * Tt + t0 + i) * HHD + h * HD + d0 + tx];
    __syncthreads();
    #pragma unroll
    for (int i = threadIdx.y; i < 32; i += 8) {
        float v = t[tx][i];
        __half hh = __float2half_rn(v);
        size_t o = ((size_t)bh * HD + d0 + i) * Tt + t0 + tx;
        Vth[o] = hh;
        Vtl[o] = __float2half_rn(v - __half2float(hh));
    }
}

__global__ __launch_bounds__(256) void rope_q_kernel(
    const float* __restrict__ Qr, const float* __restrict__ freqs,
    __half* __restrict__ Qrh, __half* __restrict__ Qrl)
{
    int idx = blockIdx.x * 256 + threadIdx.x;
    if (idx >= MROWS * Hh * (Rr / 2)) return;
    int m = idx >> 9, rem = idx & 511, h = rem >> 5, i = rem & 31;
    int t = m & (Tt - 1);
    float f = freqs[t * (Rr / 2) + i], s, c;
    sincosf(f, &s, &c);
    size_t base = (size_t)m * HRr + h * Rr + 2 * i;
    float x0 = Qr[base], x1 = Qr[base + 1];
    uint32_t hi, lo;
    split_pair(x0 * c - x1 * s, x0 * s + x1 * c, hi, lo);
    *reinterpret_cast<uint32_t*>(&Qrh[base]) = hi;
    *reinterpret_cast<uint32_t*>(&Qrl[base]) = lo;
}

__global__ __launch_bounds__(256) void rope_k_kernel(
    const float* __restrict__ KRin, const float* __restrict__ freqs,
    float* __restrict__ KRout, __half* __restrict__ Krh, __half* __restrict__ Krl)
{
    int idx = blockIdx.x * 256 + threadIdx.x;
    if (idx >= MROWS * (Rr / 2)) return;
    int m = idx >> 5, i = idx & 31;
    int t = m & (Tt - 1);
    float f = freqs[t * (Rr / 2) + i], s, c;
    sincosf(f, &s, &c);
    size_t base = (size_t)m * Rr + 2 * i;
    float x0 = KRin[base], x1 = KRin[base + 1];
    float y0 = x0 * c - x1 * s, y1 = x0 * s + x1 * c;
    KRout[base] = y0;
    KRout[base + 1] = y1;
    uint32_t hi, lo;
    split_pair(y0, y1, hi, lo);
    *reinterpret_cast<uint32_t*>(&Krh[base]) = hi;
    *reinterpret_cast<uint32_t*>(&Krl[base]) = lo;
}

// ---------------- GEMM: C[M,N]=A[M,K]@Bt[N,K]^T (fp16x3, K-chunk 64) -------
template<int TN>
__global__ __launch_bounds__(256) void tgemm_kernel(
    const __half* __restrict__ Ah, const __half* __restrict__ Al,
    const __half* __restrict__ Bh, const __half* __restrict__ Bl,
    float* __restrict__ C, __half* __restrict__ Ch, __half* __restrict__ Cl,
    int N, int K)
{
    const int tid = threadIdx.x;
    const int bm = blockIdx.y * 128, bn = blockIdx.x * TN;
#if HAS_TCGEN05
    constexpr int A_BYTES = 128 * 128;
    constexpr int B_BYTES = TN * 128;
    constexpr int STAGE = 2 * A_BYTES + 2 * B_BYTES;
    constexpr int AU = 1024, BU = TN * 8;
    constexpr int ITERS = (2 * AU + 2 * BU) / 256;
    extern __shared__ char smem[];
    MmaCtx cx = mma_begin(smem);
    const uint32_t idesc = (1u << 4) | ((uint32_t)(TN / 8) << 17) | (8u << 24);
    const int nc = K >> 6;
    const __half* psrc[4] = {Ah + (size_t)bm * K, Al + (size_t)bm * K,
                             Bh + (size_t)bn * K, Bl + (size_t)bn * K};
    for (int c = 0; c < nc; c++) {
        const int s = c - (c / 3) * 3;
        const uint32_t st = cx.tiles + s * STAGE;
        if (c >= 3) MBAR_WAIT(cx.mb + 8 * s, ((c / 3) - 1) & 1);
        const int k0 = c * 64;
        uint4 v[ITERS];
        uint32_t da[ITERS];
        #pragma unroll
        for (int i = 0; i < ITERS; i++) {
            int u = i * 256 + tid;
            int t = (u < AU) ? 0 : (u < 2*AU) ? 1 : (u < 2*AU+BU) ? 2 : 3;
            int ul = u - ((t == 0) ? 0 : (t == 1) ? AU : (t == 2) ? 2*AU : 2*AU+BU);
            int row = ul >> 3, seg = ul & 7;
            v[i] = *reinterpret_cast<const uint4*>(psrc[t] + (size_t)row * K + k0 + seg * 8);
            uint32_t bofs = row * 128 + seg * 16;
            uint32_t tb = (t == 0) ? 0 : (t == 1) ? A_BYTES : (t == 2) ? 2*A_BYTES : 2*A_BYTES+B_BYTES;
            da[i] = st + tb + (bofs ^ ((bofs >> 3) & 0x70));
        }
        #pragma unroll
        for (int i = 0; i < ITERS; i++)
            sts128(da[i], v[i].x, v[i].y, v[i].z, v[i].w);
        FENCE_ASYNC();
        __syncthreads();
        mma_chunk(cx, st, A_BYTES, B_BYTES, idesc, s, c == 0);
    }
    mma_finish(cx);

    const int w = tid >> 5, l2 = tid & 31, sub = w & 3;
    const int row = bm + sub * 32 + l2;
    constexpr int NB = TN / 32;
    int b2beg = (w >> 2) * 2;
    int b2end = (b2beg + 2 < NB) ? b2beg + 2 : NB;
    for (int b2 = b2beg; b2 < b2end; b2++) {
        uint32_t r[32];
        LDTM_X32(r, cx.tmem + b2 * 32);
        T5_WAIT_LD();
        size_t off = (size_t)row * N + bn + b2 * 32;
        if (C) {
            #pragma unroll
            for (int j = 0; j < 32; j += 4)
                *reinterpret_cast<float4*>(&C[off + j]) = make_float4(
                    __uint_as_float(r[j]), __uint_as_float(r[j+1]),
                    __uint_as_float(r[j+2]), __uint_as_float(r[j+3]));
        }
        if (Ch) {
            #pragma unroll
            for (int j = 0; j < 32; j += 8) {
                uint4 hv, lv;
                split_pair(__uint_as_float(r[j+0]), __uint_as_float(r[j+1]), hv.x, lv.x);
                split_pair(__uint_as_float(r[j+2]), __uint_as_float(r[j+3]), hv.y, lv.y);
                split_pair(__uint_as_float(r[j+4]), __uint_as_float(r[j+5]), hv.z, lv.z);
                split_pair(__uint_as_float(r[j+6]), __uint_as_float(r[j+7]), hv.w, lv.w);
                *reinterpret_cast<uint4*>(&Ch[off + j]) = hv;
                *reinterpret_cast<uint4*>(&Cl[off + j]) = lv;
            }
        }
    }
    __syncthreads();
    if (tid < 32) T5_DEALLOC(cx.tmem, 128);
#else
    for (int e = tid; e < 128 * TN; e += 256) {
        int r = e / TN, cc = e % TN;
        float acc = 0.f;
        for (int k = 0; k < K; k++)
            acc += (__half2float(Ah[(size_t)(bm+r)*K+k]) + __half2float(Al[(size_t)(bm+r)*K+k]))
                 * (__half2float(Bh[(size_t)(bn+cc)*K+k]) + __half2float(Bl[(size_t)(bn+cc)*K+k]));
        size_t off = (size_t)(bm + r) * N + bn + cc;
        if (C) C[off] = acc;
        if (Ch) {
            __half h = __float2half_rn(acc);
            Ch[off] = h;
            Cl[off] = __float2half_rn(acc - __half2float(h));
        }
    }
#endif
}

// ---------------- S = Q K^T (causal tiles, fp16x3) ----------------
__global__ __launch_bounds__(256) void sqk_kernel(
    const __half* __restrict__ Qch, const __half* __restrict__ Qcl,
    const __half* __restrict__ Qrh, const __half* __restrict__ Qrl,
    const __half* __restrict__ Kch, const __half* __restrict__ Kcl,
    const __half* __restrict__ Krh, const __half* __restrict__ Krl,
    float* __restrict__ S)
{
    const int kt = blockIdx.x, qt = blockIdx.y, bh = blockIdx.z;
    if (kt > qt) return;
    const int tid = threadIdx.x;
    const int b = bh >> 4, h = bh & 15;
#if HAS_TCGEN05
    constexpr int A_BYTES = 128 * 128;
    constexpr int STAGE = 4 * A_BYTES;
    extern __shared__ char smem[];
    MmaCtx cx = mma_begin(smem);
    const uint32_t idesc = (1u << 4) | (16u << 17) | (8u << 24);
    const size_t qrow0 = (size_t)(b * Tt + qt * 128);
    const size_t krow0 = (size_t)(b * Tt + kt * 128);

    for (int c = 0; c < 3; c++) {
        const uint32_t st = cx.tiles + c * STAGE;
        const __half* ps[4];
        int strd[4];
        if (c < 2) {
            ps[0] = Qch + qrow0 * HHD + h * HD + c * 64;
            ps[1] = Qcl + qrow0 * HHD + h * HD + c * 64;
            ps[2] = Kch + krow0 * HHD + h * HD + c * 64;
            ps[3] = Kcl + krow0 * HHD + h * HD + c * 64;
            strd[0] = strd[1] = strd[2] = strd[3] = HHD;
        } else {
            ps[0] = Qrh + qrow0 * HRr + h * Rr;
            ps[1] = Qrl + qrow0 * HRr + h * Rr;
            ps[2] = Krh + krow0 * Rr;
            ps[3] = Krl + krow0 * Rr;
            strd[0] = strd[1] = HRr;
            strd[2] = strd[3] = Rr;
        }
        uint4 v[16];
        uint32_t da[16];
        #pragma unroll
        for (int i = 0; i < 16; i++) {
            int u = i * 256 + tid;
            int t = u >> 10, ul = u & 1023;
            int row = ul >> 3, seg = ul & 7;
            v[i] = *reinterpret_cast<const uint4*>(ps[t] + (size_t)row * strd[t] + seg * 8);
            uint32_t bofs = row * 128 + seg * 16;
            da[i] = st + t * A_BYTES + (bofs ^ ((bofs >> 3) & 0x70));
        }
        #pragma unroll
        for (int i = 0; i < 16; i++)
            sts128(da[i], v[i].x, v[i].y, v[i].z, v[i].w);
        FENCE_ASYNC();
        __syncthreads();
        mma_chunk(cx, st, A_BYTES, A_BYTES, idesc, c, c == 0);
    }
    mma_finish(cx);

    const int w = tid >> 5, l2 = tid & 31, sub = w & 3;
    const size_t rowoff = ((size_t)bh * Tt + qt * 128 + sub * 32 + l2) * Tt + kt * 128;
    for (int b2 = (w >> 2) * 2; b2 < (w >> 2) * 2 + 2; b2++) {
        uint32_t r[32];
        LDTM_X32(r, cx.tmem + b2 * 32);
        T5_WAIT_LD();
        #pragma unroll
        for (int j = 0; j < 32; j += 4)
            *reinterpret_cast<float4*>(&S[rowoff + b2 * 32 + j]) = make_float4(
                __uint_as_float(r[j]), __uint_as_float(r[j+1]),
                __uint_as_float(r[j+2]), __uint_as_float(r[j+3]));
    }
    __syncthreads();
    if (tid < 32) T5_DEALLOC(cx.tmem, 128);
#else
    for (int e = tid; e < 128 * 128; e += 256) {
        int r = e >> 7, c = e & 127;
        int q = qt * 128 + r, k = kt * 128 + c;
        float acc = 0.f;
        for (int d = 0; d < 128; d++)
            acc += (__half2float(Qch[(size_t)(b*Tt+q)*HHD + h*HD + d]) + __half2float(Qcl[(size_t)(b*Tt+q)*HHD + h*HD + d]))
                 * (__half2float(Kch[(size_t)(b*Tt+k)*HHD + h*HD + d]) + __half2float(Kcl[(size_t)(b*Tt+k)*HHD + h*HD + d]));
        for (int d = 0; d < 64; d++)
            acc += (__half2float(Qrh[(size_t)(b*Tt+q)*HRr + h*Rr + d]) + __half2float(Qrl[(size_t)(b*Tt+q)*HRr + h*Rr + d]))
                 * (__half2float(Krh[(size_t)(b*Tt+k)*Rr + d]) + __half2float(Krl[(size_t)(b*Tt+k)*Rr + d]));
        S[((size_t)bh * Tt + q) * Tt + k] = acc;
    }
#endif
}

// ---------------- softmax: S -> unnormalized P(fp16 h/l) + row sums -------
__global__ __launch_bounds__(256) void softmax_kernel(
    const float* __restrict__ S, __half* __restrict__ Ph,
    __half* __restrict__ Pl, float* __restrict__ L)
{
    const float scale = 0.07216878364870323f;
    int gw = blockIdx.x * 8 + (threadIdx.x >> 5);
    int bh = gw >> 11, q = gw & 2047;
    int lane = threadIdx.x & 31;
    const float* row = S + ((size_t)bh * Tt + q) * Tt;
    const int n = q + 1;
    const int ktE = ((q >> 7) + 1) * 128;

    float m = -1e30f;
    for (int i = lane * 4; i < ktE; i += 128) {
        float4 v = *reinterpret_cast<const float4*>(&row[i]);
        if (i + 0 < n) m = fmaxf(m, v.x);
        if (i + 1 < n) m = fmaxf(m, v.y);
        if (i + 2 < n) m = fmaxf(m, v.z);
        if (i + 3 < n) m = fmaxf(m, v.w);
    }
    #pragma unroll
    for (int off = 16; off >= 1; off >>= 1)
        m = fmaxf(m, __shfl_xor_sync(0xffffffffu, m, off));
    m *= scale;

    float l = 0.f;
    size_t pbase = ((size_t)bh * Tt + q) * Tt;
    for (int i = lane * 8; i < ktE; i += 256) {
        float4 v0 = *reinterpret_cast<const float4*>(&row[i]);
        float4 v1 = *reinterpret_cast<const float4*>(&row[i + 4]);
        float vv[8] = {v0.x, v0.y, v0.z, v0.w, v1.x, v1.y, v1.z, v1.w};
        float p[8];
        #pragma unroll
        for (int j = 0; j < 8; j++) {
            p[j] = (i + j < n) ? __expf(vv[j] * scale - m) : 0.f;
            l += p[j];
        }
        uint4 hv, lv;
        split_pair(p[0], p[1], hv.x, lv.x);
        split_pair(p[2], p[3], hv.y, lv.y);
        split_pair(p[4], p[5], hv.z, lv.z);
        split_pair(p[6], p[7], hv.w, lv.w);
        *reinterpret_cast<uint4*>(&Ph[pbase + i]) = hv;
        *reinterpret_cast<uint4*>(&Pl[pbase + i]) = lv;
    }
    #pragma unroll
    for (int off = 16; off >= 1; off >>= 1)
        l += __shfl_xor_sync(0xffffffffu, l, off);
    if (lane == 0) L[bh * Tt + q] = l;
}

// ---------------- O = P @ V (fp16x3), normalize in epilogue ----------------
__global__ __launch_bounds__(256) void pv_kernel(
    const __half* __restrict__ Ph, const __half* __restrict__ Pl,
    const __half* __restrict__ Vth, const __half* __restrict__ Vtl,
    const float* __restrict__ L, __half* __restrict__ AOh, __half* __restrict__ AOl)
{
    const int qt = blockIdx.x, bh = blockIdx.y;
    const int tid = threadIdx.x;
    const int b = bh >> 4, h = bh & 15;
#if HAS_TCGEN05
    constexpr int A_BYTES = 128 * 128;
    constexpr int STAGE = 4 * A_BYTES;
    extern __shared__ char smem[];
    MmaCtx cx = mma_begin(smem);
    const uint32_t idesc = (1u << 4) | (16u << 17) | (8u << 24);
    const int nc = (qt + 1) * 2;
    const __half* psrc[4] = {Ph + ((size_t)bh * Tt + qt * 128) * Tt,
                             Pl + ((size_t)bh * Tt + qt * 128) * Tt,
                             Vth + (size_t)bh * HD * Tt,
                             Vtl + (size_t)bh * HD * Tt};
    for (int c = 0; c < nc; c++) {
        const int s = c - (c / 3) * 3;
        const uint32_t st = cx.tiles + s * STAGE;
        if (c >= 3) MBAR_WAIT(cx.mb + 8 * s, ((c / 3) - 1) & 1);
        const int k0 = c * 64;
        uint4 v[16];
        uint32_t da[16];
        #pragma unroll
        for (int i = 0; i < 16; i++) {
            int u = i * 256 + tid;
            int t = u >> 10, ul = u & 1023;
            int row = ul >> 3, seg = ul & 7;
            v[i] = *reinterpret_cast<const uint4*>(psrc[t] + (size_t)row * Tt + k0 + seg * 8);
            uint32_t bofs = row * 128 + seg * 16;
            da[i] = st + t * A_BYTES + (bofs ^ ((bofs >> 3) & 0x70));
        }
        #pragma unroll
        for (int i = 0; i < 16; i++)
            sts128(da[i], v[i].x, v[i].y, v[i].z, v[i].w);
        FENCE_ASYNC();
        __syncthreads();
        mma_chunk(cx, st, A_BYTES, A_BYTES, idesc, s, c == 0);
    }
    mma_finish(cx);

    const int w = tid >> 5, l2 = tid & 31, sub = w & 3;
    const int qrow = qt * 128 + sub * 32 + l2;
    const float invl = 1.0f / L[bh * Tt + qrow];
    const size_t off0 = (size_t)(b * Tt + qrow) * HHD + h * HD;
    for (int b2 = (w >> 2) * 2; b2 < (w >> 2) * 2 + 2; b2++) {
        uint32_t r[32];
        LDTM_X32(r, cx.tmem + b2 * 32);
        T5_WAIT_LD();
        #pragma unroll
        for (int j = 0; j < 32; j += 8) {
            uint4 hv, lv;
            split_pair(__uint_as_float(r[j+0]) * invl, __uint_as_float(r[j+1]) * invl, hv.x, lv.x);
            split_pair(__uint_as_float(r[j+2]) * invl, __uint_as_float(r[j+3]) * invl, hv.y, lv.y);
            split_pair(__uint_as_float(r[j+4]) * invl, __uint_as_float(r[j+5]) * invl, hv.z, lv.z);
            split_pair(__uint_as_float(r[j+6]) * invl, __uint_as_float(r[j+7]) * invl, hv.w, lv.w);
            *reinterpret_cast<uint4*>(&AOh[off0 + b2 * 32 + j]) = hv;
            *reinterpret_cast<uint4*>(&AOl[off0 + b2 * 32 + j]) = lv;
        }
    }
    __syncthreads();
    if (tid < 32) T5_DEALLOC(cx.tmem, 128);
#else
    const int K = (qt + 1) * 128;
    for (int e = tid; e < 128 * 128; e += 256) {
        int r = e >> 7, d = e & 127;
        int qrow = qt * 128 + r;
        float acc = 0.f;
        for (int k = 0; k < K; k++)
            acc += (__half2float(Ph[((size_t)bh*Tt + qrow)*Tt + k]) + __half2float(Pl[((size_t)bh*Tt + qrow)*Tt + k]))
                 * (__half2float(Vth[((size_t)bh*HD + d)*Tt + k]) + __half2float(Vtl[((size_t)bh*HD + d)*Tt + k]));
        acc /= L[bh * Tt + qrow];
        size_t off = (size_t)(b * Tt + qrow) * HHD + h * HD + d;
        __half hh = __float2half_rn(acc);
        AOh[off] = hh;
        AOl[off] = __float2half_rn(acc - __half2float(hh));
    }
#endif
}

// ---------------- launch ----------------
#define MMA_SMEM 200704

extern "C" void kernel_launch(void* const* d_in, const int* in_sizes, int n_in,
                              void* d_out, int out_size)
{
    const float* x     = (const float*)d_in[0];
    const float* freqs = (const float*)d_in[1];
    const float* W_DKV = (const float*)d_in[2];
    const float* W_UK  = (const float*)d_in[3];
    const float* W_UV  = (const float*)d_in[4];
    const float* W_KR  = (const float*)d_in[5];
    const float* W_DQ  = (const float*)d_in[6];
    const float* W_UQ  = (const float*)d_in[7];
    const float* W_QR  = (const float*)d_in[8];
    const float* W_O   = (const float*)d_in[9];

    float* y   = (float*)d_out;
    float* cKV = y   + (size_t)Bb * Tt * DM;
    float* KRo = cKV + (size_t)Bb * Tt * KVL;

    float *pV, *pQr, *pKR, *pS, *pL;
    __half *pxH, *pxL, *pWtH, *pWtL, *pcKVh, *pcKVl, *pcQh, *pcQl;
    __half *pQch, *pQcl, *pQrh, *pQrl, *pKch, *pKcl, *pKrh, *pKrl;
    __half *pVth, *pVtl, *pAOh, *pAOl, *pPh, *pPl;
    cudaGetSymbolAddress((void**)&pV,   g_V);
    cudaGetSymbolAddress((void**)&pQr,  g_Qr);
    cudaGetSymbolAddress((void**)&pKR,  g_KR);
    cudaGetSymbolAddress((void**)&pS,   g_S);
    cudaGetSymbolAddress((void**)&pL,   g_L);
    cudaGetSymbolAddress((void**)&pxH,  g_xH);
    cudaGetSymbolAddress((void**)&pxL,  g_xL);
    cudaGetSymbolAddress((void**)&pWtH, g_WtH);
    cudaGetSymbolAddress((void**)&pWtL, g_WtL);
    cudaGetSymbolAddress((void**)&pcKVh, g_cKVh);
    cudaGetSymbolAddress((void**)&pcKVl, g_cKVl);
    cudaGetSymbolAddress((void**)&pcQh, g_cQh);
    cudaGetSymbolAddress((void**)&pcQl, g_cQl);
    cudaGetSymbolAddress((void**)&pQch, g_Qch);
    cudaGetSymbolAddress((void**)&pQcl, g_Qcl);
    cudaGetSymbolAddress((void**)&pQrh, g_Qrh);
    cudaGetSymbolAddress((void**)&pQrl, g_Qrl);
    cudaGetSymbolAddress((void**)&pKch, g_Kch);
    cudaGetSymbolAddress((void**)&pKcl, g_Kcl);
    cudaGetSymbolAddress((void**)&pKrh, g_Krh);
    cudaGetSymbolAddress((void**)&pKrl, g_Krl);
    cudaGetSymbolAddress((void**)&pVth, g_Vth);
    cudaGetSymbolAddress((void**)&pVtl, g_Vtl);
    cudaGetSymbolAddress((void**)&pAOh, g_AOh);
    cudaGetSymbolAddress((void**)&pAOl, g_AOl);
    cudaGetSymbolAddress((void**)&pPh,  g_Ph);
    cudaGetSymbolAddress((void**)&pPl,  g_Pl);

    cudaFuncSetAttribute(tgemm_kernel<128>,
                         cudaFuncAttributeMaxDynamicSharedMemorySize, MMA_SMEM);
    cudaFuncSetAttribute(tgemm_kernel<64>,
                         cudaFuncAttributeMaxDynamicSharedMemorySize, MMA_SMEM);
    cudaFuncSetAttribute(sqk_kernel,
                         cudaFuncAttributeMaxDynamicSharedMemorySize, MMA_SMEM);
    cudaFuncSetAttribute(pv_kernel,
                         cudaFuncAttributeMaxDynamicSharedMemorySize, MMA_SMEM);

    dim3 tb(32, 8);
    // #1: split x
    split_x_kernel<<<(MROWS * DM / 4) / 256, 256>>>(x, pxH, pxL);
    // #2-5: first weight transposes
    tsplit_kernel<<<dim3(KVL/32, DM/32), tb>>>(W_DKV, pWtH + O_DKV, pWtL + O_DKV, DM, KVL);
    tsplit_kernel<<<dim3(HHD/32, KVL/32), tb>>>(W_UK, pWtH + O_UK, pWtL + O_UK, KVL, HHD);
    tsplit_kernel<<<dim3(HHD/32, KVL/32), tb>>>(W_UV, pWtH + O_UV, pWtL + O_UV, KVL, HHD);
    tsplit_kernel<<<dim3(Rr/32, DM/32), tb>>>(W_KR, pWtH + O_KR, pWtL + O_KR, DM, Rr);
    // #6: c_KV = x @ W_DKV  (ncu -s 5 profiles this launch)
    tgemm_kernel<128><<<dim3(KVL/128, MROWS/128), 256, MMA_SMEM>>>(
        pxH, pxL, pWtH + O_DKV, pWtL + O_DKV, cKV, pcKVh, pcKVl, KVL, DM);
    // remaining weight transposes
    tsplit_kernel<<<dim3(QL/32, DM/32), tb>>>(W_DQ, pWtH + O_DQ, pWtL + O_DQ, DM, QL);
    tsplit_kernel<<<dim3(HHD/32, QL/32), tb>>>(W_UQ, pWtH + O_UQ, pWtL + O_UQ, QL, HHD);
    tsplit_kernel<<<dim3(HRr/32, QL/32), tb>>>(W_QR, pWtH + O_QR, pWtL + O_QR, QL, HRr);
    tsplit_kernel<<<dim3(DM/32, HHD/32), tb>>>(W_O, pWtH + O_O, pWtL + O_O, HHD, DM);
    // K_c, V
    tgemm_kernel<128><<<dim3(HHD/128, MROWS/128), 256, MMA_SMEM>>>(
        pcKVh, pcKVl, pWtH + O_UK, pWtL + O_UK, nullptr, pKch, pKcl, HHD, KVL);
    tgemm_kernel<128><<<dim3(HHD/128, MROWS/128), 256, MMA_SMEM>>>(
        pcKVh, pcKVl, pWtH + O_UV, pWtL + O_UV, pV, nullptr, nullptr, HHD, KVL);
    transpose_v_kernel<<<dim3(Tt/32, HD/32, BH), tb>>>(pV, pVth, pVtl);
    // K rope path
    tgemm_kernel<64><<<dim3(1, MROWS/128), 256, MMA_SMEM>>>(
        pxH, pxL, pWtH + O_KR, pWtL + O_KR, pKR, nullptr, nullptr, Rr, DM);
    rope_k_kernel<<<(MROWS * (Rr/2) + 255) / 256, 256>>>(pKR, freqs, KRo, pKrh, pKrl);
    // Q path
    tgemm_kernel<128><<<dim3(QL/128, MROWS/128), 256, MMA_SMEM>>>(
        pxH, pxL, pWtH + O_DQ, pWtL + O_DQ, nullptr, pcQh, pcQl, QL, DM);
    tgemm_kernel<128><<<dim3(HHD/128, MROWS/128), 256, MMA_SMEM>>>(
        pcQh, pcQl, pWtH + O_UQ, pWtL + O_UQ, nullptr, pQch, pQcl, HHD, QL);
    tgemm_kernel<128><<<dim3(HRr/128, MROWS/128), 256, MMA_SMEM>>>(
        pcQh, pcQl, pWtH + O_QR, pWtL + O_QR, pQr, nullptr, nullptr, HRr, QL);
    rope_q_kernel<<<(MROWS * Hh * (Rr/2) + 255) / 256, 256>>>(pQr, freqs, pQrh, pQrl);
    // attention
    sqk_kernel<<<dim3(16, 16, BH), 256, MMA_SMEM>>>(
        pQch, pQcl, pQrh, pQrl, pKch, pKcl, pKrh, pKrl, pS);
    softmax_kernel<<<(BH * Tt) / 8, 256>>>(pS, pPh, pPl, pL);
    pv_kernel<<<dim3(16, BH), 256, MMA_SMEM>>>(pPh, pPl, pVth, pVtl, pL, pAOh, pAOl);
    // output projection
    tgemm_kernel<128><<<dim3(DM/128, MROWS/128), 256, MMA_SMEM>>>(
        pAOh, pAOl, pWtH + O_O, pWtL + O_O, y, nullptr, nullptr, DM, HHD);
}

// round 7
// speedup vs baseline: 2.2018x; 1.0401x over previous
#include <cuda_runtime.h>
#include <cuda_fp16.h>
#include <math.h>
#include <stdint.h>

#define Bb 2
#define Tt 2048
#define DM 2048
#define Hh 16
#define HD 128
#define KVL 512
#define QL 1024
#define Rr 64
#define MROWS (Bb*Tt)
#define BH (Bb*Hh)
#define HHD (Hh*HD)
#define HRr (Hh*Rr)

#if defined(__CUDA_ARCH_FEAT_SM103_ALL) || defined(__CUDA_ARCH_FEAT_SM100_ALL)
#define HAS_TCGEN05 1
#else
#define HAS_TCGEN05 0
#endif

// ---------------- scratch ----------------
__device__ float g_V [MROWS * HHD];
__device__ float g_Qr[MROWS * HRr];
__device__ float g_KRp[MROWS * 128];            // padded KR (stride 128)
__device__ float g_S [(size_t)BH * Tt * Tt];
__device__ float g_L [BH * Tt];
__device__ __half g_xH[MROWS * DM],  g_xL[MROWS * DM];
__device__ __half g_cKVh[MROWS * KVL], g_cKVl[MROWS * KVL];
__device__ __half g_cQh[MROWS * QL],   g_cQl[MROWS * QL];
__device__ __half g_Qch[MROWS * HHD],  g_Qcl[MROWS * HHD];
__device__ __half g_Qrh[MROWS * HRr],  g_Qrl[MROWS * HRr];
__device__ __half g_Kch[MROWS * HHD],  g_Kcl[MROWS * HHD];
__device__ __half g_Krh[MROWS * Rr],   g_Krl[MROWS * Rr];
__device__ __half g_Vth[BH * HD * Tt], g_Vtl[BH * HD * Tt];
__device__ __half g_AOh[MROWS * HHD],  g_AOl[MROWS * HHD];
__device__ __half g_Ph[(size_t)BH * Tt * Tt], g_Pl[(size_t)BH * Tt * Tt];
#define O_DKV 0
#define O_UK  (O_DKV + 512*2048)
#define O_UV  (O_UK  + 2048*512)
#define O_DQ  (O_UV  + 2048*512)
#define O_UQ  (O_DQ  + 1024*2048)
#define O_QR  (O_UQ  + 2048*1024)
#define O_O   (O_QR  + 2048*1024)
#define O_KRP (O_O   + 2048*2048)
#define WT_TOTAL (O_KRP + 128*2048)
__device__ __half g_WtH[WT_TOTAL], g_WtL[WT_TOTAL];

// ---------------- helpers ----------------
__device__ __forceinline__ uint32_t smem_u32(const void* p) {
    uint32_t a;
    asm("{ .reg .u64 t; cvta.to.shared.u64 t, %1; cvt.u32.u64 %0, t; }"
        : "=r"(a) : "l"(p));
    return a;
}
__device__ __forceinline__ void split_pair(float a, float b,
                                           uint32_t& hi, uint32_t& lo) {
    __half ha = __float2half_rn(a), hb = __float2half_rn(b);
    hi = ((uint32_t)__half_as_ushort(hb) << 16) | __half_as_ushort(ha);
    lo = ((uint32_t)__half_as_ushort(__float2half_rn(b - __half2float(hb))) << 16)
       | __half_as_ushort(__float2half_rn(a - __half2float(ha)));
}

#if HAS_TCGEN05
__device__ __forceinline__ bool elect1() {
    uint32_t r;
    asm volatile("{\n\t.reg .pred p;\n\telect.sync _|p, 0xFFFFFFFF;\n\t"
                 "selp.b32 %0,1,0,p;\n\t}" : "=r"(r));
    return r != 0;
}
#define MBAR_INIT(a, c) \
    asm volatile("mbarrier.init.shared.b64 [%0], %1;" :: "r"(a), "r"(c) : "memory")
#define MBAR_WAIT(a, ph) do { \
    uint32_t _m = (a), _p = (uint32_t)(ph), _d; \
    asm volatile("{\n\t.reg .pred p;\n\t" \
        "mbarrier.try_wait.parity.acquire.cta.shared::cta.b64 p, [%1], %2;\n\t" \
        "selp.b32 %0,1,0,p;\n\t}" : "=r"(_d) : "r"(_m), "r"(_p) : "memory"); \
    while (!_d) { \
        asm volatile("{\n\t.reg .pred p;\n\t" \
            "mbarrier.try_wait.parity.acquire.cta.shared::cta.b64 p, [%1], %2, 0x989680;\n\t" \
            "selp.b32 %0,1,0,p;\n\t}" : "=r"(_d) : "r"(_m), "r"(_p) : "memory"); \
    } } while (0)
#define T5_COMMIT(a) \
    asm volatile("tcgen05.commit.cta_group::1.mbarrier::arrive::one.shared::cluster.b64 [%0];" \
                 :: "r"(a) : "memory")
#define T5_ALLOC(a, n) \
    asm volatile("tcgen05.alloc.cta_group::1.sync.aligned.shared::cta.b32 [%0], %1;" \
                 :: "r"(a), "r"(n) : "memory")
#define T5_DEALLOC(t, n) \
    asm volatile("tcgen05.dealloc.cta_group::1.sync.aligned.b32 %0, %1;" :: "r"(t), "r"(n))
#define T5_RELINQ() \
    asm volatile("tcgen05.relinquish_alloc_permit.cta_group::1.sync.aligned;")
#define T5_WAIT_LD()   asm volatile("tcgen05.wait::ld.sync.aligned;" ::: "memory")
#define T5_FENCE_AFTER() asm volatile("tcgen05.fence::after_thread_sync;" ::: "memory")
#define FENCE_ASYNC()  asm volatile("fence.proxy.async.shared::cta;" ::: "memory")

#define LDTM_X32(r, addr) \
    asm volatile("tcgen05.ld.sync.aligned.32x32b.x32.b32 " \
        "{%0, %1, %2, %3, %4, %5, %6, %7, %8, %9, %10, %11, %12, %13, %14, %15, " \
        "%16, %17, %18, %19, %20, %21, %22, %23, %24, %25, %26, %27, %28, %29, %30, %31}, [%32];" \
        : "=r"((r)[0]),  "=r"((r)[1]),  "=r"((r)[2]),  "=r"((r)[3]), \
          "=r"((r)[4]),  "=r"((r)[5]),  "=r"((r)[6]),  "=r"((r)[7]), \
          "=r"((r)[8]),  "=r"((r)[9]),  "=r"((r)[10]), "=r"((r)[11]), \
          "=r"((r)[12]), "=r"((r)[13]), "=r"((r)[14]), "=r"((r)[15]), \
          "=r"((r)[16]), "=r"((r)[17]), "=r"((r)[18]), "=r"((r)[19]), \
          "=r"((r)[20]), "=r"((r)[21]), "=r"((r)[22]), "=r"((r)[23]), \
          "=r"((r)[24]), "=r"((r)[25]), "=r"((r)[26]), "=r"((r)[27]), \
          "=r"((r)[28]), "=r"((r)[29]), "=r"((r)[30]), "=r"((r)[31]) \
        : "r"(addr))

__device__ __forceinline__ void mma_f16(uint32_t d, uint64_t ad, uint64_t bd,
                                        uint32_t idesc, uint32_t en) {
    asm volatile("{\n\t.reg .pred p;\n\tsetp.ne.u32 p, %4, 0;\n\t"
        "tcgen05.mma.cta_group::1.kind::f16 [%0], %1, %2, %3, p;\n\t}"
        :: "r"(d), "l"(ad), "l"(bd), "r"(idesc), "r"(en) : "memory");
}
__device__ __forceinline__ uint64_t mk_desc(uint32_t addr) {
    return ((uint64_t)2 << 61) | ((uint64_t)1 << 46) | ((uint64_t)64 << 32)
         | ((uint64_t)1 << 16) | ((addr >> 4) & 0x3FFF);
}
__device__ __forceinline__ void sts128(uint32_t addr, uint32_t a, uint32_t b,
                                       uint32_t c, uint32_t d) {
    asm volatile("st.shared.v4.b32 [%0], {%1,%2,%3,%4};"
                 :: "r"(addr), "r"(a), "r"(b), "r"(c), "r"(d) : "memory");
}
struct MmaCtx { uint32_t mb, mb_done, tmem, tiles; };
__device__ __forceinline__ MmaCtx mma_begin(char* smem, int ncols) {
    MmaCtx cx;
    uint32_t sbase = smem_u32(smem);
    cx.mb = sbase;
    cx.mb_done = sbase + 24;
    cx.tiles = (sbase + 64 + 1023) & ~1023u;
    if (threadIdx.x == 0) {
        MBAR_INIT(cx.mb + 0, 1);
        MBAR_INIT(cx.mb + 8, 1);
        MBAR_INIT(cx.mb + 16, 1);
        MBAR_INIT(cx.mb_done, 1);
    }
    if (threadIdx.x < 32) { T5_ALLOC(sbase + 32, ncols); T5_RELINQ(); }
    __syncthreads();
    asm volatile("ld.shared.b32 %0, [%1];" : "=r"(cx.tmem) : "r"(sbase + 32));
    return cx;
}
// 12 MMAs (hh, hl, lh) for one K=64 chunk
__device__ __forceinline__ void mma_chunk(uint32_t tmem, uint32_t mbar,
                                          uint64_t ah, uint64_t al,
                                          uint64_t bh, uint64_t bl,
                                          uint32_t idesc, bool first) {
    if (threadIdx.x < 32 && elect1()) {
        #pragma unroll
        for (int q = 0; q < 4; q++)
            mma_f16(tmem, ah + 2*q, bh + 2*q, idesc, (first && q == 0) ? 0u : 1u);
        #pragma unroll
        for (int q = 0; q < 4; q++)
            mma_f16(tmem, ah + 2*q, bl + 2*q, idesc, 1u);
        #pragma unroll
        for (int q = 0; q < 4; q++)
            mma_f16(tmem, al + 2*q, bh + 2*q, idesc, 1u);
        T5_COMMIT(mbar);
    }
}
#endif

// ---------------- generic fp16x3 GEMM core (TN=128, K-chunk 64) -----------
// C128rows x 128cols tile: Ah/Al pre-offset to row block (stride K),
// Bh/Bl pre-offset to col block (stride K). Outputs optional.
__device__ __forceinline__ void gemm_core(
    const __half* Ah, const __half* Al,
    const __half* Bh, const __half* Bl, int K,
    float* Cf, __half* Ch, __half* Cl, int strideN)
{
    const int tid = threadIdx.x;
#if HAS_TCGEN05
    constexpr int T_BYTES = 128 * 128;   // one 128x64 fp16 tile
    constexpr int STAGE = 4 * T_BYTES;
    extern __shared__ char smem[];
    MmaCtx cx = mma_begin(smem, 128);
    const uint32_t idesc = (1u << 4) | (16u << 17) | (8u << 24);
    const int nc = K >> 6;
    const __half* psrc[4] = {Ah, Al, Bh, Bl};
    for (int c = 0; c < nc; c++) {
        const int s = c - (c / 3) * 3;
        const uint32_t st = cx.tiles + s * STAGE;
        if (c >= 3) MBAR_WAIT(cx.mb + 8 * s, ((c / 3) - 1) & 1);
        const int k0 = c * 64;
        uint4 v[16];
        uint32_t da[16];
        #pragma unroll
        for (int i = 0; i < 16; i++) {
            int u = i * 256 + tid;
            int t = u >> 10, ul = u & 1023;
            int row = ul >> 3, seg = ul & 7;
            v[i] = *reinterpret_cast<const uint4*>(psrc[t] + (size_t)row * K + k0 + seg * 8);
            uint32_t bofs = row * 128 + seg * 16;
            da[i] = st + t * T_BYTES + (bofs ^ ((bofs >> 3) & 0x70));
        }
        #pragma unroll
        for (int i = 0; i < 16; i++)
            sts128(da[i], v[i].x, v[i].y, v[i].z, v[i].w);
        FENCE_ASYNC();
        __syncthreads();
        mma_chunk(cx.tmem, cx.mb + 8 * s,
                  mk_desc(st), mk_desc(st + T_BYTES),
                  mk_desc(st + 2 * T_BYTES), mk_desc(st + 3 * T_BYTES),
                  idesc, c == 0);
    }
    if (tid < 32 && elect1()) T5_COMMIT(cx.mb_done);
    MBAR_WAIT(cx.mb_done, 0);
    T5_FENCE_AFTER();

    const int w = tid >> 5, l2 = tid & 31, sub = w & 3;
    const int row = sub * 32 + l2;
    for (int b2 = (w >> 2) * 2; b2 < (w >> 2) * 2 + 2; b2++) {
        uint32_t r[32];
        LDTM_X32(r, cx.tmem + b2 * 32);
        T5_WAIT_LD();
        size_t off = (size_t)row * strideN + b2 * 32;
        if (Cf) {
            #pragma unroll
            for (int j = 0; j < 32; j += 4)
                *reinterpret_cast<float4*>(&Cf[off + j]) = make_float4(
                    __uint_as_float(r[j]), __uint_as_float(r[j+1]),
                    __uint_as_float(r[j+2]), __uint_as_float(r[j+3]));
        }
        if (Ch) {
            #pragma unroll
            for (int j = 0; j < 32; j += 8) {
                uint4 hv, lv;
                split_pair(__uint_as_float(r[j+0]), __uint_as_float(r[j+1]), hv.x, lv.x);
                split_pair(__uint_as_float(r[j+2]), __uint_as_float(r[j+3]), hv.y, lv.y);
                split_pair(__uint_as_float(r[j+4]), __uint_as_float(r[j+5]), hv.z, lv.z);
                split_pair(__uint_as_float(r[j+6]), __uint_as_float(r[j+7]), hv.w, lv.w);
                *reinterpret_cast<uint4*>(&Ch[off + j]) = hv;
                *reinterpret_cast<uint4*>(&Cl[off + j]) = lv;
            }
        }
    }
    __syncthreads();
    if (tid < 32) T5_DEALLOC(cx.tmem, 128);
#else
    for (int e = tid; e < 128 * 128; e += 256) {
        int r = e >> 7, cc = e & 127;
        float acc = 0.f;
        for (int k = 0; k < K; k++)
            acc += (__half2float(Ah[(size_t)r*K+k]) + __half2float(Al[(size_t)r*K+k]))
                 * (__half2float(Bh[(size_t)cc*K+k]) + __half2float(Bl[(size_t)cc*K+k]));
        size_t off = (size_t)r * strideN + cc;
        if (Cf) Cf[off] = acc;
        if (Ch) {
            __half h = __float2half_rn(acc);
            Ch[off] = h;
            Cl[off] = __float2half_rn(acc - __half2float(h));
        }
    }
#endif
}

// ---------------- producers ----------------
__global__ __launch_bounds__(256) void split_x_kernel(
    const float* __restrict__ x, __half* __restrict__ xh, __half* __restrict__ xl)
{
    size_t i = (size_t)(blockIdx.x * 256 + threadIdx.x) * 4;
    float4 v = *reinterpret_cast<const float4*>(&x[i]);
    uint32_t h0, l0, h1, l1;
    split_pair(v.x, v.y, h0, l0);
    split_pair(v.z, v.w, h1, l1);
    *reinterpret_cast<uint2*>(&xh[i]) = make_uint2(h0, h1);
    *reinterpret_cast<uint2*>(&xl[i]) = make_uint2(l0, l1);
}

struct TSJob { const float* W; __half* H; __half* L; int K; int N; int tile0; };
struct TSJobs { TSJob a[8]; };

__global__ __launch_bounds__(256) void tsplit_all_kernel(TSJobs jobs)
{
    __shared__ float t[32][33];
    int bx = blockIdx.x;
    int ji = 0;
    #pragma unroll
    for (int i = 1; i < 8; i++)
        if (bx >= jobs.a[i].tile0) ji = i;
    TSJob j = jobs.a[ji];
    int tl = bx - j.tile0;
    int ntN = j.N >> 5;
    int n0 = (tl % ntN) * 32, k0 = (tl / ntN) * 32;
    int tx = threadIdx.x & 31, ty = threadIdx.x >> 5;
    #pragma unroll
    for (int i = ty; i < 32; i += 8)
        t[i][tx] = j.W[(size_t)(k0 + i) * j.N + n0 + tx];
    __syncthreads();
    #pragma unroll
    for (int i = ty; i < 32; i += 8) {
        float v = t[tx][i];
        __half h = __float2half_rn(v);
        j.H[(size_t)(n0 + i) * j.K + k0 + tx] = h;
        j.L[(size_t)(n0 + i) * j.K + k0 + tx] = __float2half_rn(v - __half2float(h));
    }
}

__global__ __launch_bounds__(256) void transpose_v_kernel(
    const float* __restrict__ V, __half* __restrict__ Vth, __half* __restrict__ Vtl)
{
    __shared__ float t[32][33];
    int bh = blockIdx.z, b = bh >> 4, h = bh & 15;
    int t0 = blockIdx.x * 32, d0 = blockIdx.y * 32;
    int tx = threadIdx.x & 31, ty = threadIdx.x >> 5;
    #pragma unroll
    for (int i = ty; i < 32; i += 8)
        t[i][tx] = V[(size_t)(b * Tt + t0 + i) * HHD + h * HD + d0 + tx];
    __syncthreads();
    #pragma unroll
    for (int i = ty; i < 32; i += 8) {
        float v = t[tx][i];
        __half hh = __float2half_rn(v);
        size_t o = ((size_t)bh * HD + d0 + i) * Tt + t0 + tx;
        Vth[o] = hh;
        Vtl[o] = __float2half_rn(v - __half2float(hh));
    }
}

__global__ __launch_bounds__(256) void rope_q_kernel(
    const float* __restrict__ Qr, const float* __restrict__ freqs,
    __half* __restrict__ Qrh, __half* __restrict__ Qrl)
{
    int idx = blockIdx.x * 256 + threadIdx.x;
    if (idx >= MROWS * Hh * (Rr / 2)) return;
    int m = idx >> 9, rem = idx & 511, h = rem >> 5, i = rem & 31;
    int t = m & (Tt - 1);
    float f = freqs[t * (Rr / 2) + i], s, c;
    sincosf(f, &s, &c);
    size_t base = (size_t)m * HRr + h * Rr + 2 * i;
    float x0 = Qr[base], x1 = Qr[base + 1];
    uint32_t hi, lo;
    split_pair(x0 * c - x1 * s, x0 * s + x1 * c, hi, lo);
    *reinterpret_cast<uint32_t*>(&Qrh[base]) = hi;
    *reinterpret_cast<uint32_t*>(&Qrl[base]) = lo;
}

// KRp has stride 128 (padded); outputs KRo (stride 64) + fp16 pairs
__global__ __launch_bounds__(256) void rope_k_kernel(
    const float* __restrict__ KRp, const float* __restrict__ freqs,
    float* __restrict__ KRout, __half* __restrict__ Krh, __half* __restrict__ Krl)
{
    int idx = blockIdx.x * 256 + threadIdx.x;
    if (idx >= MROWS * (Rr / 2)) return;
    int m = idx >> 5, i = idx & 31;
    int t = m & (Tt - 1);
    float f = freqs[t * (Rr / 2) + i], s, c;
    sincosf(f, &s, &c);
    float x0 = KRp[(size_t)m * 128 + 2 * i];
    float x1 = KRp[(size_t)m * 128 + 2 * i + 1];
    float y0 = x0 * c - x1 * s, y1 = x0 * s + x1 * c;
    size_t base = (size_t)m * Rr + 2 * i;
    KRout[base] = y0;
    KRout[base + 1] = y1;
    uint32_t hi, lo;
    split_pair(y0, y1, hi, lo);
    *reinterpret_cast<uint32_t*>(&Krh[base]) = hi;
    *reinterpret_cast<uint32_t*>(&Krl[base]) = lo;
}

// ---------------- merged projection kernels ----------------
// xproj: N-tiles [0,4)=cKV, [4,12)=cQ, 12=KR(pad). K=2048 for all.
__global__ __launch_bounds__(256) void xproj_kernel(
    const __half* __restrict__ xh, const __half* __restrict__ xl,
    const __half* __restrict__ WtH, const __half* __restrict__ WtL,
    float* __restrict__ cKVf, __half* __restrict__ cKVh, __half* __restrict__ cKVl,
    __half* __restrict__ cQh, __half* __restrict__ cQl, float* __restrict__ KRp)
{
    const int bx = blockIdx.x, bm = blockIdx.y * 128;
    const __half* Ah = xh + (size_t)bm * DM;
    const __half* Al = xl + (size_t)bm * DM;
    const __half *Bh, *Bl;
    float* Cf = nullptr;
    __half *Ch = nullptr, *Cl = nullptr;
    int strideN;
    if (bx < 4) {
        size_t bo = O_DKV + (size_t)(bx * 128) * DM;
        Bh = WtH + bo; Bl = WtL + bo;
        size_t co = (size_t)bm * KVL + bx * 128;
        Cf = cKVf + co; Ch = cKVh + co; Cl = cKVl + co;
        strideN = KVL;
    } else if (bx < 12) {
        size_t bo = O_DQ + (size_t)((bx - 4) * 128) * DM;
        Bh = WtH + bo; Bl = WtL + bo;
        size_t co = (size_t)bm * QL + (bx - 4) * 128;
        Ch = cQh + co; Cl = cQl + co;
        strideN = QL;
    } else {
        Bh = WtH + O_KRP; Bl = WtL + O_KRP;
        Cf = KRp + (size_t)bm * 128;
        strideN = 128;
    }
    gemm_core(Ah, Al, Bh, Bl, DM, Cf, Ch, Cl, strideN);
}

// kvproj: [0,16)=UK -> Kc pairs, [16,32)=UV -> V fp32. K=512.
__global__ __launch_bounds__(256) void kvproj_kernel(
    const __half* __restrict__ cKVh, const __half* __restrict__ cKVl,
    const __half* __restrict__ WtH, const __half* __restrict__ WtL,
    __half* __restrict__ Kch, __half* __restrict__ Kcl, float* __restrict__ Vf)
{
    const int bx = blockIdx.x, bm = blockIdx.y * 128;
    const __half* Ah = cKVh + (size_t)bm * KVL;
    const __half* Al = cKVl + (size_t)bm * KVL;
    if (bx < 16) {
        size_t bo = O_UK + (size_t)(bx * 128) * KVL;
        size_t co = (size_t)bm * HHD + bx * 128;
        gemm_core(Ah, Al, WtH + bo, WtL + bo, KVL,
                  nullptr, Kch + co, Kcl + co, HHD);
    } else {
        size_t bo = O_UV + (size_t)((bx - 16) * 128) * KVL;
        size_t co = (size_t)bm * HHD + (bx - 16) * 128;
        gemm_core(Ah, Al, WtH + bo, WtL + bo, KVL,
                  Vf + co, nullptr, nullptr, HHD);
    }
}

// qproj: [0,16)=UQ -> Qc pairs, [16,24)=QR -> Qr fp32. K=1024.
__global__ __launch_bounds__(256) void qproj_kernel(
    const __half* __restrict__ cQh, const __half* __restrict__ cQl,
    const __half* __restrict__ WtH, const __half* __restrict__ WtL,
    __half* __restrict__ Qch, __half* __restrict__ Qcl, float* __restrict__ Qrf)
{
    const int bx = blockIdx.x, bm = blockIdx.y * 128;
    const __half* Ah = cQh + (size_t)bm * QL;
    const __half* Al = cQl + (size_t)bm * QL;
    if (bx < 16) {
        size_t bo = O_UQ + (size_t)(bx * 128) * QL;
        size_t co = (size_t)bm * HHD + bx * 128;
        gemm_core(Ah, Al, WtH + bo, WtL + bo, QL,
                  nullptr, Qch + co, Qcl + co, HHD);
    } else {
        size_t bo = O_QR + (size_t)((bx - 16) * 128) * QL;
        size_t co = (size_t)bm * HRr + (bx - 16) * 128;
        gemm_core(Ah, Al, WtH + bo, WtL + bo, QL,
                  Qrf + co, nullptr, nullptr, HRr);
    }
}

// wo: y = AO @ W_O. K=2048.
__global__ __launch_bounds__(256) void wo_kernel(
    const __half* __restrict__ AOh, const __half* __restrict__ AOl,
    const __half* __restrict__ WtH, const __half* __restrict__ WtL,
    float* __restrict__ y)
{
    const int bx = blockIdx.x, bm = blockIdx.y * 128;
    size_t bo = O_O + (size_t)(bx * 128) * HHD;
    gemm_core(AOh + (size_t)bm * HHD, AOl + (size_t)bm * HHD,
              WtH + bo, WtL + bo, HHD,
              y + (size_t)bm * DM + bx * 128, nullptr, nullptr, DM);
}

// ---------------- sqk: per (qt,bh) CTA, Q persistent, loop kt -------------
__global__ __launch_bounds__(256) void sqk_kernel(
    const __half* __restrict__ Qch, const __half* __restrict__ Qcl,
    const __half* __restrict__ Qrh, const __half* __restrict__ Qrl,
    const __half* __restrict__ Kch, const __half* __restrict__ Kcl,
    const __half* __restrict__ Krh, const __half* __restrict__ Krl,
    float* __restrict__ S)
{
    const int qt = 15 - blockIdx.x, bh = blockIdx.y;
    const int tid = threadIdx.x;
    const int b = bh >> 4, h = bh & 15;
#if HAS_TCGEN05
    constexpr int T_BYTES = 128 * 128;   // 16 KB tile
    extern __shared__ char smem[];
    MmaCtx cx = mma_begin(smem, 256);
    const uint32_t qbase = cx.tiles;              // 6 tiles (96 KB)
    const uint32_t kbase = cx.tiles + 6 * T_BYTES; // 3 stages x 2 tiles
    const uint32_t idesc = (1u << 4) | (16u << 17) | (8u << 24);
    const size_t qrow0 = (size_t)(b * Tt + qt * 128);

    // load Q (6 tiles): c0 hi/lo, c1 hi/lo, rope hi/lo
    {
        const __half* qsrc[6] = {
            Qch + qrow0 * HHD + h * HD,       Qcl + qrow0 * HHD + h * HD,
            Qch + qrow0 * HHD + h * HD + 64,  Qcl + qrow0 * HHD + h * HD + 64,
            Qrh + qrow0 * HRr + h * Rr,       Qrl + qrow0 * HRr + h * Rr };
        const int qstr[6] = {HHD, HHD, HHD, HHD, HRr, HRr};
        #pragma unroll
        for (int i = 0; i < 24; i++) {
            int u = i * 256 + tid;
            int t = u >> 10, ul = u & 1023;
            int row = ul >> 3, seg = ul & 7;
            uint4 v = *reinterpret_cast<const uint4*>(
                qsrc[t] + (size_t)row * qstr[t] + seg * 8);
            uint32_t bofs = row * 128 + seg * 16;
            sts128(qbase + t * T_BYTES + (bofs ^ ((bofs >> 3) & 0x70)),
                   v.x, v.y, v.z, v.w);
        }
    }

    for (int kt = 0; kt <= qt; kt++) {
        const size_t krow0 = (size_t)(b * Tt + kt * 128);
        const uint32_t acc = cx.tmem + (kt & 1) * 128;
        for (int c = 0; c < 3; c++) {
            if (kt >= 1) MBAR_WAIT(cx.mb + 8 * c, (kt - 1) & 1);
            const uint32_t st = kbase + c * 2 * T_BYTES;
            const __half* kh = (c < 2) ? Kch + krow0 * HHD + h * HD + c * 64
                                       : Krh + krow0 * Rr;
            const __half* kl = (c < 2) ? Kcl + krow0 * HHD + h * HD + c * 64
                                       : Krl + krow0 * Rr;
            const int str = (c < 2) ? HHD : Rr;
            #pragma unroll
            for (int i = 0; i < 8; i++) {
                int u = i * 256 + tid;
                int t = u >> 10, ul = u & 1023;
                int row = ul >> 3, seg = ul & 7;
                const __half* src = t ? kl : kh;
                uint4 v = *reinterpret_cast<const uint4*>(
                    src + (size_t)row * str + seg * 8);
                uint32_t bofs = row * 128 + seg * 16;
                sts128(st + t * T_BYTES + (bofs ^ ((bofs >> 3) & 0x70)),
                       v.x, v.y, v.z, v.w);
            }
            FENCE_ASYNC();
            __syncthreads();
            mma_chunk(acc, cx.mb + 8 * c,
                      mk_desc(qbase + (c * 2) * T_BYTES),
                      mk_desc(qbase + (c * 2 + 1) * T_BYTES),
                      mk_desc(st), mk_desc(st + T_BYTES),
                      idesc, c == 0);
        }
        // wait all three chunk groups of this kt, then read out
        MBAR_WAIT(cx.mb + 0, kt & 1);
        MBAR_WAIT(cx.mb + 8, kt & 1);
        MBAR_WAIT(cx.mb + 16, kt & 1);
        T5_FENCE_AFTER();
        const int w = tid >> 5, l2 = tid & 31, sub = w & 3;
        const size_t rowoff = ((size_t)bh * Tt + qt * 128 + sub * 32 + l2) * Tt
                            + kt * 128;
        for (int b2 = (w >> 2) * 2; b2 < (w >> 2) * 2 + 2; b2++) {
            uint32_t r[32];
            LDTM_X32(r, acc + b2 * 32);
            T5_WAIT_LD();
            #pragma unroll
            for (int j = 0; j < 32; j += 4)
                *reinterpret_cast<float4*>(&S[rowoff + b2 * 32 + j]) = make_float4(
                    __uint_as_float(r[j]), __uint_as_float(r[j+1]),
                    __uint_as_float(r[j+2]), __uint_as_float(r[j+3]));
        }
    }
    __syncthreads();
    if (tid < 32) T5_DEALLOC(cx.tmem, 256);
#else
    for (int kt = 0; kt <= qt; kt++)
        for (int e = tid; e < 128 * 128; e += 256) {
            int r = e >> 7, c = e & 127;
            int q = qt * 128 + r, k = kt * 128 + c;
            float acc = 0.f;
            for (int d = 0; d < 128; d++)
                acc += (__half2float(Qch[(size_t)(b*Tt+q)*HHD + h*HD + d]) + __half2float(Qcl[(size_t)(b*Tt+q)*HHD + h*HD + d]))
                     * (__half2float(Kch[(size_t)(b*Tt+k)*HHD + h*HD + d]) + __half2float(Kcl[(size_t)(b*Tt+k)*HHD + h*HD + d]));
            for (int d = 0; d < 64; d++)
                acc += (__half2float(Qrh[(size_t)(b*Tt+q)*HRr + h*Rr + d]) + __half2float(Qrl[(size_t)(b*Tt+q)*HRr + h*Rr + d]))
                     * (__half2float(Krh[(size_t)(b*Tt+k)*Rr + d]) + __half2float(Krl[(size_t)(b*Tt+k)*Rr + d]));
            S[((size_t)bh * Tt + q) * Tt + k] = acc;
        }
#endif
}

// ---------------- softmax: S -> unnormalized P(fp16 h/l) + row sums -------
__global__ __launch_bounds__(256) void softmax_kernel(
    const float* __restrict__ S, __half* __restrict__ Ph,
    __half* __restrict__ Pl, float* __restrict__ L)
{
    const float scale = 0.07216878364870323f;
    int gw = blockIdx.x * 8 + (threadIdx.x >> 5);
    int bh = gw >> 11, q = gw & 2047;
    int lane = threadIdx.x & 31;
    const float* row = S + ((size_t)bh * Tt + q) * Tt;
    const int n = q + 1;
    const int ktE = ((q >> 7) + 1) * 128;

    float m = -1e30f;
    for (int i = lane * 4; i < ktE; i += 128) {
        float4 v = *reinterpret_cast<const float4*>(&row[i]);
        if (i + 0 < n) m = fmaxf(m, v.x);
        if (i + 1 < n) m = fmaxf(m, v.y);
        if (i + 2 < n) m = fmaxf(m, v.z);
        if (i + 3 < n) m = fmaxf(m, v.w);
    }
    #pragma unroll
    for (int off = 16; off >= 1; off >>= 1)
        m = fmaxf(m, __shfl_xor_sync(0xffffffffu, m, off));
    m *= scale;

    float l = 0.f;
    size_t pbase = ((size_t)bh * Tt + q) * Tt;
    for (int i = lane * 8; i < ktE; i += 256) {
        float4 v0 = *reinterpret_cast<const float4*>(&row[i]);
        float4 v1 = *reinterpret_cast<const float4*>(&row[i + 4]);
        float vv[8] = {v0.x, v0.y, v0.z, v0.w, v1.x, v1.y, v1.z, v1.w};
        float p[8];
        #pragma unroll
        for (int j = 0; j < 8; j++) {
            p[j] = (i + j < n) ? __expf(vv[j] * scale - m) : 0.f;
            l += p[j];
        }
        uint4 hv, lv;
        split_pair(p[0], p[1], hv.x, lv.x);
        split_pair(p[2], p[3], hv.y, lv.y);
        split_pair(p[4], p[5], hv.z, lv.z);
        split_pair(p[6], p[7], hv.w, lv.w);
        *reinterpret_cast<uint4*>(&Ph[pbase + i]) = hv;
        *reinterpret_cast<uint4*>(&Pl[pbase + i]) = lv;
    }
    #pragma unroll
    for (int off = 16; off >= 1; off >>= 1)
        l += __shfl_xor_sync(0xffffffffu, l, off);
    if (lane == 0) L[bh * Tt + q] = l;
}

// ---------------- O = P @ V (fp16x3), normalize in epilogue ----------------
__global__ __launch_bounds__(256) void pv_kernel(
    const __half* __restrict__ Ph, const __half* __restrict__ Pl,
    const __half* __restrict__ Vth, const __half* __restrict__ Vtl,
    const float* __restrict__ L, __half* __restrict__ AOh, __half* __restrict__ AOl)
{
    const int qt = 15 - blockIdx.x, bh = blockIdx.y;
    const int tid = threadIdx.x;
    const int b = bh >> 4, h = bh & 15;
#if HAS_TCGEN05
    constexpr int T_BYTES = 128 * 128;
    constexpr int STAGE = 4 * T_BYTES;
    extern __shared__ char smem[];
    MmaCtx cx = mma_begin(smem, 128);
    const uint32_t idesc = (1u << 4) | (16u << 17) | (8u << 24);
    const int nc = (qt + 1) * 2;
    const __half* psrc[4] = {Ph + ((size_t)bh * Tt + qt * 128) * Tt,
                             Pl + ((size_t)bh * Tt + qt * 128) * Tt,
                             Vth + (size_t)bh * HD * Tt,
                             Vtl + (size_t)bh * HD * Tt};
    for (int c = 0; c < nc; c++) {
        const int s = c - (c / 3) * 3;
        const uint32_t st = cx.tiles + s * STAGE;
        if (c >= 3) MBAR_WAIT(cx.mb + 8 * s, ((c / 3) - 1) & 1);
        const int k0 = c * 64;
        uint4 v[16];
        uint32_t da[16];
        #pragma unroll
        for (int i = 0; i < 16; i++) {
            int u = i * 256 + tid;
            int t = u >> 10, ul = u & 1023;
            int row = ul >> 3, seg = ul & 7;
            v[i] = *reinterpret_cast<const uint4*>(psrc[t] + (size_t)row * Tt + k0 + seg * 8);
            uint32_t bofs = row * 128 + seg * 16;
            da[i] = st + t * T_BYTES + (bofs ^ ((bofs >> 3) & 0x70));
        }
        #pragma unroll
        for (int i = 0; i < 16; i++)
            sts128(da[i], v[i].x, v[i].y, v[i].z, v[i].w);
        FENCE_ASYNC();
        __syncthreads();
        mma_chunk(cx.tmem, cx.mb + 8 * s,
                  mk_desc(st), mk_desc(st + T_BYTES),
                  mk_desc(st + 2 * T_BYTES), mk_desc(st + 3 * T_BYTES),
                  idesc, c == 0);
    }
    if (tid < 32 && elect1()) T5_COMMIT(cx.mb_done);
    MBAR_WAIT(cx.mb_done, 0);
    T5_FENCE_AFTER();

    const int w = tid >> 5, l2 = tid & 31, sub = w & 3;
    const int qrow = qt * 128 + sub * 32 + l2;
    const float invl = 1.0f / L[bh * Tt + qrow];
    const size_t off0 = (size_t)(b * Tt + qrow) * HHD + h * HD;
    for (int b2 = (w >> 2) * 2; b2 < (w >> 2) * 2 + 2; b2++) {
        uint32_t r[32];
        LDTM_X32(r, cx.tmem + b2 * 32);
        T5_WAIT_LD();
        #pragma unroll
        for (int j = 0; j < 32; j += 8) {
            uint4 hv, lv;
            split_pair(__uint_as_float(r[j+0]) * invl, __uint_as_float(r[j+1]) * invl, hv.x, lv.x);
            split_pair(__uint_as_float(r[j+2]) * invl, __uint_as_float(r[j+3]) * invl, hv.y, lv.y);
            split_pair(__uint_as_float(r[j+4]) * invl, __uint_as_float(r[j+5]) * invl, hv.z, lv.z);
            split_pair(__uint_as_float(r[j+6]) * invl, __uint_as_float(r[j+7]) * invl, hv.w, lv.w);
            *reinterpret_cast<uint4*>(&AOh[off0 + b2 * 32 + j]) = hv;
            *reinterpret_cast<uint4*>(&AOl[off0 + b2 * 32 + j]) = lv;
        }
    }
    __syncthreads();
    if (tid < 32) T5_DEALLOC(cx.tmem, 128);
#else
    const int K = (qt + 1) * 128;
    for (int e = tid; e < 128 * 128; e += 256) {
        int r = e >> 7, d = e & 127;
        int qrow = qt * 128 + r;
        float acc = 0.f;
        for (int k = 0; k < K; k++)
            acc += (__half2float(Ph[((size_t)bh*Tt + qrow)*Tt + k]) + __half2float(Pl[((size_t)bh*Tt + qrow)*Tt + k]))
                 * (__half2float(Vth[((size_t)bh*HD + d)*Tt + k]) + __half2float(Vtl[((size_t)bh*HD + d)*Tt + k]));
        acc /= L[bh * Tt + qrow];
        size_t off = (size_t)(b * Tt + qrow) * HHD + h * HD + d;
        __half hh = __float2half_rn(acc);
        AOh[off] = hh;
        AOl[off] = __float2half_rn(acc - __half2float(hh));
    }
#endif
}

// ---------------- launch ----------------
#define MMA_SMEM 200704

extern "C" void kernel_launch(void* const* d_in, const int* in_sizes, int n_in,
                              void* d_out, int out_size)
{
    const float* x     = (const float*)d_in[0];
    const float* freqs = (const float*)d_in[1];
    const float* W_DKV = (const float*)d_in[2];
    const float* W_UK  = (const float*)d_in[3];
    const float* W_UV  = (const float*)d_in[4];
    const float* W_KR  = (const float*)d_in[5];
    const float* W_DQ  = (const float*)d_in[6];
    const float* W_UQ  = (const float*)d_in[7];
    const float* W_QR  = (const float*)d_in[8];
    const float* W_O   = (const float*)d_in[9];

    float* y   = (float*)d_out;
    float* cKV = y   + (size_t)Bb * Tt * DM;
    float* KRo = cKV + (size_t)Bb * Tt * KVL;

    float *pV, *pQr, *pKRp, *pS, *pL;
    __half *pxH, *pxL, *pWtH, *pWtL, *pcKVh, *pcKVl, *pcQh, *pcQl;
    __half *pQch, *pQcl, *pQrh, *pQrl, *pKch, *pKcl, *pKrh, *pKrl;
    __half *pVth, *pVtl, *pAOh, *pAOl, *pPh, *pPl;
    cudaGetSymbolAddress((void**)&pV,   g_V);
    cudaGetSymbolAddress((void**)&pQr,  g_Qr);
    cudaGetSymbolAddress((void**)&pKRp, g_KRp);
    cudaGetSymbolAddress((void**)&pS,   g_S);
    cudaGetSymbolAddress((void**)&pL,   g_L);
    cudaGetSymbolAddress((void**)&pxH,  g_xH);
    cudaGetSymbolAddress((void**)&pxL,  g_xL);
    cudaGetSymbolAddress((void**)&pWtH, g_WtH);
    cudaGetSymbolAddress((void**)&pWtL, g_WtL);
    cudaGetSymbolAddress((void**)&pcKVh, g_cKVh);
    cudaGetSymbolAddress((void**)&pcKVl, g_cKVl);
    cudaGetSymbolAddress((void**)&pcQh, g_cQh);
    cudaGetSymbolAddress((void**)&pcQl, g_cQl);
    cudaGetSymbolAddress((void**)&pQch, g_Qch);
    cudaGetSymbolAddress((void**)&pQcl, g_Qcl);
    cudaGetSymbolAddress((void**)&pQrh, g_Qrh);
    cudaGetSymbolAddress((void**)&pQrl, g_Qrl);
    cudaGetSymbolAddress((void**)&pKch, g_Kch);
    cudaGetSymbolAddress((void**)&pKcl, g_Kcl);
    cudaGetSymbolAddress((void**)&pKrh, g_Krh);
    cudaGetSymbolAddress((void**)&pKrl, g_Krl);
    cudaGetSymbolAddress((void**)&pVth, g_Vth);
    cudaGetSymbolAddress((void**)&pVtl, g_Vtl);
    cudaGetSymbolAddress((void**)&pAOh, g_AOh);
    cudaGetSymbolAddress((void**)&pAOl, g_AOl);
    cudaGetSymbolAddress((void**)&pPh,  g_Ph);
    cudaGetSymbolAddress((void**)&pPl,  g_Pl);

    cudaFuncSetAttribute(xproj_kernel,  cudaFuncAttributeMaxDynamicSharedMemorySize, MMA_SMEM);
    cudaFuncSetAttribute(kvproj_kernel, cudaFuncAttributeMaxDynamicSharedMemorySize, MMA_SMEM);
    cudaFuncSetAttribute(qproj_kernel,  cudaFuncAttributeMaxDynamicSharedMemorySize, MMA_SMEM);
    cudaFuncSetAttribute(wo_kernel,     cudaFuncAttributeMaxDynamicSharedMemorySize, MMA_SMEM);
    cudaFuncSetAttribute(sqk_kernel,    cudaFuncAttributeMaxDynamicSharedMemorySize, MMA_SMEM);
    cudaFuncSetAttribute(pv_kernel,     cudaFuncAttributeMaxDynamicSharedMemorySize, MMA_SMEM);

    // #1: split x
    split_x_kernel<<<(MROWS * DM / 4) / 256, 256>>>(x, pxH, pxL);

    // #2: all weight transposes (KR padded into 128x2048 region, rows 64+ stay 0)
    TSJobs jobs;
    int tiles = 0;
    auto addjob = [&](int i, const float* W, size_t off, int K, int N) {
        jobs.a[i] = {W, pWtH + off, pWtL + off, K, N, tiles};
        tiles += (K / 32) * (N / 32);
    };
    addjob(0, W_DKV, O_DKV, DM, KVL);
    addjob(1, W_UK,  O_UK,  KVL, HHD);
    addjob(2, W_UV,  O_UV,  KVL, HHD);
    addjob(3, W_DQ,  O_DQ,  DM, QL);
    addjob(4, W_UQ,  O_UQ,  QL, HHD);
    addjob(5, W_QR,  O_QR,  QL, HRr);
    addjob(6, W_O,   O_O,   HHD, DM);
    addjob(7, W_KR,  O_KRP, DM, Rr);
    tsplit_all_kernel<<<tiles, 256>>>(jobs);

    // #3: xproj (cKV | cQ | KR)
    xproj_kernel<<<dim3(13, MROWS/128), 256, MMA_SMEM>>>(
        pxH, pxL, pWtH, pWtL, cKV, pcKVh, pcKVl, pcQh, pcQl, pKRp);
    // #4: rope K
    rope_k_kernel<<<(MROWS * (Rr/2) + 255) / 256, 256>>>(pKRp, freqs, KRo, pKrh, pKrl);
    // #5: kvproj (UK | UV)
    kvproj_kernel<<<dim3(32, MROWS/128), 256, MMA_SMEM>>>(
        pcKVh, pcKVl, pWtH, pWtL, pKch, pKcl, pV);
    // #6: qproj (UQ | QR)
    qproj_kernel<<<dim3(24, MROWS/128), 256, MMA_SMEM>>>(
        pcQh, pcQl, pWtH, pWtL, pQch, pQcl, pQr);
    // #7: rope Q
    rope_q_kernel<<<(MROWS * Hh * (Rr/2) + 255) / 256, 256>>>(pQr, freqs, pQrh, pQrl);
    // #8: V transpose + split
    transpose_v_kernel<<<dim3(Tt/32, HD/32, BH), 256>>>(pV, pVth, pVtl);
    // #9: S = Q K^T
    sqk_kernel<<<dim3(16, BH), 256, MMA_SMEM>>>(
        pQch, pQcl, pQrh, pQrl, pKch, pKcl, pKrh, pKrl, pS);
    // #10: softmax
    softmax_kernel<<<(BH * Tt) / 8, 256>>>(pS, pPh, pPl, pL);
    // #11: O = P V
    pv_kernel<<<dim3(16, BH), 256, MMA_SMEM>>>(pPh, pPl, pVth, pVtl, pL, pAOh, pAOl);
    // #12: y = AO @ W_O
    wo_kernel<<<dim3(16, MROWS/128), 256, MMA_SMEM>>>(pAOh, pAOl, pWtH, pWtL, y);
}

// round 8
// speedup vs baseline: 2.7358x; 1.2425x over previous
#include <cuda_runtime.h>
#include <cuda_fp16.h>
#include <math.h>
#include <stdint.h>

#define Bb 2
#define Tt 2048
#define DM 2048
#define Hh 16
#define HD 128
#define KVL 512
#define QL 1024
#define Rr 64
#define MROWS (Bb*Tt)
#define BH (Bb*Hh)
#define HHD (Hh*HD)
#define HRr (Hh*Rr)

#if defined(__CUDA_ARCH_FEAT_SM103_ALL) || defined(__CUDA_ARCH_FEAT_SM100_ALL)
#define HAS_TCGEN05 1
#else
#define HAS_TCGEN05 0
#endif

// ---------------- scratch ----------------
__device__ float g_V [MROWS * HHD];
__device__ float g_Qr[MROWS * HRr];
__device__ float g_KRp[MROWS * 128];            // padded KR (stride 128)
__device__ __half g_xH[MROWS * DM],  g_xL[MROWS * DM];
__device__ __half g_cKVh[MROWS * KVL], g_cKVl[MROWS * KVL];
__device__ __half g_cQh[MROWS * QL],   g_cQl[MROWS * QL];
__device__ __half g_Qch[MROWS * HHD],  g_Qcl[MROWS * HHD];
__device__ __half g_Qrh[MROWS * HRr],  g_Qrl[MROWS * HRr];
__device__ __half g_Kch[MROWS * HHD],  g_Kcl[MROWS * HHD];
__device__ __half g_Krh[MROWS * Rr],   g_Krl[MROWS * Rr];
__device__ __half g_Vth[BH * HD * Tt], g_Vtl[BH * HD * Tt];
__device__ __half g_AOh[MROWS * HHD],  g_AOl[MROWS * HHD];
#define O_DKV 0
#define O_UK  (O_DKV + 512*2048)
#define O_UV  (O_UK  + 2048*512)
#define O_DQ  (O_UV  + 2048*512)
#define O_UQ  (O_DQ  + 1024*2048)
#define O_QR  (O_UQ  + 2048*1024)
#define O_O   (O_QR  + 2048*1024)
#define O_KRP (O_O   + 2048*2048)
#define WT_TOTAL (O_KRP + 128*2048)
__device__ __half g_WtH[WT_TOTAL], g_WtL[WT_TOTAL];

// ---------------- helpers ----------------
__device__ __forceinline__ uint32_t smem_u32(const void* p) {
    uint32_t a;
    asm("{ .reg .u64 t; cvta.to.shared.u64 t, %1; cvt.u32.u64 %0, t; }"
        : "=r"(a) : "l"(p));
    return a;
}
__device__ __forceinline__ void split_pair(float a, float b,
                                           uint32_t& hi, uint32_t& lo) {
    __half ha = __float2half_rn(a), hb = __float2half_rn(b);
    hi = ((uint32_t)__half_as_ushort(hb) << 16) | __half_as_ushort(ha);
    lo = ((uint32_t)__half_as_ushort(__float2half_rn(b - __half2float(hb))) << 16)
       | __half_as_ushort(__float2half_rn(a - __half2float(ha)));
}

#if HAS_TCGEN05
__device__ __forceinline__ bool elect1() {
    uint32_t r;
    asm volatile("{\n\t.reg .pred p;\n\telect.sync _|p, 0xFFFFFFFF;\n\t"
                 "selp.b32 %0,1,0,p;\n\t}" : "=r"(r));
    return r != 0;
}
#define MBAR_INIT(a, c) \
    asm volatile("mbarrier.init.shared.b64 [%0], %1;" :: "r"(a), "r"(c) : "memory")
#define MBAR_WAIT(a, ph) do { \
    uint32_t _m = (a), _p = (uint32_t)(ph), _d; \
    asm volatile("{\n\t.reg .pred p;\n\t" \
        "mbarrier.try_wait.parity.acquire.cta.shared::cta.b64 p, [%1], %2;\n\t" \
        "selp.b32 %0,1,0,p;\n\t}" : "=r"(_d) : "r"(_m), "r"(_p) : "memory"); \
    while (!_d) { \
        asm volatile("{\n\t.reg .pred p;\n\t" \
            "mbarrier.try_wait.parity.acquire.cta.shared::cta.b64 p, [%1], %2, 0x989680;\n\t" \
            "selp.b32 %0,1,0,p;\n\t}" : "=r"(_d) : "r"(_m), "r"(_p) : "memory"); \
    } } while (0)
#define T5_COMMIT(a) \
    asm volatile("tcgen05.commit.cta_group::1.mbarrier::arrive::one.shared::cluster.b64 [%0];" \
                 :: "r"(a) : "memory")
#define T5_ALLOC(a, n) \
    asm volatile("tcgen05.alloc.cta_group::1.sync.aligned.shared::cta.b32 [%0], %1;" \
                 :: "r"(a), "r"(n) : "memory")
#define T5_DEALLOC(t, n) \
    asm volatile("tcgen05.dealloc.cta_group::1.sync.aligned.b32 %0, %1;" :: "r"(t), "r"(n))
#define T5_RELINQ() \
    asm volatile("tcgen05.relinquish_alloc_permit.cta_group::1.sync.aligned;")
#define T5_WAIT_LD()   asm volatile("tcgen05.wait::ld.sync.aligned;" ::: "memory")
#define T5_FENCE_AFTER() asm volatile("tcgen05.fence::after_thread_sync;" ::: "memory")
#define T5_FENCE_BEFORE() asm volatile("tcgen05.fence::before_thread_sync;" ::: "memory")
#define FENCE_ASYNC()  asm volatile("fence.proxy.async.shared::cta;" ::: "memory")

#define LDTM_X32(r, addr) \
    asm volatile("tcgen05.ld.sync.aligned.32x32b.x32.b32 " \
        "{%0, %1, %2, %3, %4, %5, %6, %7, %8, %9, %10, %11, %12, %13, %14, %15, " \
        "%16, %17, %18, %19, %20, %21, %22, %23, %24, %25, %26, %27, %28, %29, %30, %31}, [%32];" \
        : "=r"((r)[0]),  "=r"((r)[1]),  "=r"((r)[2]),  "=r"((r)[3]), \
          "=r"((r)[4]),  "=r"((r)[5]),  "=r"((r)[6]),  "=r"((r)[7]), \
          "=r"((r)[8]),  "=r"((r)[9]),  "=r"((r)[10]), "=r"((r)[11]), \
          "=r"((r)[12]), "=r"((r)[13]), "=r"((r)[14]), "=r"((r)[15]), \
          "=r"((r)[16]), "=r"((r)[17]), "=r"((r)[18]), "=r"((r)[19]), \
          "=r"((r)[20]), "=r"((r)[21]), "=r"((r)[22]), "=r"((r)[23]), \
          "=r"((r)[24]), "=r"((r)[25]), "=r"((r)[26]), "=r"((r)[27]), \
          "=r"((r)[28]), "=r"((r)[29]), "=r"((r)[30]), "=r"((r)[31]) \
        : "r"(addr))

__device__ __forceinline__ void mma_f16(uint32_t d, uint64_t ad, uint64_t bd,
                                        uint32_t idesc, uint32_t en) {
    asm volatile("{\n\t.reg .pred p;\n\tsetp.ne.u32 p, %4, 0;\n\t"
        "tcgen05.mma.cta_group::1.kind::f16 [%0], %1, %2, %3, p;\n\t}"
        :: "r"(d), "l"(ad), "l"(bd), "r"(idesc), "r"(en) : "memory");
}
__device__ __forceinline__ uint64_t mk_desc(uint32_t addr) {
    return ((uint64_t)2 << 61) | ((uint64_t)1 << 46) | ((uint64_t)64 << 32)
         | ((uint64_t)1 << 16) | ((addr >> 4) & 0x3FFF);
}
__device__ __forceinline__ void sts128(uint32_t addr, uint32_t a, uint32_t b,
                                       uint32_t c, uint32_t d) {
    asm volatile("st.shared.v4.b32 [%0], {%1,%2,%3,%4};"
                 :: "r"(addr), "r"(a), "r"(b), "r"(c), "r"(d) : "memory");
}
struct MmaCtx { uint32_t mb, mb_done, tmem, tiles; };
__device__ __forceinline__ MmaCtx mma_begin(char* smem, int ncols) {
    MmaCtx cx;
    uint32_t sbase = smem_u32(smem);
    cx.mb = sbase;
    cx.mb_done = sbase + 24;
    cx.tiles = (sbase + 64 + 1023) & ~1023u;
    if (threadIdx.x == 0) {
        MBAR_INIT(cx.mb + 0, 1);
        MBAR_INIT(cx.mb + 8, 1);
        MBAR_INIT(cx.mb + 16, 1);
        MBAR_INIT(cx.mb_done, 1);
    }
    if (threadIdx.x < 32) { T5_ALLOC(sbase + 32, ncols); T5_RELINQ(); }
    __syncthreads();
    asm volatile("ld.shared.b32 %0, [%1];" : "=r"(cx.tmem) : "r"(sbase + 32));
    return cx;
}
// 12 MMAs (hh, hl, lh) for one K=64 chunk
__device__ __forceinline__ void mma_chunk(uint32_t tmem, uint32_t mbar,
                                          uint64_t ah, uint64_t al,
                                          uint64_t bh, uint64_t bl,
                                          uint32_t idesc, bool first) {
    if (threadIdx.x < 32 && elect1()) {
        #pragma unroll
        for (int q = 0; q < 4; q++)
            mma_f16(tmem, ah + 2*q, bh + 2*q, idesc, (first && q == 0) ? 0u : 1u);
        #pragma unroll
        for (int q = 0; q < 4; q++)
            mma_f16(tmem, ah + 2*q, bl + 2*q, idesc, 1u);
        #pragma unroll
        for (int q = 0; q < 4; q++)
            mma_f16(tmem, al + 2*q, bh + 2*q, idesc, 1u);
        T5_COMMIT(mbar);
    }
}
#endif

// ---------------- generic fp16x3 GEMM core (TN=128, K-chunk 64) -----------
__device__ __forceinline__ void gemm_core(
    const __half* Ah, const __half* Al,
    const __half* Bh, const __half* Bl, int K,
    float* Cf, __half* Ch, __half* Cl, int strideN)
{
    const int tid = threadIdx.x;
#if HAS_TCGEN05
    constexpr int T_BYTES = 128 * 128;
    constexpr int STAGE = 4 * T_BYTES;
    extern __shared__ char smem[];
    MmaCtx cx = mma_begin(smem, 128);
    const uint32_t idesc = (1u << 4) | (16u << 17) | (8u << 24);
    const int nc = K >> 6;
    const __half* psrc[4] = {Ah, Al, Bh, Bl};
    for (int c = 0; c < nc; c++) {
        const int s = c - (c / 3) * 3;
        const uint32_t st = cx.tiles + s * STAGE;
        if (c >= 3) MBAR_WAIT(cx.mb + 8 * s, ((c / 3) - 1) & 1);
        const int k0 = c * 64;
        uint4 v[16];
        uint32_t da[16];
        #pragma unroll
        for (int i = 0; i < 16; i++) {
            int u = i * 256 + tid;
            int t = u >> 10, ul = u & 1023;
            int row = ul >> 3, seg = ul & 7;
            v[i] = *reinterpret_cast<const uint4*>(psrc[t] + (size_t)row * K + k0 + seg * 8);
            uint32_t bofs = row * 128 + seg * 16;
            da[i] = st + t * T_BYTES + (bofs ^ ((bofs >> 3) & 0x70));
        }
        #pragma unroll
        for (int i = 0; i < 16; i++)
            sts128(da[i], v[i].x, v[i].y, v[i].z, v[i].w);
        FENCE_ASYNC();
        __syncthreads();
        mma_chunk(cx.tmem, cx.mb + 8 * s,
                  mk_desc(st), mk_desc(st + T_BYTES),
                  mk_desc(st + 2 * T_BYTES), mk_desc(st + 3 * T_BYTES),
                  idesc, c == 0);
    }
    if (tid < 32 && elect1()) T5_COMMIT(cx.mb_done);
    MBAR_WAIT(cx.mb_done, 0);
    T5_FENCE_AFTER();

    const int w = tid >> 5, l2 = tid & 31, sub = w & 3;
    const int row = sub * 32 + l2;
    for (int b2 = (w >> 2) * 2; b2 < (w >> 2) * 2 + 2; b2++) {
        uint32_t r[32];
        LDTM_X32(r, cx.tmem + b2 * 32);
        T5_WAIT_LD();
        size_t off = (size_t)row * strideN + b2 * 32;
        if (Cf) {
            #pragma unroll
            for (int j = 0; j < 32; j += 4)
                *reinterpret_cast<float4*>(&Cf[off + j]) = make_float4(
                    __uint_as_float(r[j]), __uint_as_float(r[j+1]),
                    __uint_as_float(r[j+2]), __uint_as_float(r[j+3]));
        }
        if (Ch) {
            #pragma unroll
            for (int j = 0; j < 32; j += 8) {
                uint4 hv, lv;
                split_pair(__uint_as_float(r[j+0]), __uint_as_float(r[j+1]), hv.x, lv.x);
                split_pair(__uint_as_float(r[j+2]), __uint_as_float(r[j+3]), hv.y, lv.y);
                split_pair(__uint_as_float(r[j+4]), __uint_as_float(r[j+5]), hv.z, lv.z);
                split_pair(__uint_as_float(r[j+6]), __uint_as_float(r[j+7]), hv.w, lv.w);
                *reinterpret_cast<uint4*>(&Ch[off + j]) = hv;
                *reinterpret_cast<uint4*>(&Cl[off + j]) = lv;
            }
        }
    }
    __syncthreads();
    if (tid < 32) T5_DEALLOC(cx.tmem, 128);
#else
    for (int e = tid; e < 128 * 128; e += 256) {
        int r = e >> 7, cc = e & 127;
        float acc = 0.f;
        for (int k = 0; k < K; k++)
            acc += (__half2float(Ah[(size_t)r*K+k]) + __half2float(Al[(size_t)r*K+k]))
                 * (__half2float(Bh[(size_t)cc*K+k]) + __half2float(Bl[(size_t)cc*K+k]));
        size_t off = (size_t)r * strideN + cc;
        if (Cf) Cf[off] = acc;
        if (Ch) {
            __half h = __float2half_rn(acc);
            Ch[off] = h;
            Cl[off] = __float2half_rn(acc - __half2float(h));
        }
    }
#endif
}

// ---------------- producers ----------------
__global__ __launch_bounds__(256) void split_x_kernel(
    const float* __restrict__ x, __half* __restrict__ xh, __half* __restrict__ xl)
{
    size_t i = (size_t)(blockIdx.x * 256 + threadIdx.x) * 4;
    float4 v = *reinterpret_cast<const float4*>(&x[i]);
    uint32_t h0, l0, h1, l1;
    split_pair(v.x, v.y, h0, l0);
    split_pair(v.z, v.w, h1, l1);
    *reinterpret_cast<uint2*>(&xh[i]) = make_uint2(h0, h1);
    *reinterpret_cast<uint2*>(&xl[i]) = make_uint2(l0, l1);
}

struct TSJob { const float* W; __half* H; __half* L; int K; int N; int tile0; };
struct TSJobs { TSJob a[8]; };

__global__ __launch_bounds__(256) void tsplit_all_kernel(TSJobs jobs)
{
    __shared__ float t[32][33];
    int bx = blockIdx.x;
    int ji = 0;
    #pragma unroll
    for (int i = 1; i < 8; i++)
        if (bx >= jobs.a[i].tile0) ji = i;
    TSJob j = jobs.a[ji];
    int tl = bx - j.tile0;
    int ntN = j.N >> 5;
    int n0 = (tl % ntN) * 32, k0 = (tl / ntN) * 32;
    int tx = threadIdx.x & 31, ty = threadIdx.x >> 5;
    #pragma unroll
    for (int i = ty; i < 32; i += 8)
        t[i][tx] = j.W[(size_t)(k0 + i) * j.N + n0 + tx];
    __syncthreads();
    #pragma unroll
    for (int i = ty; i < 32; i += 8) {
        float v = t[tx][i];
        __half h = __float2half_rn(v);
        j.H[(size_t)(n0 + i) * j.K + k0 + tx] = h;
        j.L[(size_t)(n0 + i) * j.K + k0 + tx] = __float2half_rn(v - __half2float(h));
    }
}

__global__ __launch_bounds__(256) void transpose_v_kernel(
    const float* __restrict__ V, __half* __restrict__ Vth, __half* __restrict__ Vtl)
{
    __shared__ float t[32][33];
    int bh = blockIdx.z, b = bh >> 4, h = bh & 15;
    int t0 = blockIdx.x * 32, d0 = blockIdx.y * 32;
    int tx = threadIdx.x & 31, ty = threadIdx.x >> 5;
    #pragma unroll
    for (int i = ty; i < 32; i += 8)
        t[i][tx] = V[(size_t)(b * Tt + t0 + i) * HHD + h * HD + d0 + tx];
    __syncthreads();
    #pragma unroll
    for (int i = ty; i < 32; i += 8) {
        float v = t[tx][i];
        __half hh = __float2half_rn(v);
        size_t o = ((size_t)bh * HD + d0 + i) * Tt + t0 + tx;
        Vth[o] = hh;
        Vtl[o] = __float2half_rn(v - __half2float(hh));
    }
}

__global__ __launch_bounds__(256) void rope_q_kernel(
    const float* __restrict__ Qr, const float* __restrict__ freqs,
    __half* __restrict__ Qrh, __half* __restrict__ Qrl)
{
    int idx = blockIdx.x * 256 + threadIdx.x;
    if (idx >= MROWS * Hh * (Rr / 2)) return;
    int m = idx >> 9, rem = idx & 511, h = rem >> 5, i = rem & 31;
    int t = m & (Tt - 1);
    float f = freqs[t * (Rr / 2) + i], s, c;
    sincosf(f, &s, &c);
    size_t base = (size_t)m * HRr + h * Rr + 2 * i;
    float x0 = Qr[base], x1 = Qr[base + 1];
    uint32_t hi, lo;
    split_pair(x0 * c - x1 * s, x0 * s + x1 * c, hi, lo);
    *reinterpret_cast<uint32_t*>(&Qrh[base]) = hi;
    *reinterpret_cast<uint32_t*>(&Qrl[base]) = lo;
}

__global__ __launch_bounds__(256) void rope_k_kernel(
    const float* __restrict__ KRp, const float* __restrict__ freqs,
    float* __restrict__ KRout, __half* __restrict__ Krh, __half* __restrict__ Krl)
{
    int idx = blockIdx.x * 256 + threadIdx.x;
    if (idx >= MROWS * (Rr / 2)) return;
    int m = idx >> 5, i = idx & 31;
    int t = m & (Tt - 1);
    float f = freqs[t * (Rr / 2) + i], s, c;
    sincosf(f, &s, &c);
    float x0 = KRp[(size_t)m * 128 + 2 * i];
    float x1 = KRp[(size_t)m * 128 + 2 * i + 1];
    float y0 = x0 * c - x1 * s, y1 = x0 * s + x1 * c;
    size_t base = (size_t)m * Rr + 2 * i;
    KRout[base] = y0;
    KRout[base + 1] = y1;
    uint32_t hi, lo;
    split_pair(y0, y1, hi, lo);
    *reinterpret_cast<uint32_t*>(&Krh[base]) = hi;
    *reinterpret_cast<uint32_t*>(&Krl[base]) = lo;
}

// ---------------- merged projection kernels ----------------
__global__ __launch_bounds__(256) void xproj_kernel(
    const __half* __restrict__ xh, const __half* __restrict__ xl,
    const __half* __restrict__ WtH, const __half* __restrict__ WtL,
    float* __restrict__ cKVf, __half* __restrict__ cKVh, __half* __restrict__ cKVl,
    __half* __restrict__ cQh, __half* __restrict__ cQl, float* __restrict__ KRp)
{
    const int bx = blockIdx.x, bm = blockIdx.y * 128;
    const __half* Ah = xh + (size_t)bm * DM;
    const __half* Al = xl + (size_t)bm * DM;
    const __half *Bh, *Bl;
    float* Cf = nullptr;
    __half *Ch = nullptr, *Cl = nullptr;
    int strideN;
    if (bx < 4) {
        size_t bo = O_DKV + (size_t)(bx * 128) * DM;
        Bh = WtH + bo; Bl = WtL + bo;
        size_t co = (size_t)bm * KVL + bx * 128;
        Cf = cKVf + co; Ch = cKVh + co; Cl = cKVl + co;
        strideN = KVL;
    } else if (bx < 12) {
        size_t bo = O_DQ + (size_t)((bx - 4) * 128) * DM;
        Bh = WtH + bo; Bl = WtL + bo;
        size_t co = (size_t)bm * QL + (bx - 4) * 128;
        Ch = cQh + co; Cl = cQl + co;
        strideN = QL;
    } else {
        Bh = WtH + O_KRP; Bl = WtL + O_KRP;
        Cf = KRp + (size_t)bm * 128;
        strideN = 128;
    }
    gemm_core(Ah, Al, Bh, Bl, DM, Cf, Ch, Cl, strideN);
}

__global__ __launch_bounds__(256) void kvproj_kernel(
    const __half* __restrict__ cKVh, const __half* __restrict__ cKVl,
    const __half* __restrict__ WtH, const __half* __restrict__ WtL,
    __half* __restrict__ Kch, __half* __restrict__ Kcl, float* __restrict__ Vf)
{
    const int bx = blockIdx.x, bm = blockIdx.y * 128;
    const __half* Ah = cKVh + (size_t)bm * KVL;
    const __half* Al = cKVl + (size_t)bm * KVL;
    if (bx < 16) {
        size_t bo = O_UK + (size_t)(bx * 128) * KVL;
        size_t co = (size_t)bm * HHD + bx * 128;
        gemm_core(Ah, Al, WtH + bo, WtL + bo, KVL,
                  nullptr, Kch + co, Kcl + co, HHD);
    } else {
        size_t bo = O_UV + (size_t)((bx - 16) * 128) * KVL;
        size_t co = (size_t)bm * HHD + (bx - 16) * 128;
        gemm_core(Ah, Al, WtH + bo, WtL + bo, KVL,
                  Vf + co, nullptr, nullptr, HHD);
    }
}

__global__ __launch_bounds__(256) void qproj_kernel(
    const __half* __restrict__ cQh, const __half* __restrict__ cQl,
    const __half* __restrict__ WtH, const __half* __restrict__ WtL,
    __half* __restrict__ Qch, __half* __restrict__ Qcl, float* __restrict__ Qrf)
{
    const int bx = blockIdx.x, bm = blockIdx.y * 128;
    const __half* Ah = cQh + (size_t)bm * QL;
    const __half* Al = cQl + (size_t)bm * QL;
    if (bx < 16) {
        size_t bo = O_UQ + (size_t)(bx * 128) * QL;
        size_t co = (size_t)bm * HHD + bx * 128;
        gemm_core(Ah, Al, WtH + bo, WtL + bo, QL,
                  nullptr, Qch + co, Qcl + co, HHD);
    } else {
        size_t bo = O_QR + (size_t)((bx - 16) * 128) * QL;
        size_t co = (size_t)bm * HRr + (bx - 16) * 128;
        gemm_core(Ah, Al, WtH + bo, WtL + bo, QL,
                  Qrf + co, nullptr, nullptr, HRr);
    }
}

__global__ __launch_bounds__(256) void wo_kernel(
    const __half* __restrict__ AOh, const __half* __restrict__ AOl,
    const __half* __restrict__ WtH, const __half* __restrict__ WtL,
    float* __restrict__ y)
{
    const int bx = blockIdx.x, bm = blockIdx.y * 128;
    size_t bo = O_O + (size_t)(bx * 128) * HHD;
    gemm_core(AOh + (size_t)bm * HHD, AOl + (size_t)bm * HHD,
              WtH + bo, WtL + bo, HHD,
              y + (size_t)bm * DM + bx * 128, nullptr, nullptr, DM);
}

// ---------------- fused flash attention ----------------
// grid (16 qt desc, 32 bh), 256 threads. Q persistent (6 tiles, fp16 h/l),
// per kt: QK^T (fp16x3) -> TMEM S; LDTM S; online softmax in registers
// (cross-half reduce via smem); P (fp16 hi only) -> smem; PV -> TMEM O;
// LDTM O -> register accumulator with alpha rescale.
__global__ __launch_bounds__(256) void flash_kernel(
    const __half* __restrict__ Qch, const __half* __restrict__ Qcl,
    const __half* __restrict__ Qrh, const __half* __restrict__ Qrl,
    const __half* __restrict__ Kch, const __half* __restrict__ Kcl,
    const __half* __restrict__ Krh, const __half* __restrict__ Krl,
    const __half* __restrict__ Vth, const __half* __restrict__ Vtl,
    __half* __restrict__ AOh, __half* __restrict__ AOl)
{
    const int qt = 15 - blockIdx.x, bh = blockIdx.y;
    const int tid = threadIdx.x;
    const int b = bh >> 4, h = bh & 15;
    const float scale = 0.07216878364870323f;   // 1/sqrt(192)
#if HAS_TCGEN05
    constexpr int T_BYTES = 16384;
    extern __shared__ char smem[];
    MmaCtx cx = mma_begin(smem, 256);
    const uint32_t qbase  = cx.tiles;                   // 6 tiles (96 KB)
    const uint32_t pbase  = qbase + 6 * T_BYTES;        // 2 tiles (32 KB)
    const uint32_t redmax = pbase + 2 * T_BYTES;        // 1 KB
    const uint32_t redsum = redmax + 1024;              // 1 KB
    const uint32_t bufb   = redsum + 1024;              // 2 x 32 KB (aligned)
    const uint32_t idesc = (1u << 4) | (16u << 17) | (8u << 24);
    const uint32_t tmemS = cx.tmem, tmemO = cx.tmem + 128;
    const size_t qrow0 = (size_t)(b * Tt + qt * 128);

    // load Q (6 tiles): c0 hi/lo, c1 hi/lo, rope hi/lo
    {
        const __half* qsrc[6] = {
            Qch + qrow0 * HHD + h * HD,       Qcl + qrow0 * HHD + h * HD,
            Qch + qrow0 * HHD + h * HD + 64,  Qcl + qrow0 * HHD + h * HD + 64,
            Qrh + qrow0 * HRr + h * Rr,       Qrl + qrow0 * HRr + h * Rr };
        const int qstr[6] = {HHD, HHD, HHD, HHD, HRr, HRr};
        #pragma unroll
        for (int i = 0; i < 24; i++) {
            int u = i * 256 + tid;
            int t = u >> 10, ul = u & 1023;
            int row = ul >> 3, seg = ul & 7;
            uint4 v = *reinterpret_cast<const uint4*>(
                qsrc[t] + (size_t)row * qstr[t] + seg * 8);
            uint32_t bo = row * 128 + seg * 16;
            sts128(qbase + t * T_BYTES + (bo ^ ((bo >> 3) & 0x70)),
                   v.x, v.y, v.z, v.w);
        }
    }

    const int w = tid >> 5, l2 = tid & 31, sub = w & 3, halfi = w >> 2;
    const int rowl = sub * 32 + l2;
    const int qglob = qt * 128 + rowl;
    float oacc[64];
    #pragma unroll
    for (int j = 0; j < 64; j++) oacc[j] = 0.f;
    float mrow = -INFINITY, lrow = 0.f;
    int u0 = 0, u1 = 0;

    for (int kt = 0; kt <= qt; kt++) {
        const size_t krow0 = (size_t)(b * Tt + kt * 128);
        // ---- QK^T: 3 chunks of K=64 into TMEM S
        for (int c = 0; c < 3; c++) {
            const int bid = c & 1;
            int cnt = bid ? u1 : u0;
            if (cnt > 0) MBAR_WAIT(cx.mb + 8 * bid, (cnt - 1) & 1);
            const uint32_t st = bufb + bid * 2 * T_BYTES;
            const __half* kh = (c < 2) ? Kch + krow0 * HHD + h * HD + c * 64
                                       : Krh + krow0 * Rr;
            const __half* kl = (c < 2) ? Kcl + krow0 * HHD + h * HD + c * 64
                                       : Krl + krow0 * Rr;
            const int str = (c < 2) ? HHD : Rr;
            #pragma unroll
            for (int i = 0; i < 8; i++) {
                int u = i * 256 + tid;
                int t = u >> 10, ul = u & 1023;
                int row = ul >> 3, seg = ul & 7;
                const __half* src = t ? kl : kh;
                uint4 v = *reinterpret_cast<const uint4*>(
                    src + (size_t)row * str + seg * 8);
                uint32_t bo = row * 128 + seg * 16;
                sts128(st + t * T_BYTES + (bo ^ ((bo >> 3) & 0x70)),
                       v.x, v.y, v.z, v.w);
            }
            FENCE_ASYNC();
            __syncthreads();
            mma_chunk(tmemS, cx.mb + 8 * bid,
                      mk_desc(qbase + (2 * c) * T_BYTES),
                      mk_desc(qbase + (2 * c + 1) * T_BYTES),
                      mk_desc(st), mk_desc(st + T_BYTES), idesc, c == 0);
            if (bid) u1++; else u0++;
        }
        MBAR_WAIT(cx.mb + 0, (u0 - 1) & 1);   // last QK chunk (c=2) on buf0
        T5_FENCE_AFTER();

        // ---- LDTM S, online softmax (this warp owns cols halfi*64..+64)
        uint32_t sr[32];
        float sv[64];
        LDTM_X32(sr, tmemS + halfi * 64);
        T5_WAIT_LD();
        #pragma unroll
        for (int j = 0; j < 32; j++) sv[j] = __uint_as_float(sr[j]) * scale;
        LDTM_X32(sr, tmemS + halfi * 64 + 32);
        T5_WAIT_LD();
        #pragma unroll
        for (int j = 0; j < 32; j++) sv[32 + j] = __uint_as_float(sr[j]) * scale;
        T5_FENCE_BEFORE();
        if (kt == qt) {
            int cbase = kt * 128 + halfi * 64;
            #pragma unroll
            for (int j = 0; j < 64; j++)
                if (cbase + j > qglob) sv[j] = -INFINITY;
        }
        float pmax = -INFINITY;
        #pragma unroll
        for (int j = 0; j < 64; j++) pmax = fmaxf(pmax, sv[j]);
        asm volatile("st.shared.f32 [%0], %1;"
                     :: "r"(redmax + (halfi * 128 + rowl) * 4), "f"(pmax) : "memory");
        __syncthreads();
        float omax;
        asm volatile("ld.shared.f32 %0, [%1];"
                     : "=f"(omax) : "r"(redmax + ((1 - halfi) * 128 + rowl) * 4));
        float mnew = fmaxf(mrow, fmaxf(pmax, omax));
        float alpha = __expf(mrow - mnew);
        mrow = mnew;
        float psum = 0.f;
        uint32_t pw[32];
        #pragma unroll
        for (int j = 0; j < 32; j++) {
            float p0 = __expf(sv[2 * j] - mnew);
            float p1 = __expf(sv[2 * j + 1] - mnew);
            psum += p0 + p1;
            pw[j] = ((uint32_t)__half_as_ushort(__float2half_rn(p1)) << 16)
                  | __half_as_ushort(__float2half_rn(p0));
        }
        #pragma unroll
        for (int sgm = 0; sgm < 8; sgm++) {
            uint32_t bo = rowl * 128 + sgm * 16;
            sts128(pbase + halfi * T_BYTES + (bo ^ ((bo >> 3) & 0x70)),
                   pw[sgm * 4], pw[sgm * 4 + 1], pw[sgm * 4 + 2], pw[sgm * 4 + 3]);
        }
        asm volatile("st.shared.f32 [%0], %1;"
                     :: "r"(redsum + (halfi * 128 + rowl) * 4), "f"(psum) : "memory");
        FENCE_ASYNC();
        __syncthreads();
        float osum;
        asm volatile("ld.shared.f32 %0, [%1];"
                     : "=f"(osum) : "r"(redsum + ((1 - halfi) * 128 + rowl) * 4));
        lrow = lrow * alpha + psum + osum;

        // ---- PV: 2 chunks of K=64, P(hi) x (Vh + Vl) into TMEM O
        for (int c = 0; c < 2; c++) {
            const int bid = c;
            int cnt = bid ? u1 : u0;
            if (cnt > 0) MBAR_WAIT(cx.mb + 8 * bid, (cnt - 1) & 1);
            const uint32_t st = bufb + bid * 2 * T_BYTES;
            const __half* vh = Vth + (size_t)bh * HD * Tt + kt * 128 + c * 64;
            const __half* vl = Vtl + (size_t)bh * HD * Tt + kt * 128 + c * 64;
            #pragma unroll
            for (int i = 0; i < 8; i++) {
                int u = i * 256 + tid;
                int t = u >> 10, ul = u & 1023;
                int row = ul >> 3, seg = ul & 7;
                const __half* src = t ? vl : vh;
                uint4 v = *reinterpret_cast<const uint4*>(
                    src + (size_t)row * Tt + seg * 8);
                uint32_t bo = row * 128 + seg * 16;
                sts128(st + t * T_BYTES + (bo ^ ((bo >> 3) & 0x70)),
                       v.x, v.y, v.z, v.w);
            }
            FENCE_ASYNC();
            __syncthreads();
            if (tid < 32 && elect1()) {
                uint64_t pd = mk_desc(pbase + c * T_BYTES);
                uint64_t vhd = mk_desc(st), vld = mk_desc(st + T_BYTES);
                #pragma unroll
                for (int q = 0; q < 4; q++)
                    mma_f16(tmemO, pd + 2 * q, vhd + 2 * q, idesc,
                            (c == 0 && q == 0) ? 0u : 1u);
                #pragma unroll
                for (int q = 0; q < 4; q++)
                    mma_f16(tmemO, pd + 2 * q, vld + 2 * q, idesc, 1u);
                T5_COMMIT(cx.mb + 8 * bid);
            }
            if (bid) u1++; else u0++;
        }
        MBAR_WAIT(cx.mb + 8, (u1 - 1) & 1);   // last PV chunk on buf1
        T5_FENCE_AFTER();
        LDTM_X32(sr, tmemO + halfi * 64);
        T5_WAIT_LD();
        #pragma unroll
        for (int j = 0; j < 32; j++)
            oacc[j] = oacc[j] * alpha + __uint_as_float(sr[j]);
        LDTM_X32(sr, tmemO + halfi * 64 + 32);
        T5_WAIT_LD();
        #pragma unroll
        for (int j = 0; j < 32; j++)
            oacc[32 + j] = oacc[32 + j] * alpha + __uint_as_float(sr[j]);
        T5_FENCE_BEFORE();
        __syncthreads();
    }

    // epilogue: normalize and split to AO hi/lo
    const float invl = 1.0f / lrow;
    const size_t off = (size_t)(b * Tt + qt * 128 + rowl) * HHD + h * HD + halfi * 64;
    #pragma unroll
    for (int j = 0; j < 64; j += 8) {
        uint4 hv, lv;
        split_pair(oacc[j+0] * invl, oacc[j+1] * invl, hv.x, lv.x);
        split_pair(oacc[j+2] * invl, oacc[j+3] * invl, hv.y, lv.y);
        split_pair(oacc[j+4] * invl, oacc[j+5] * invl, hv.z, lv.z);
        split_pair(oacc[j+6] * invl, oacc[j+7] * invl, hv.w, lv.w);
        *reinterpret_cast<uint4*>(&AOh[off + j]) = hv;
        *reinterpret_cast<uint4*>(&AOl[off + j]) = lv;
    }
    __syncthreads();
    if (tid < 32) T5_DEALLOC(cx.tmem, 256);
#else
    // naive fallback (compile-only on plain targets)
    for (int e = tid; e < 128 * 128; e += 256) {
        int r = e >> 7, d = e & 127;
        int qg = qt * 128 + r;
        size_t qoC = (size_t)(b * Tt + qg) * HHD + h * HD;
        size_t qoR = (size_t)(b * Tt + qg) * HRr + h * Rr;
        float m = -1e30f;
        for (int k = 0; k <= qg; k++) {
            size_t koC = (size_t)(b * Tt + k) * HHD + h * HD;
            size_t koR = (size_t)(b * Tt + k) * Rr;
            float s = 0.f;
            for (int dd = 0; dd < HD; dd++)
                s += (__half2float(Qch[qoC+dd]) + __half2float(Qcl[qoC+dd]))
                   * (__half2float(Kch[koC+dd]) + __half2float(Kcl[koC+dd]));
            for (int dd = 0; dd < Rr; dd++)
                s += (__half2float(Qrh[qoR+dd]) + __half2float(Qrl[qoR+dd]))
                   * (__half2float(Krh[koR+dd]) + __half2float(Krl[koR+dd]));
            s *= scale;
            if (s > m) m = s;
        }
        float l = 0.f, o = 0.f;
        for (int k = 0; k <= qg; k++) {
            size_t koC = (size_t)(b * Tt + k) * HHD + h * HD;
            size_t koR = (size_t)(b * Tt + k) * Rr;
            float s = 0.f;
            for (int dd = 0; dd < HD; dd++)
                s += (__half2float(Qch[qoC+dd]) + __half2float(Qcl[qoC+dd]))
                   * (__half2float(Kch[koC+dd]) + __half2float(Kcl[koC+dd]));
            for (int dd = 0; dd < Rr; dd++)
                s += (__half2float(Qrh[qoR+dd]) + __half2float(Qrl[qoR+dd]))
                   * (__half2float(Krh[koR+dd]) + __half2float(Krl[koR+dd]));
            float p = expf(s * scale - m);
            l += p;
            o += p * (__half2float(Vth[((size_t)bh*HD + d)*Tt + k])
                    + __half2float(Vtl[((size_t)bh*HD + d)*Tt + k]));
        }
        o /= l;
        size_t off = (size_t)(b * Tt + qg) * HHD + h * HD + d;
        __half hh = __float2half_rn(o);
        AOh[off] = hh;
        AOl[off] = __float2half_rn(o - __half2float(hh));
    }
#endif
}

// ---------------- launch ----------------
#define MMA_SMEM 200704
#define FLASH_SMEM 202752

extern "C" void kernel_launch(void* const* d_in, const int* in_sizes, int n_in,
                              void* d_out, int out_size)
{
    const float* x     = (const float*)d_in[0];
    const float* freqs = (const float*)d_in[1];
    const float* W_DKV = (const float*)d_in[2];
    const float* W_UK  = (const float*)d_in[3];
    const float* W_UV  = (const float*)d_in[4];
    const float* W_KR  = (const float*)d_in[5];
    const float* W_DQ  = (const float*)d_in[6];
    const float* W_UQ  = (const float*)d_in[7];
    const float* W_QR  = (const float*)d_in[8];
    const float* W_O   = (const float*)d_in[9];

    float* y   = (float*)d_out;
    float* cKV = y   + (size_t)Bb * Tt * DM;
    float* KRo = cKV + (size_t)Bb * Tt * KVL;

    float *pV, *pQr, *pKRp;
    __half *pxH, *pxL, *pWtH, *pWtL, *pcKVh, *pcKVl, *pcQh, *pcQl;
    __half *pQch, *pQcl, *pQrh, *pQrl, *pKch, *pKcl, *pKrh, *pKrl;
    __half *pVth, *pVtl, *pAOh, *pAOl;
    cudaGetSymbolAddress((void**)&pV,   g_V);
    cudaGetSymbolAddress((void**)&pQr,  g_Qr);
    cudaGetSymbolAddress((void**)&pKRp, g_KRp);
    cudaGetSymbolAddress((void**)&pxH,  g_xH);
    cudaGetSymbolAddress((void**)&pxL,  g_xL);
    cudaGetSymbolAddress((void**)&pWtH, g_WtH);
    cudaGetSymbolAddress((void**)&pWtL, g_WtL);
    cudaGetSymbolAddress((void**)&pcKVh, g_cKVh);
    cudaGetSymbolAddress((void**)&pcKVl, g_cKVl);
    cudaGetSymbolAddress((void**)&pcQh, g_cQh);
    cudaGetSymbolAddress((void**)&pcQl, g_cQl);
    cudaGetSymbolAddress((void**)&pQch, g_Qch);
    cudaGetSymbolAddress((void**)&pQcl, g_Qcl);
    cudaGetSymbolAddress((void**)&pQrh, g_Qrh);
    cudaGetSymbolAddress((void**)&pQrl, g_Qrl);
    cudaGetSymbolAddress((void**)&pKch, g_Kch);
    cudaGetSymbolAddress((void**)&pKcl, g_Kcl);
    cudaGetSymbolAddress((void**)&pKrh, g_Krh);
    cudaGetSymbolAddress((void**)&pKrl, g_Krl);
    cudaGetSymbolAddress((void**)&pVth, g_Vth);
    cudaGetSymbolAddress((void**)&pVtl, g_Vtl);
    cudaGetSymbolAddress((void**)&pAOh, g_AOh);
    cudaGetSymbolAddress((void**)&pAOl, g_AOl);

    cudaFuncSetAttribute(xproj_kernel,  cudaFuncAttributeMaxDynamicSharedMemorySize, MMA_SMEM);
    cudaFuncSetAttribute(kvproj_kernel, cudaFuncAttributeMaxDynamicSharedMemorySize, MMA_SMEM);
    cudaFuncSetAttribute(qproj_kernel,  cudaFuncAttributeMaxDynamicSharedMemorySize, MMA_SMEM);
    cudaFuncSetAttribute(wo_kernel,     cudaFuncAttributeMaxDynamicSharedMemorySize, MMA_SMEM);
    cudaFuncSetAttribute(flash_kernel,  cudaFuncAttributeMaxDynamicSharedMemorySize, FLASH_SMEM);

    // #1: split x
    split_x_kernel<<<(MROWS * DM / 4) / 256, 256>>>(x, pxH, pxL);

    // #2: all weight transposes
    TSJobs jobs;
    int tiles = 0;
    auto addjob = [&](int i, const float* W, size_t off, int K, int N) {
        jobs.a[i] = {W, pWtH + off, pWtL + off, K, N, tiles};
        tiles += (K / 32) * (N / 32);
    };
    addjob(0, W_DKV, O_DKV, DM, KVL);
    addjob(1, W_UK,  O_UK,  KVL, HHD);
    addjob(2, W_UV,  O_UV,  KVL, HHD);
    addjob(3, W_DQ,  O_DQ,  DM, QL);
    addjob(4, W_UQ,  O_UQ,  QL, HHD);
    addjob(5, W_QR,  O_QR,  QL, HRr);
    addjob(6, W_O,   O_O,   HHD, DM);
    addjob(7, W_KR,  O_KRP, DM, Rr);
    tsplit_all_kernel<<<tiles, 256>>>(jobs);

    // #3: xproj (cKV | cQ | KR)
    xproj_kernel<<<dim3(13, MROWS/128), 256, MMA_SMEM>>>(
        pxH, pxL, pWtH, pWtL, cKV, pcKVh, pcKVl, pcQh, pcQl, pKRp);
    // #4: rope K
    rope_k_kernel<<<(MROWS * (Rr/2) + 255) / 256, 256>>>(pKRp, freqs, KRo, pKrh, pKrl);
    // #5: kvproj (UK | UV)
    kvproj_kernel<<<dim3(32, MROWS/128), 256, MMA_SMEM>>>(
        pcKVh, pcKVl, pWtH, pWtL, pKch, pKcl, pV);
    // #6: qproj (UQ | QR)  -- ncu -s 5 profiles this launch
    qproj_kernel<<<dim3(24, MROWS/128), 256, MMA_SMEM>>>(
        pcQh, pcQl, pWtH, pWtL, pQch, pQcl, pQr);
    // #7: rope Q
    rope_q_kernel<<<(MROWS * Hh * (Rr/2) + 255) / 256, 256>>>(pQr, freqs, pQrh, pQrl);
    // #8: V transpose + split
    transpose_v_kernel<<<dim3(Tt/32, HD/32, BH), 256>>>(pV, pVth, pVtl);
    // #9: fused flash attention
    flash_kernel<<<dim3(16, BH), 256, FLASH_SMEM>>>(
        pQch, pQcl, pQrh, pQrl, pKch, pKcl, pKrh, pKrl, pVth, pVtl, pAOh, pAOl);
    // #10: y = AO @ W_O
    wo_kernel<<<dim3(16, MROWS/128), 256, MMA_SMEM>>>(pAOh, pAOl, pWtH, pWtL, y);
}

// round 9
// speedup vs baseline: 3.0196x; 1.1037x over previous
#include <cuda_runtime.h>
#include <cuda_fp16.h>
#include <math.h>
#include <stdint.h>

#define Bb 2
#define Tt 2048
#define DM 2048
#define Hh 16
#define HD 128
#define KVL 512
#define QL 1024
#define Rr 64
#define MROWS (Bb*Tt)
#define BH (Bb*Hh)
#define HHD (Hh*HD)
#define HRr (Hh*Rr)

#if defined(__CUDA_ARCH_FEAT_SM103_ALL) || defined(__CUDA_ARCH_FEAT_SM100_ALL)
#define HAS_TCGEN05 1
#else
#define HAS_TCGEN05 0
#endif

// ---------------- scratch ----------------
__device__ __half g_xH[MROWS * DM],  g_xL[MROWS * DM];
__device__ __half g_cKVh[MROWS * KVL], g_cKVl[MROWS * KVL];
__device__ __half g_cQh[MROWS * QL],   g_cQl[MROWS * QL];
__device__ __half g_Qch[MROWS * HHD],  g_Qcl[MROWS * HHD];
__device__ __half g_Qrh[MROWS * HRr],  g_Qrl[MROWS * HRr];
__device__ __half g_Kch[MROWS * HHD],  g_Kcl[MROWS * HHD];
__device__ __half g_Krh[MROWS * Rr],   g_Krl[MROWS * Rr];
__device__ __half g_Vth[BH * HD * Tt], g_Vtl[BH * HD * Tt];
__device__ __half g_AOh[MROWS * HHD],  g_AOl[MROWS * HHD];
#define O_DKV 0
#define O_UK  (O_DKV + 512*2048)
#define O_UV  (O_UK  + 2048*512)
#define O_DQ  (O_UV  + 2048*512)
#define O_UQ  (O_DQ  + 1024*2048)
#define O_QR  (O_UQ  + 2048*1024)
#define O_O   (O_QR  + 2048*1024)
#define O_KRP (O_O   + 2048*2048)
#define WT_TOTAL (O_KRP + 128*2048)
__device__ __half g_WtH[WT_TOTAL], g_WtL[WT_TOTAL];   // zero-init: KRP pad rows stay 0

// ---------------- helpers ----------------
__device__ __forceinline__ uint32_t smem_u32(const void* p) {
    uint32_t a;
    asm("{ .reg .u64 t; cvta.to.shared.u64 t, %1; cvt.u32.u64 %0, t; }"
        : "=r"(a) : "l"(p));
    return a;
}
__device__ __forceinline__ void split_pair(float a, float b,
                                           uint32_t& hi, uint32_t& lo) {
    __half ha = __float2half_rn(a), hb = __float2half_rn(b);
    hi = ((uint32_t)__half_as_ushort(hb) << 16) | __half_as_ushort(ha);
    lo = ((uint32_t)__half_as_ushort(__float2half_rn(b - __half2float(hb))) << 16)
       | __half_as_ushort(__float2half_rn(a - __half2float(ha)));
}

#if HAS_TCGEN05
__device__ __forceinline__ bool elect1() {
    uint32_t r;
    asm volatile("{\n\t.reg .pred p;\n\telect.sync _|p, 0xFFFFFFFF;\n\t"
                 "selp.b32 %0,1,0,p;\n\t}" : "=r"(r));
    return r != 0;
}
#define MBAR_INIT(a, c) \
    asm volatile("mbarrier.init.shared.b64 [%0], %1;" :: "r"(a), "r"(c) : "memory")
#define MBAR_WAIT(a, ph) do { \
    uint32_t _m = (a), _p = (uint32_t)(ph), _d; \
    asm volatile("{\n\t.reg .pred p;\n\t" \
        "mbarrier.try_wait.parity.acquire.cta.shared::cta.b64 p, [%1], %2;\n\t" \
        "selp.b32 %0,1,0,p;\n\t}" : "=r"(_d) : "r"(_m), "r"(_p) : "memory"); \
    while (!_d) { \
        asm volatile("{\n\t.reg .pred p;\n\t" \
            "mbarrier.try_wait.parity.acquire.cta.shared::cta.b64 p, [%1], %2, 0x989680;\n\t" \
            "selp.b32 %0,1,0,p;\n\t}" : "=r"(_d) : "r"(_m), "r"(_p) : "memory"); \
    } } while (0)
#define T5_COMMIT(a) \
    asm volatile("tcgen05.commit.cta_group::1.mbarrier::arrive::one.shared::cluster.b64 [%0];" \
                 :: "r"(a) : "memory")
#define T5_ALLOC(a, n) \
    asm volatile("tcgen05.alloc.cta_group::1.sync.aligned.shared::cta.b32 [%0], %1;" \
                 :: "r"(a), "r"(n) : "memory")
#define T5_DEALLOC(t, n) \
    asm volatile("tcgen05.dealloc.cta_group::1.sync.aligned.b32 %0, %1;" :: "r"(t), "r"(n))
#define T5_RELINQ() \
    asm volatile("tcgen05.relinquish_alloc_permit.cta_group::1.sync.aligned;")
#define T5_WAIT_LD()   asm volatile("tcgen05.wait::ld.sync.aligned;" ::: "memory")
#define T5_FENCE_AFTER() asm volatile("tcgen05.fence::after_thread_sync;" ::: "memory")
#define T5_FENCE_BEFORE() asm volatile("tcgen05.fence::before_thread_sync;" ::: "memory")
#define FENCE_ASYNC()  asm volatile("fence.proxy.async.shared::cta;" ::: "memory")

#define LDTM_X32(r, addr) \
    asm volatile("tcgen05.ld.sync.aligned.32x32b.x32.b32 " \
        "{%0, %1, %2, %3, %4, %5, %6, %7, %8, %9, %10, %11, %12, %13, %14, %15, " \
        "%16, %17, %18, %19, %20, %21, %22, %23, %24, %25, %26, %27, %28, %29, %30, %31}, [%32];" \
        : "=r"((r)[0]),  "=r"((r)[1]),  "=r"((r)[2]),  "=r"((r)[3]), \
          "=r"((r)[4]),  "=r"((r)[5]),  "=r"((r)[6]),  "=r"((r)[7]), \
          "=r"((r)[8]),  "=r"((r)[9]),  "=r"((r)[10]), "=r"((r)[11]), \
          "=r"((r)[12]), "=r"((r)[13]), "=r"((r)[14]), "=r"((r)[15]), \
          "=r"((r)[16]), "=r"((r)[17]), "=r"((r)[18]), "=r"((r)[19]), \
          "=r"((r)[20]), "=r"((r)[21]), "=r"((r)[22]), "=r"((r)[23]), \
          "=r"((r)[24]), "=r"((r)[25]), "=r"((r)[26]), "=r"((r)[27]), \
          "=r"((r)[28]), "=r"((r)[29]), "=r"((r)[30]), "=r"((r)[31]) \
        : "r"(addr))

__device__ __forceinline__ void mma_f16(uint32_t d, uint64_t ad, uint64_t bd,
                                        uint32_t idesc, uint32_t en) {
    asm volatile("{\n\t.reg .pred p;\n\tsetp.ne.u32 p, %4, 0;\n\t"
        "tcgen05.mma.cta_group::1.kind::f16 [%0], %1, %2, %3, p;\n\t}"
        :: "r"(d), "l"(ad), "l"(bd), "r"(idesc), "r"(en) : "memory");
}
__device__ __forceinline__ uint64_t mk_desc(uint32_t addr) {
    return ((uint64_t)2 << 61) | ((uint64_t)1 << 46) | ((uint64_t)64 << 32)
         | ((uint64_t)1 << 16) | ((addr >> 4) & 0x3FFF);
}
__device__ __forceinline__ void sts128(uint32_t addr, uint32_t a, uint32_t b,
                                       uint32_t c, uint32_t d) {
    asm volatile("st.shared.v4.b32 [%0], {%1,%2,%3,%4};"
                 :: "r"(addr), "r"(a), "r"(b), "r"(c), "r"(d) : "memory");
}
struct MmaCtx { uint32_t mb, mb_done, tmem, tiles; };
__device__ __forceinline__ MmaCtx mma_begin(char* smem, int ncols) {
    MmaCtx cx;
    uint32_t sbase = smem_u32(smem);
    cx.mb = sbase;
    cx.mb_done = sbase + 24;
    cx.tiles = (sbase + 64 + 1023) & ~1023u;
    if (threadIdx.x == 0) {
        MBAR_INIT(cx.mb + 0, 1);
        MBAR_INIT(cx.mb + 8, 1);
        MBAR_INIT(cx.mb + 16, 1);
        MBAR_INIT(cx.mb_done, 1);
    }
    if (threadIdx.x < 32) { T5_ALLOC(sbase + 32, ncols); T5_RELINQ(); }
    __syncthreads();
    asm volatile("ld.shared.b32 %0, [%1];" : "=r"(cx.tmem) : "r"(sbase + 32));
    return cx;
}
// 12 MMAs (hh, hl, lh) for one K=64 chunk
__device__ __forceinline__ void mma_chunk(uint32_t tmem, uint32_t mbar,
                                          uint64_t ah, uint64_t al,
                                          uint64_t bh, uint64_t bl,
                                          uint32_t idesc, bool first) {
    if (threadIdx.x < 32 && elect1()) {
        #pragma unroll
        for (int q = 0; q < 4; q++)
            mma_f16(tmem, ah + 2*q, bh + 2*q, idesc, (first && q == 0) ? 0u : 1u);
        #pragma unroll
        for (int q = 0; q < 4; q++)
            mma_f16(tmem, ah + 2*q, bl + 2*q, idesc, 1u);
        #pragma unroll
        for (int q = 0; q < 4; q++)
            mma_f16(tmem, al + 2*q, bh + 2*q, idesc, 1u);
        T5_COMMIT(mbar);
    }
}

// ---------------- GEMM mainloop: 128x128 tile, accumulate in TMEM ---------
// LDGs issued before the stage-reuse wait (latency overlap).
__device__ __forceinline__ MmaCtx gemm_main(
    const __half* Ah, const __half* Al,
    const __half* Bh, const __half* Bl, int K)
{
    constexpr int T_BYTES = 128 * 128;
    constexpr int STAGE = 4 * T_BYTES;
    extern __shared__ char smem[];
    MmaCtx cx = mma_begin(smem, 128);
    const int tid = threadIdx.x;
    const uint32_t idesc = (1u << 4) | (16u << 17) | (8u << 24);
    const int nc = K >> 6;
    const __half* psrc[4] = {Ah, Al, Bh, Bl};
    for (int c = 0; c < nc; c++) {
        const int s = c - (c / 3) * 3;
        const uint32_t st = cx.tiles + s * STAGE;
        const int k0 = c * 64;
        uint4 v[16];
        uint32_t da[16];
        #pragma unroll
        for (int i = 0; i < 16; i++) {
            int u = i * 256 + tid;
            int t = u >> 10, ul = u & 1023;
            int row = ul >> 3, seg = ul & 7;
            v[i] = *reinterpret_cast<const uint4*>(psrc[t] + (size_t)row * K + k0 + seg * 8);
            uint32_t bofs = row * 128 + seg * 16;
            da[i] = st + t * T_BYTES + (bofs ^ ((bofs >> 3) & 0x70));
        }
        if (c >= 3) MBAR_WAIT(cx.mb + 8 * s, ((c / 3) - 1) & 1);
        #pragma unroll
        for (int i = 0; i < 16; i++)
            sts128(da[i], v[i].x, v[i].y, v[i].z, v[i].w);
        FENCE_ASYNC();
        __syncthreads();
        mma_chunk(cx.tmem, cx.mb + 8 * s,
                  mk_desc(st), mk_desc(st + T_BYTES),
                  mk_desc(st + 2 * T_BYTES), mk_desc(st + 3 * T_BYTES),
                  idesc, c == 0);
    }
    if (tid < 32 && elect1()) T5_COMMIT(cx.mb_done);
    MBAR_WAIT(cx.mb_done, 0);
    T5_FENCE_AFTER();
    return cx;
}
#else
// fallback accumulate helper (compile-only on plain targets)
__device__ __forceinline__ float dot_hl(
    const __half* Ah, const __half* Al,
    const __half* Bh, const __half* Bl, int K, int r, int c)
{
    float acc = 0.f;
    for (int k = 0; k < K; k++)
        acc += (__half2float(Ah[(size_t)r*K+k]) + __half2float(Al[(size_t)r*K+k]))
             * (__half2float(Bh[(size_t)c*K+k]) + __half2float(Bl[(size_t)c*K+k]));
    return acc;
}
#endif

// ---------------- producers ----------------
__global__ __launch_bounds__(256) void split_x_kernel(
    const float* __restrict__ x, __half* __restrict__ xh, __half* __restrict__ xl)
{
    size_t i = (size_t)(blockIdx.x * 256 + threadIdx.x) * 4;
    float4 v = *reinterpret_cast<const float4*>(&x[i]);
    uint32_t h0, l0, h1, l1;
    split_pair(v.x, v.y, h0, l0);
    split_pair(v.z, v.w, h1, l1);
    *reinterpret_cast<uint2*>(&xh[i]) = make_uint2(h0, h1);
    *reinterpret_cast<uint2*>(&xl[i]) = make_uint2(l0, l1);
}

struct TSJob { const float* W; __half* H; __half* L; int K; int N; int tile0; };
struct TSJobs { TSJob a[8]; };

__global__ __launch_bounds__(256) void tsplit_all_kernel(TSJobs jobs)
{
    __shared__ float t[32][33];
    int bx = blockIdx.x;
    int ji = 0;
    #pragma unroll
    for (int i = 1; i < 8; i++)
        if (bx >= jobs.a[i].tile0) ji = i;
    TSJob j = jobs.a[ji];
    int tl = bx - j.tile0;
    int ntN = j.N >> 5;
    int n0 = (tl % ntN) * 32, k0 = (tl / ntN) * 32;
    int tx = threadIdx.x & 31, ty = threadIdx.x >> 5;
    #pragma unroll
    for (int i = ty; i < 32; i += 8)
        t[i][tx] = j.W[(size_t)(k0 + i) * j.N + n0 + tx];
    __syncthreads();
    #pragma unroll
    for (int i = ty; i < 32; i += 8) {
        float v = t[tx][i];
        __half h = __float2half_rn(v);
        j.H[(size_t)(n0 + i) * j.K + k0 + tx] = h;
        j.L[(size_t)(n0 + i) * j.K + k0 + tx] = __float2half_rn(v - __half2float(h));
    }
}

// ---------------- xproj: cKV | cQ | KR(+rope) ----------------
__global__ __launch_bounds__(256) void xproj_kernel(
    const __half* __restrict__ xh, const __half* __restrict__ xl,
    const __half* __restrict__ WtH, const __half* __restrict__ WtL,
    const float* __restrict__ freqs,
    float* __restrict__ cKVf, __half* __restrict__ cKVh, __half* __restrict__ cKVl,
    __half* __restrict__ cQh, __half* __restrict__ cQl,
    float* __restrict__ KRo, __half* __restrict__ Krh, __half* __restrict__ Krl)
{
    const int bx = blockIdx.x, bm = blockIdx.y * 128;
#if HAS_TCGEN05
    const __half* Ah = xh + (size_t)bm * DM;
    const __half* Al = xl + (size_t)bm * DM;
    size_t bo = (bx < 4) ? O_DKV + (size_t)(bx * 128) * DM
              : (bx < 12) ? O_DQ + (size_t)((bx - 4) * 128) * DM
              : (size_t)O_KRP;
    MmaCtx cx = gemm_main(Ah, Al, WtH + bo, WtL + bo, DM);

    const int w = threadIdx.x >> 5, l2 = threadIdx.x & 31;
    const int sub = w & 3, halfi = w >> 2;
    const int rowl = sub * 32 + l2;
    const int m = bm + rowl;
    if (bx < 12) {
        for (int b2 = halfi * 2; b2 < halfi * 2 + 2; b2++) {
            uint32_t r[32];
            LDTM_X32(r, cx.tmem + b2 * 32);
            T5_WAIT_LD();
            if (bx < 4) {
                size_t off = (size_t)m * KVL + bx * 128 + b2 * 32;
                #pragma unroll
                for (int j = 0; j < 32; j += 4)
                    *reinterpret_cast<float4*>(&cKVf[off + j]) = make_float4(
                        __uint_as_float(r[j]), __uint_as_float(r[j+1]),
                        __uint_as_float(r[j+2]), __uint_as_float(r[j+3]));
                #pragma unroll
                for (int j = 0; j < 32; j += 8) {
                    uint4 hv, lv;
                    split_pair(__uint_as_float(r[j+0]), __uint_as_float(r[j+1]), hv.x, lv.x);
                    split_pair(__uint_as_float(r[j+2]), __uint_as_float(r[j+3]), hv.y, lv.y);
                    split_pair(__uint_as_float(r[j+4]), __uint_as_float(r[j+5]), hv.z, lv.z);
                    split_pair(__uint_as_float(r[j+6]), __uint_as_float(r[j+7]), hv.w, lv.w);
                    *reinterpret_cast<uint4*>(&cKVh[off + j]) = hv;
                    *reinterpret_cast<uint4*>(&cKVl[off + j]) = lv;
                }
            } else {
                size_t off = (size_t)m * QL + (bx - 4) * 128 + b2 * 32;
                #pragma unroll
                for (int j = 0; j < 32; j += 8) {
                    uint4 hv, lv;
                    split_pair(__uint_as_float(r[j+0]), __uint_as_float(r[j+1]), hv.x, lv.x);
                    split_pair(__uint_as_float(r[j+2]), __uint_as_float(r[j+3]), hv.y, lv.y);
                    split_pair(__uint_as_float(r[j+4]), __uint_as_float(r[j+5]), hv.z, lv.z);
                    split_pair(__uint_as_float(r[j+6]), __uint_as_float(r[j+7]), hv.w, lv.w);
                    *reinterpret_cast<uint4*>(&cQh[off + j]) = hv;
                    *reinterpret_cast<uint4*>(&cQl[off + j]) = lv;
                }
            }
        }
    } else if (halfi == 0) {
        // KR: cols 0..63 real, apply rope; cols 64..127 are pad (skipped)
        const int t = m & (Tt - 1);
        for (int b2 = 0; b2 < 2; b2++) {
            uint32_t r[32];
            LDTM_X32(r, cx.tmem + b2 * 32);
            T5_WAIT_LD();
            #pragma unroll
            for (int j = 0; j < 32; j += 2) {
                int col = b2 * 32 + j;
                float f = freqs[t * (Rr / 2) + (col >> 1)], s, c;
                sincosf(f, &s, &c);
                float x0 = __uint_as_float(r[j]), x1 = __uint_as_float(r[j + 1]);
                float y0 = x0 * c - x1 * s, y1 = x0 * s + x1 * c;
                size_t off = (size_t)m * Rr + col;
                KRo[off] = y0;
                KRo[off + 1] = y1;
                uint32_t hi, lo;
                split_pair(y0, y1, hi, lo);
                *reinterpret_cast<uint32_t*>(&Krh[off]) = hi;
                *reinterpret_cast<uint32_t*>(&Krl[off]) = lo;
            }
        }
    }
    __syncthreads();
    if (threadIdx.x < 32) T5_DEALLOC(cx.tmem, 128);
#else
    const int tid = threadIdx.x;
    for (int e = tid; e < 128 * 128; e += 256) {
        int rr = e >> 7, cc = e & 127;
        int m = bm + rr;
        if (bx < 4) {
            float acc = dot_hl(xh + (size_t)bm*DM, xl + (size_t)bm*DM,
                               g_WtH + O_DKV + (size_t)(bx*128)*DM,
                               g_WtL + O_DKV + (size_t)(bx*128)*DM, DM, rr, cc);
            size_t off = (size_t)m * KVL + bx * 128 + cc;
            cKVf[off] = acc;
            __half h = __float2half_rn(acc);
            cKVh[off] = h;
            cKVl[off] = __float2half_rn(acc - __half2float(h));
        } else if (bx < 12) {
            float acc = dot_hl(xh + (size_t)bm*DM, xl + (size_t)bm*DM,
                               g_WtH + O_DQ + (size_t)((bx-4)*128)*DM,
                               g_WtL + O_DQ + (size_t)((bx-4)*128)*DM, DM, rr, cc);
            size_t off = (size_t)m * QL + (bx - 4) * 128 + cc;
            __half h = __float2half_rn(acc);
            cQh[off] = h;
            cQl[off] = __float2half_rn(acc - __half2float(h));
        } else if (cc < Rr && (cc & 1) == 0) {
            float x0 = dot_hl(xh + (size_t)bm*DM, xl + (size_t)bm*DM,
                              g_WtH + O_KRP, g_WtL + O_KRP, DM, rr, cc);
            float x1 = dot_hl(xh + (size_t)bm*DM, xl + (size_t)bm*DM,
                              g_WtH + O_KRP, g_WtL + O_KRP, DM, rr, cc + 1);
            int t = m & (Tt - 1);
            float f = freqs[t * (Rr / 2) + (cc >> 1)], s, c;
            sincosf(f, &s, &c);
            float y0 = x0 * c - x1 * s, y1 = x0 * s + x1 * c;
            size_t off = (size_t)m * Rr + cc;
            KRo[off] = y0; KRo[off + 1] = y1;
            __half h0 = __float2half_rn(y0), h1 = __float2half_rn(y1);
            Krh[off] = h0; Krh[off + 1] = h1;
            Krl[off] = __float2half_rn(y0 - __half2float(h0));
            Krl[off + 1] = __float2half_rn(y1 - __half2float(h1));
        }
    }
#endif
}

// ---------------- kvproj: UK -> Kc pairs | UV -> Vt pairs (transposed) ----
__global__ __launch_bounds__(256) void kvproj_kernel(
    const __half* __restrict__ cKVh, const __half* __restrict__ cKVl,
    const __half* __restrict__ WtH, const __half* __restrict__ WtL,
    __half* __restrict__ Kch, __half* __restrict__ Kcl,
    __half* __restrict__ Vth, __half* __restrict__ Vtl)
{
    const int bx = blockIdx.x, bm = blockIdx.y * 128;
#if HAS_TCGEN05
    const __half* Ah = cKVh + (size_t)bm * KVL;
    const __half* Al = cKVl + (size_t)bm * KVL;
    size_t bo = (bx < 16) ? O_UK + (size_t)(bx * 128) * KVL
                          : O_UV + (size_t)((bx - 16) * 128) * KVL;
    MmaCtx cx = gemm_main(Ah, Al, WtH + bo, WtL + bo, KVL);

    const int w = threadIdx.x >> 5, l2 = threadIdx.x & 31;
    const int sub = w & 3, halfi = w >> 2;
    const int rowl = sub * 32 + l2;
    const int m = bm + rowl;
    for (int b2 = halfi * 2; b2 < halfi * 2 + 2; b2++) {
        uint32_t r[32];
        LDTM_X32(r, cx.tmem + b2 * 32);
        T5_WAIT_LD();
        if (bx < 16) {
            size_t off = (size_t)m * HHD + bx * 128 + b2 * 32;
            #pragma unroll
            for (int j = 0; j < 32; j += 8) {
                uint4 hv, lv;
                split_pair(__uint_as_float(r[j+0]), __uint_as_float(r[j+1]), hv.x, lv.x);
                split_pair(__uint_as_float(r[j+2]), __uint_as_float(r[j+3]), hv.y, lv.y);
                split_pair(__uint_as_float(r[j+4]), __uint_as_float(r[j+5]), hv.z, lv.z);
                split_pair(__uint_as_float(r[j+6]), __uint_as_float(r[j+7]), hv.w, lv.w);
                *reinterpret_cast<uint4*>(&Kch[off + j]) = hv;
                *reinterpret_cast<uint4*>(&Kcl[off + j]) = lv;
            }
        } else {
            // V: write transposed Vt[bh][d][t]
            const int bq = m >> 11, tloc = m & (Tt - 1);
            #pragma unroll
            for (int j = 0; j < 32; j++) {
                int gcol = (bx - 16) * 128 + b2 * 32 + j;
                int hh2 = gcol >> 7, d = gcol & 127;
                float v = __uint_as_float(r[j]);
                __half vh = __float2half_rn(v);
                size_t off = ((size_t)(bq * Hh + hh2) * HD + d) * Tt + tloc;
                Vth[off] = vh;
                Vtl[off] = __float2half_rn(v - __half2float(vh));
            }
        }
    }
    __syncthreads();
    if (threadIdx.x < 32) T5_DEALLOC(cx.tmem, 128);
#else
    const int tid = threadIdx.x;
    for (int e = tid; e < 128 * 128; e += 256) {
        int rr = e >> 7, cc = e & 127;
        int m = bm + rr;
        if (bx < 16) {
            float acc = dot_hl(cKVh + (size_t)bm*KVL, cKVl + (size_t)bm*KVL,
                               g_WtH + O_UK + (size_t)(bx*128)*KVL,
                               g_WtL + O_UK + (size_t)(bx*128)*KVL, KVL, rr, cc);
            size_t off = (size_t)m * HHD + bx * 128 + cc;
            __half h = __float2half_rn(acc);
            Kch[off] = h;
            Kcl[off] = __float2half_rn(acc - __half2float(h));
        } else {
            float acc = dot_hl(cKVh + (size_t)bm*KVL, cKVl + (size_t)bm*KVL,
                               g_WtH + O_UV + (size_t)((bx-16)*128)*KVL,
                               g_WtL + O_UV + (size_t)((bx-16)*128)*KVL, KVL, rr, cc);
            int gcol = (bx - 16) * 128 + cc;
            int hh2 = gcol >> 7, d = gcol & 127;
            int bq = m >> 11, tloc = m & (Tt - 1);
            size_t off = ((size_t)(bq * Hh + hh2) * HD + d) * Tt + tloc;
            __half h = __float2half_rn(acc);
            Vth[off] = h;
            Vtl[off] = __float2half_rn(acc - __half2float(h));
        }
    }
#endif
}

// ---------------- qproj: UQ -> Qc pairs | QR -> Qr (+rope) pairs ----------
__global__ __launch_bounds__(256) void qproj_kernel(
    const __half* __restrict__ cQh, const __half* __restrict__ cQl,
    const __half* __restrict__ WtH, const __half* __restrict__ WtL,
    const float* __restrict__ freqs,
    __half* __restrict__ Qch, __half* __restrict__ Qcl,
    __half* __restrict__ Qrh, __half* __restrict__ Qrl)
{
    const int bx = blockIdx.x, bm = blockIdx.y * 128;
#if HAS_TCGEN05
    const __half* Ah = cQh + (size_t)bm * QL;
    const __half* Al = cQl + (size_t)bm * QL;
    size_t bo = (bx < 16) ? O_UQ + (size_t)(bx * 128) * QL
                          : O_QR + (size_t)((bx - 16) * 128) * QL;
    MmaCtx cx = gemm_main(Ah, Al, WtH + bo, WtL + bo, QL);

    const int w = threadIdx.x >> 5, l2 = threadIdx.x & 31;
    const int sub = w & 3, halfi = w >> 2;
    const int rowl = sub * 32 + l2;
    const int m = bm + rowl;
    const int t = m & (Tt - 1);
    for (int b2 = halfi * 2; b2 < halfi * 2 + 2; b2++) {
        uint32_t r[32];
        LDTM_X32(r, cx.tmem + b2 * 32);
        T5_WAIT_LD();
        if (bx < 16) {
            size_t off = (size_t)m * HHD + bx * 128 + b2 * 32;
            #pragma unroll
            for (int j = 0; j < 32; j += 8) {
                uint4 hv, lv;
                split_pair(__uint_as_float(r[j+0]), __uint_as_float(r[j+1]), hv.x, lv.x);
                split_pair(__uint_as_float(r[j+2]), __uint_as_float(r[j+3]), hv.y, lv.y);
                split_pair(__uint_as_float(r[j+4]), __uint_as_float(r[j+5]), hv.z, lv.z);
                split_pair(__uint_as_float(r[j+6]), __uint_as_float(r[j+7]), hv.w, lv.w);
                *reinterpret_cast<uint4*>(&Qch[off + j]) = hv;
                *reinterpret_cast<uint4*>(&Qcl[off + j]) = lv;
            }
        } else {
            // rope Q in-register, pairs are adjacent columns
            #pragma unroll
            for (int j = 0; j < 32; j += 2) {
                int gcol = (bx - 16) * 128 + b2 * 32 + j;
                float f = freqs[t * (Rr / 2) + ((gcol & 63) >> 1)], s, c;
                sincosf(f, &s, &c);
                float x0 = __uint_as_float(r[j]), x1 = __uint_as_float(r[j + 1]);
                float y0 = x0 * c - x1 * s, y1 = x0 * s + x1 * c;
                uint32_t hi, lo;
                split_pair(y0, y1, hi, lo);
                size_t off = (size_t)m * HRr + gcol;
                *reinterpret_cast<uint32_t*>(&Qrh[off]) = hi;
                *reinterpret_cast<uint32_t*>(&Qrl[off]) = lo;
            }
        }
    }
    __syncthreads();
    if (threadIdx.x < 32) T5_DEALLOC(cx.tmem, 128);
#else
    const int tid = threadIdx.x;
    for (int e = tid; e < 128 * 128; e += 256) {
        int rr = e >> 7, cc = e & 127;
        int m = bm + rr;
        if (bx < 16) {
            float acc = dot_hl(cQh + (size_t)bm*QL, cQl + (size_t)bm*QL,
                               g_WtH + O_UQ + (size_t)(bx*128)*QL,
                               g_WtL + O_UQ + (size_t)(bx*128)*QL, QL, rr, cc);
            size_t off = (size_t)m * HHD + bx * 128 + cc;
            __half h = __float2half_rn(acc);
            Qch[off] = h;
            Qcl[off] = __float2half_rn(acc - __half2float(h));
        } else if ((cc & 1) == 0) {
            float x0 = dot_hl(cQh + (size_t)bm*QL, cQl + (size_t)bm*QL,
                              g_WtH + O_QR + (size_t)((bx-16)*128)*QL,
                              g_WtL + O_QR + (size_t)((bx-16)*128)*QL, QL, rr, cc);
            float x1 = dot_hl(cQh + (size_t)bm*QL, cQl + (size_t)bm*QL,
                              g_WtH + O_QR + (size_t)((bx-16)*128)*QL,
                              g_WtL + O_QR + (size_t)((bx-16)*128)*QL, QL, rr, cc + 1);
            int gcol = (bx - 16) * 128 + cc;
            int t = m & (Tt - 1);
            float f = freqs[t * (Rr / 2) + ((gcol & 63) >> 1)], s, c;
            sincosf(f, &s, &c);
            float y0 = x0 * c - x1 * s, y1 = x0 * s + x1 * c;
            size_t off = (size_t)m * HRr + gcol;
            __half h0 = __float2half_rn(y0), h1 = __float2half_rn(y1);
            Qrh[off] = h0; Qrh[off + 1] = h1;
            Qrl[off] = __float2half_rn(y0 - __half2float(h0));
            Qrl[off + 1] = __float2half_rn(y1 - __half2float(h1));
        }
    }
#endif
}

// ---------------- wo: y = AO @ W_O ----------------
__global__ __launch_bounds__(256) void wo_kernel(
    const __half* __restrict__ AOh, const __half* __restrict__ AOl,
    const __half* __restrict__ WtH, const __half* __restrict__ WtL,
    float* __restrict__ y)
{
    const int bx = blockIdx.x, bm = blockIdx.y * 128;
#if HAS_TCGEN05
    size_t bo = O_O + (size_t)(bx * 128) * HHD;
    MmaCtx cx = gemm_main(AOh + (size_t)bm * HHD, AOl + (size_t)bm * HHD,
                          WtH + bo, WtL + bo, HHD);
    const int w = threadIdx.x >> 5, l2 = threadIdx.x & 31;
    const int sub = w & 3, halfi = w >> 2;
    const int m = bm + sub * 32 + l2;
    for (int b2 = halfi * 2; b2 < halfi * 2 + 2; b2++) {
        uint32_t r[32];
        LDTM_X32(r, cx.tmem + b2 * 32);
        T5_WAIT_LD();
        size_t off = (size_t)m * DM + bx * 128 + b2 * 32;
        #pragma unroll
        for (int j = 0; j < 32; j += 4)
            *reinterpret_cast<float4*>(&y[off + j]) = make_float4(
                __uint_as_float(r[j]), __uint_as_float(r[j+1]),
                __uint_as_float(r[j+2]), __uint_as_float(r[j+3]));
    }
    __syncthreads();
    if (threadIdx.x < 32) T5_DEALLOC(cx.tmem, 128);
#else
    const int tid = threadIdx.x;
    for (int e = tid; e < 128 * 128; e += 256) {
        int rr = e >> 7, cc = e & 127;
        float acc = dot_hl(AOh + (size_t)bm*HHD, AOl + (size_t)bm*HHD,
                           g_WtH + O_O + (size_t)(bx*128)*HHD,
                           g_WtL + O_O + (size_t)(bx*128)*HHD, HHD, rr, cc);
        y[(size_t)(bm + rr) * DM + bx * 128 + cc] = acc;
    }
#endif
}

// ---------------- fused flash attention ----------------
__global__ __launch_bounds__(256) void flash_kernel(
    const __half* __restrict__ Qch, const __half* __restrict__ Qcl,
    const __half* __restrict__ Qrh, const __half* __restrict__ Qrl,
    const __half* __restrict__ Kch, const __half* __restrict__ Kcl,
    const __half* __restrict__ Krh, const __half* __restrict__ Krl,
    const __half* __restrict__ Vth, const __half* __restrict__ Vtl,
    __half* __restrict__ AOh, __half* __restrict__ AOl)
{
    const int qt = 15 - blockIdx.x, bh = blockIdx.y;
    const int tid = threadIdx.x;
    const int b = bh >> 4, h = bh & 15;
    const float scale = 0.07216878364870323f;   // 1/sqrt(192)
#if HAS_TCGEN05
    constexpr int T_BYTES = 16384;
    extern __shared__ char smem[];
    MmaCtx cx = mma_begin(smem, 256);
    const uint32_t qbase  = cx.tiles;                   // 6 tiles (96 KB)
    const uint32_t pbase  = qbase + 6 * T_BYTES;        // 2 tiles (32 KB)
    const uint32_t redmax = pbase + 2 * T_BYTES;        // 1 KB
    const uint32_t redsum = redmax + 1024;              // 1 KB
    const uint32_t bufb   = redsum + 1024;              // 2 x 32 KB
    const uint32_t idesc = (1u << 4) | (16u << 17) | (8u << 24);
    const uint32_t tmemS = cx.tmem, tmemO = cx.tmem + 128;
    const size_t qrow0 = (size_t)(b * Tt + qt * 128);

    {
        const __half* qsrc[6] = {
            Qch + qrow0 * HHD + h * HD,       Qcl + qrow0 * HHD + h * HD,
            Qch + qrow0 * HHD + h * HD + 64,  Qcl + qrow0 * HHD + h * HD + 64,
            Qrh + qrow0 * HRr + h * Rr,       Qrl + qrow0 * HRr + h * Rr };
        const int qstr[6] = {HHD, HHD, HHD, HHD, HRr, HRr};
        #pragma unroll
        for (int i = 0; i < 24; i++) {
            int u = i * 256 + tid;
            int t = u >> 10, ul = u & 1023;
            int row = ul >> 3, seg = ul & 7;
            uint4 v = *reinterpret_cast<const uint4*>(
                qsrc[t] + (size_t)row * qstr[t] + seg * 8);
            uint32_t bo = row * 128 + seg * 16;
            sts128(qbase + t * T_BYTES + (bo ^ ((bo >> 3) & 0x70)),
                   v.x, v.y, v.z, v.w);
        }
    }

    const int w = tid >> 5, l2 = tid & 31, sub = w & 3, halfi = w >> 2;
    const int rowl = sub * 32 + l2;
    const int qglob = qt * 128 + rowl;
    float oacc[64];
    #pragma unroll
    for (int j = 0; j < 64; j++) oacc[j] = 0.f;
    float mrow = -INFINITY, lrow = 0.f;
    int u0 = 0, u1 = 0;

    for (int kt = 0; kt <= qt; kt++) {
        const size_t krow0 = (size_t)(b * Tt + kt * 128);
        for (int c = 0; c < 3; c++) {
            const int bid = c & 1;
            int cnt = bid ? u1 : u0;
            const uint32_t st = bufb + bid * 2 * T_BYTES;
            const __half* kh = (c < 2) ? Kch + krow0 * HHD + h * HD + c * 64
                                       : Krh + krow0 * Rr;
            const __half* kl = (c < 2) ? Kcl + krow0 * HHD + h * HD + c * 64
                                       : Krl + krow0 * Rr;
            const int str = (c < 2) ? HHD : Rr;
            uint4 v[8];
            uint32_t da[8];
            #pragma unroll
            for (int i = 0; i < 8; i++) {
                int u = i * 256 + tid;
                int t = u >> 10, ul = u & 1023;
                int row = ul >> 3, seg = ul & 7;
                const __half* src = t ? kl : kh;
                v[i] = *reinterpret_cast<const uint4*>(
                    src + (size_t)row * str + seg * 8);
                uint32_t bo = row * 128 + seg * 16;
                da[i] = st + t * T_BYTES + (bo ^ ((bo >> 3) & 0x70));
            }
            if (cnt > 0) MBAR_WAIT(cx.mb + 8 * bid, (cnt - 1) & 1);
            #pragma unroll
            for (int i = 0; i < 8; i++)
                sts128(da[i], v[i].x, v[i].y, v[i].z, v[i].w);
            FENCE_ASYNC();
            __syncthreads();
            mma_chunk(tmemS, cx.mb + 8 * bid,
                      mk_desc(qbase + (2 * c) * T_BYTES),
                      mk_desc(qbase + (2 * c + 1) * T_BYTES),
                      mk_desc(st), mk_desc(st + T_BYTES), idesc, c == 0);
            if (bid) u1++; else u0++;
        }
        MBAR_WAIT(cx.mb + 0, (u0 - 1) & 1);
        T5_FENCE_AFTER();

        uint32_t sr[32];
        float sv[64];
        LDTM_X32(sr, tmemS + halfi * 64);
        T5_WAIT_LD();
        #pragma unroll
        for (int j = 0; j < 32; j++) sv[j] = __uint_as_float(sr[j]) * scale;
        LDTM_X32(sr, tmemS + halfi * 64 + 32);
        T5_WAIT_LD();
        #pragma unroll
        for (int j = 0; j < 32; j++) sv[32 + j] = __uint_as_float(sr[j]) * scale;
        T5_FENCE_BEFORE();
        if (kt == qt) {
            int cbase = kt * 128 + halfi * 64;
            #pragma unroll
            for (int j = 0; j < 64; j++)
                if (cbase + j > qglob) sv[j] = -INFINITY;
        }
        float pmax = -INFINITY;
        #pragma unroll
        for (int j = 0; j < 64; j++) pmax = fmaxf(pmax, sv[j]);
        asm volatile("st.shared.f32 [%0], %1;"
                     :: "r"(redmax + (halfi * 128 + rowl) * 4), "f"(pmax) : "memory");
        __syncthreads();
        float omax;
        asm volatile("ld.shared.f32 %0, [%1];"
                     : "=f"(omax) : "r"(redmax + ((1 - halfi) * 128 + rowl) * 4));
        float mnew = fmaxf(mrow, fmaxf(pmax, omax));
        float alpha = __expf(mrow - mnew);
        mrow = mnew;
        float psum = 0.f;
        uint32_t pw[32];
        #pragma unroll
        for (int j = 0; j < 32; j++) {
            float p0 = __expf(sv[2 * j] - mnew);
            float p1 = __expf(sv[2 * j + 1] - mnew);
            psum += p0 + p1;
            pw[j] = ((uint32_t)__half_as_ushort(__float2half_rn(p1)) << 16)
                  | __half_as_ushort(__float2half_rn(p0));
        }
        #pragma unroll
        for (int sgm = 0; sgm < 8; sgm++) {
            uint32_t bo = rowl * 128 + sgm * 16;
            sts128(pbase + halfi * T_BYTES + (bo ^ ((bo >> 3) & 0x70)),
                   pw[sgm * 4], pw[sgm * 4 + 1], pw[sgm * 4 + 2], pw[sgm * 4 + 3]);
        }
        asm volatile("st.shared.f32 [%0], %1;"
                     :: "r"(redsum + (halfi * 128 + rowl) * 4), "f"(psum) : "memory");
        FENCE_ASYNC();
        __syncthreads();
        float osum;
        asm volatile("ld.shared.f32 %0, [%1];"
                     : "=f"(osum) : "r"(redsum + ((1 - halfi) * 128 + rowl) * 4));
        lrow = lrow * alpha + psum + osum;

        for (int c = 0; c < 2; c++) {
            const int bid = c;
            int cnt = bid ? u1 : u0;
            const uint32_t st = bufb + bid * 2 * T_BYTES;
            const __half* vh = Vth + (size_t)bh * HD * Tt + kt * 128 + c * 64;
            const __half* vl = Vtl + (size_t)bh * HD * Tt + kt * 128 + c * 64;
            uint4 v[8];
            uint32_t da[8];
            #pragma unroll
            for (int i = 0; i < 8; i++) {
                int u = i * 256 + tid;
                int t = u >> 10, ul = u & 1023;
                int row = ul >> 3, seg = ul & 7;
                const __half* src = t ? vl : vh;
                v[i] = *reinterpret_cast<const uint4*>(
                    src + (size_t)row * Tt + seg * 8);
                uint32_t bo = row * 128 + seg * 16;
                da[i] = st + t * T_BYTES + (bo ^ ((bo >> 3) & 0x70));
            }
            if (cnt > 0) MBAR_WAIT(cx.mb + 8 * bid, (cnt - 1) & 1);
            #pragma unroll
            for (int i = 0; i < 8; i++)
                sts128(da[i], v[i].x, v[i].y, v[i].z, v[i].w);
            FENCE_ASYNC();
            __syncthreads();
            if (tid < 32 && elect1()) {
                uint64_t pd = mk_desc(pbase + c * T_BYTES);
                uint64_t vhd = mk_desc(st), vld = mk_desc(st + T_BYTES);
                #pragma unroll
                for (int q = 0; q < 4; q++)
                    mma_f16(tmemO, pd + 2 * q, vhd + 2 * q, idesc,
                            (c == 0 && q == 0) ? 0u : 1u);
                #pragma unroll
                for (int q = 0; q < 4; q++)
                    mma_f16(tmemO, pd + 2 * q, vld + 2 * q, idesc, 1u);
                T5_COMMIT(cx.mb + 8 * bid);
            }
            if (bid) u1++; else u0++;
        }
        MBAR_WAIT(cx.mb + 8, (u1 - 1) & 1);
        T5_FENCE_AFTER();
        LDTM_X32(sr, tmemO + halfi * 64);
        T5_WAIT_LD();
        #pragma unroll
        for (int j = 0; j < 32; j++)
            oacc[j] = oacc[j] * alpha + __uint_as_float(sr[j]);
        LDTM_X32(sr, tmemO + halfi * 64 + 32);
        T5_WAIT_LD();
        #pragma unroll
        for (int j = 0; j < 32; j++)
            oacc[32 + j] = oacc[32 + j] * alpha + __uint_as_float(sr[j]);
        T5_FENCE_BEFORE();
        __syncthreads();
    }

    const float invl = 1.0f / lrow;
    const size_t off = (size_t)(b * Tt + qt * 128 + rowl) * HHD + h * HD + halfi * 64;
    #pragma unroll
    for (int j = 0; j < 64; j += 8) {
        uint4 hv, lv;
        split_pair(oacc[j+0] * invl, oacc[j+1] * invl, hv.x, lv.x);
        split_pair(oacc[j+2] * invl, oacc[j+3] * invl, hv.y, lv.y);
        split_pair(oacc[j+4] * invl, oacc[j+5] * invl, hv.z, lv.z);
        split_pair(oacc[j+6] * invl, oacc[j+7] * invl, hv.w, lv.w);
        *reinterpret_cast<uint4*>(&AOh[off + j]) = hv;
        *reinterpret_cast<uint4*>(&AOl[off + j]) = lv;
    }
    __syncthreads();
    if (tid < 32) T5_DEALLOC(cx.tmem, 256);
#else
    for (int e = tid; e < 128 * 128; e += 256) {
        int r = e >> 7, d = e & 127;
        int qg = qt * 128 + r;
        size_t qoC = (size_t)(b * Tt + qg) * HHD + h * HD;
        size_t qoR = (size_t)(b * Tt + qg) * HRr + h * Rr;
        float m = -1e30f;
        for (int k = 0; k <= qg; k++) {
            size_t koC = (size_t)(b * Tt + k) * HHD + h * HD;
            size_t koR = (size_t)(b * Tt + k) * Rr;
            float s = 0.f;
            for (int dd = 0; dd < HD; dd++)
                s += (__half2float(Qch[qoC+dd]) + __half2float(Qcl[qoC+dd]))
                   * (__half2float(Kch[koC+dd]) + __half2float(Kcl[koC+dd]));
            for (int dd = 0; dd < Rr; dd++)
                s += (__half2float(Qrh[qoR+dd]) + __half2float(Qrl[qoR+dd]))
                   * (__half2float(Krh[koR+dd]) + __half2float(Krl[koR+dd]));
            s *= scale;
            if (s > m) m = s;
        }
        float l = 0.f, o = 0.f;
        for (int k = 0; k <= qg; k++) {
            size_t koC = (size_t)(b * Tt + k) * HHD + h * HD;
            size_t koR = (size_t)(b * Tt + k) * Rr;
            float s = 0.f;
            for (int dd = 0; dd < HD; dd++)
                s += (__half2float(Qch[qoC+dd]) + __half2float(Qcl[qoC+dd]))
                   * (__half2float(Kch[koC+dd]) + __half2float(Kcl[koC+dd]));
            for (int dd = 0; dd < Rr; dd++)
                s += (__half2float(Qrh[qoR+dd]) + __half2float(Qrl[qoR+dd]))
                   * (__half2float(Krh[koR+dd]) + __half2float(Krl[koR+dd]));
            float p = expf(s * scale - m);
            l += p;
            o += p * (__half2float(Vth[((size_t)bh*HD + d)*Tt + k])
                    + __half2float(Vtl[((size_t)bh*HD + d)*Tt + k]));
        }
        o /= l;
        size_t off = (size_t)(b * Tt + qg) * HHD + h * HD + d;
        __half hh = __float2half_rn(o);
        AOh[off] = hh;
        AOl[off] = __float2half_rn(o - __half2float(hh));
    }
#endif
}

// ---------------- launch ----------------
#define MMA_SMEM 200704
#define FLASH_SMEM 202752

extern "C" void kernel_launch(void* const* d_in, const int* in_sizes, int n_in,
                              void* d_out, int out_size)
{
    const float* x     = (const float*)d_in[0];
    const float* freqs = (const float*)d_in[1];
    const float* W_DKV = (const float*)d_in[2];
    const float* W_UK  = (const float*)d_in[3];
    const float* W_UV  = (const float*)d_in[4];
    const float* W_KR  = (const float*)d_in[5];
    const float* W_DQ  = (const float*)d_in[6];
    const float* W_UQ  = (const float*)d_in[7];
    const float* W_QR  = (const float*)d_in[8];
    const float* W_O   = (const float*)d_in[9];

    float* y   = (float*)d_out;
    float* cKV = y   + (size_t)Bb * Tt * DM;
    float* KRo = cKV + (size_t)Bb * Tt * KVL;

    __half *pxH, *pxL, *pWtH, *pWtL, *pcKVh, *pcKVl, *pcQh, *pcQl;
    __half *pQch, *pQcl, *pQrh, *pQrl, *pKch, *pKcl, *pKrh, *pKrl;
    __half *pVth, *pVtl, *pAOh, *pAOl;
    cudaGetSymbolAddress((void**)&pxH,  g_xH);
    cudaGetSymbolAddress((void**)&pxL,  g_xL);
    cudaGetSymbolAddress((void**)&pWtH, g_WtH);
    cudaGetSymbolAddress((void**)&pWtL, g_WtL);
    cudaGetSymbolAddress((void**)&pcKVh, g_cKVh);
    cudaGetSymbolAddress((void**)&pcKVl, g_cKVl);
    cudaGetSymbolAddress((void**)&pcQh, g_cQh);
    cudaGetSymbolAddress((void**)&pcQl, g_cQl);
    cudaGetSymbolAddress((void**)&pQch, g_Qch);
    cudaGetSymbolAddress((void**)&pQcl, g_Qcl);
    cudaGetSymbolAddress((void**)&pQrh, g_Qrh);
    cudaGetSymbolAddress((void**)&pQrl, g_Qrl);
    cudaGetSymbolAddress((void**)&pKch, g_Kch);
    cudaGetSymbolAddress((void**)&pKcl, g_Kcl);
    cudaGetSymbolAddress((void**)&pKrh, g_Krh);
    cudaGetSymbolAddress((void**)&pKrl, g_Krl);
    cudaGetSymbolAddress((void**)&pVth, g_Vth);
    cudaGetSymbolAddress((void**)&pVtl, g_Vtl);
    cudaGetSymbolAddress((void**)&pAOh, g_AOh);
    cudaGetSymbolAddress((void**)&pAOl, g_AOl);

    cudaFuncSetAttribute(xproj_kernel,  cudaFuncAttributeMaxDynamicSharedMemorySize, MMA_SMEM);
    cudaFuncSetAttribute(kvproj_kernel, cudaFuncAttributeMaxDynamicSharedMemorySize, MMA_SMEM);
    cudaFuncSetAttribute(qproj_kernel,  cudaFuncAttributeMaxDynamicSharedMemorySize, MMA_SMEM);
    cudaFuncSetAttribute(wo_kernel,     cudaFuncAttributeMaxDynamicSharedMemorySize, MMA_SMEM);
    cudaFuncSetAttribute(flash_kernel,  cudaFuncAttributeMaxDynamicSharedMemorySize, FLASH_SMEM);

    // #1: split x
    split_x_kernel<<<(MROWS * DM / 4) / 256, 256>>>(x, pxH, pxL);

    // #2: all weight transposes (KR padded; pad rows stay zero from static init)
    TSJobs jobs;
    int tiles = 0;
    auto addjob = [&](int i, const float* W, size_t off, int K, int N) {
        jobs.a[i] = {W, pWtH + off, pWtL + off, K, N, tiles};
        tiles += (K / 32) * (N / 32);
    };
    addjob(0, W_DKV, O_DKV, DM, KVL);
    addjob(1, W_UK,  O_UK,  KVL, HHD);
    addjob(2, W_UV,  O_UV,  KVL, HHD);
    addjob(3, W_DQ,  O_DQ,  DM, QL);
    addjob(4, W_UQ,  O_UQ,  QL, HHD);
    addjob(5, W_QR,  O_QR,  QL, HRr);
    addjob(6, W_O,   O_O,   HHD, DM);
    addjob(7, W_KR,  O_KRP, DM, Rr);
    tsplit_all_kernel<<<tiles, 256>>>(jobs);

    // #3: xproj (cKV | cQ | KR+rope)
    xproj_kernel<<<dim3(13, MROWS/128), 256, MMA_SMEM>>>(
        pxH, pxL, pWtH, pWtL, freqs, cKV, pcKVh, pcKVl, pcQh, pcQl,
        KRo, pKrh, pKrl);
    // #4: kvproj (UK -> Kc | UV -> Vt transposed)
    kvproj_kernel<<<dim3(32, MROWS/128), 256, MMA_SMEM>>>(
        pcKVh, pcKVl, pWtH, pWtL, pKch, pKcl, pVth, pVtl);
    // #5: qproj (UQ -> Qc | QR -> Qr roped)
    qproj_kernel<<<dim3(24, MROWS/128), 256, MMA_SMEM>>>(
        pcQh, pcQl, pWtH, pWtL, freqs, pQch, pQcl, pQrh, pQrl);
    // #6: fused flash attention
    flash_kernel<<<dim3(16, BH), 256, FLASH_SMEM>>>(
        pQch, pQcl, pQrh, pQrl, pKch, pKcl, pKrh, pKrl, pVth, pVtl, pAOh, pAOl);
    // #7: y = AO @ W_O
    wo_kernel<<<dim3(16, MROWS/128), 256, MMA_SMEM>>>(pAOh, pAOl, pWtH, pWtL, y);
}

// round 10
// speedup vs baseline: 3.8537x; 1.2762x over previous
#include <cuda_runtime.h>
#include <cuda_fp16.h>
#include <math.h>
#include <stdint.h>

#define Bb 2
#define Tt 2048
#define DM 2048
#define Hh 16
#define HD 128
#define KVL 512
#define QL 1024
#define Rr 64
#define MROWS (Bb*Tt)
#define BH (Bb*Hh)
#define HHD (Hh*HD)
#define HRr (Hh*Rr)

#if defined(__CUDA_ARCH_FEAT_SM103_ALL) || defined(__CUDA_ARCH_FEAT_SM100_ALL)
#define HAS_TCGEN05 1
#else
#define HAS_TCGEN05 0
#endif

// ---------------- scratch ----------------
__device__ __half g_xH[MROWS * DM],  g_xL[MROWS * DM];
__device__ __half g_cKVh[MROWS * KVL], g_cKVl[MROWS * KVL];
__device__ __half g_cQh[MROWS * QL],   g_cQl[MROWS * QL];
__device__ __half g_Qch[MROWS * HHD],  g_Qcl[MROWS * HHD];
__device__ __half g_Qrh[MROWS * HRr],  g_Qrl[MROWS * HRr];
__device__ __half g_Kch[MROWS * HHD],  g_Kcl[MROWS * HHD];
__device__ __half g_Krh[MROWS * Rr],   g_Krl[MROWS * Rr];
__device__ __half g_Vth[BH * HD * Tt], g_Vtl[BH * HD * Tt];
__device__ __half g_AOh[MROWS * HHD],  g_AOl[MROWS * HHD];
#define O_DKV 0
#define O_UK  (O_DKV + 512*2048)
#define O_UV  (O_UK  + 2048*512)
#define O_DQ  (O_UV  + 2048*512)
#define O_UQ  (O_DQ  + 1024*2048)
#define O_QR  (O_UQ  + 2048*1024)
#define O_O   (O_QR  + 2048*1024)
#define O_KRP (O_O   + 2048*2048)
#define WT_TOTAL (O_KRP + 128*2048)
__device__ __half g_WtH[WT_TOTAL], g_WtL[WT_TOTAL];   // zero-init: KRP pad rows stay 0

// ---------------- helpers ----------------
__device__ __forceinline__ uint32_t smem_u32(const void* p) {
    uint32_t a;
    asm("{ .reg .u64 t; cvta.to.shared.u64 t, %1; cvt.u32.u64 %0, t; }"
        : "=r"(a) : "l"(p));
    return a;
}
__device__ __forceinline__ void split_pair(float a, float b,
                                           uint32_t& hi, uint32_t& lo) {
    __half ha = __float2half_rn(a), hb = __float2half_rn(b);
    hi = ((uint32_t)__half_as_ushort(hb) << 16) | __half_as_ushort(ha);
    lo = ((uint32_t)__half_as_ushort(__float2half_rn(b - __half2float(hb))) << 16)
       | __half_as_ushort(__float2half_rn(a - __half2float(ha)));
}

#if HAS_TCGEN05
__device__ __forceinline__ bool elect1() {
    uint32_t r;
    asm volatile("{\n\t.reg .pred p;\n\telect.sync _|p, 0xFFFFFFFF;\n\t"
                 "selp.b32 %0,1,0,p;\n\t}" : "=r"(r));
    return r != 0;
}
#define MBAR_INIT(a, c) \
    asm volatile("mbarrier.init.shared.b64 [%0], %1;" :: "r"(a), "r"(c) : "memory")
#define MBAR_WAIT(a, ph) do { \
    uint32_t _m = (a), _p = (uint32_t)(ph), _d; \
    asm volatile("{\n\t.reg .pred p;\n\t" \
        "mbarrier.try_wait.parity.acquire.cta.shared::cta.b64 p, [%1], %2;\n\t" \
        "selp.b32 %0,1,0,p;\n\t}" : "=r"(_d) : "r"(_m), "r"(_p) : "memory"); \
    while (!_d) { \
        asm volatile("{\n\t.reg .pred p;\n\t" \
            "mbarrier.try_wait.parity.acquire.cta.shared::cta.b64 p, [%1], %2, 0x989680;\n\t" \
            "selp.b32 %0,1,0,p;\n\t}" : "=r"(_d) : "r"(_m), "r"(_p) : "memory"); \
    } } while (0)
#define T5_COMMIT(a) \
    asm volatile("tcgen05.commit.cta_group::1.mbarrier::arrive::one.shared::cluster.b64 [%0];" \
                 :: "r"(a) : "memory")
#define T5_ALLOC(a, n) \
    asm volatile("tcgen05.alloc.cta_group::1.sync.aligned.shared::cta.b32 [%0], %1;" \
                 :: "r"(a), "r"(n) : "memory")
#define T5_DEALLOC(t, n) \
    asm volatile("tcgen05.dealloc.cta_group::1.sync.aligned.b32 %0, %1;" :: "r"(t), "r"(n))
#define T5_RELINQ() \
    asm volatile("tcgen05.relinquish_alloc_permit.cta_group::1.sync.aligned;")
#define T5_WAIT_LD()   asm volatile("tcgen05.wait::ld.sync.aligned;" ::: "memory")
#define T5_FENCE_AFTER() asm volatile("tcgen05.fence::after_thread_sync;" ::: "memory")
#define T5_FENCE_BEFORE() asm volatile("tcgen05.fence::before_thread_sync;" ::: "memory")
#define FENCE_ASYNC()  asm volatile("fence.proxy.async.shared::cta;" ::: "memory")
#define CP_ASYNC16(dst, src) \
    asm volatile("cp.async.cg.shared.global [%0], [%1], 16;" \
                 :: "r"(dst), "l"(src) : "memory")
#define CP_COMMIT() asm volatile("cp.async.commit_group;" ::: "memory")
#define CP_WAIT(n)  asm volatile("cp.async.wait_group %0;" :: "n"(n) : "memory")

#define LDTM_X32(r, addr) \
    asm volatile("tcgen05.ld.sync.aligned.32x32b.x32.b32 " \
        "{%0, %1, %2, %3, %4, %5, %6, %7, %8, %9, %10, %11, %12, %13, %14, %15, " \
        "%16, %17, %18, %19, %20, %21, %22, %23, %24, %25, %26, %27, %28, %29, %30, %31}, [%32];" \
        : "=r"((r)[0]),  "=r"((r)[1]),  "=r"((r)[2]),  "=r"((r)[3]), \
          "=r"((r)[4]),  "=r"((r)[5]),  "=r"((r)[6]),  "=r"((r)[7]), \
          "=r"((r)[8]),  "=r"((r)[9]),  "=r"((r)[10]), "=r"((r)[11]), \
          "=r"((r)[12]), "=r"((r)[13]), "=r"((r)[14]), "=r"((r)[15]), \
          "=r"((r)[16]), "=r"((r)[17]), "=r"((r)[18]), "=r"((r)[19]), \
          "=r"((r)[20]), "=r"((r)[21]), "=r"((r)[22]), "=r"((r)[23]), \
          "=r"((r)[24]), "=r"((r)[25]), "=r"((r)[26]), "=r"((r)[27]), \
          "=r"((r)[28]), "=r"((r)[29]), "=r"((r)[30]), "=r"((r)[31]) \
        : "r"(addr))

__device__ __forceinline__ void mma_f16(uint32_t d, uint64_t ad, uint64_t bd,
                                        uint32_t idesc, uint32_t en) {
    asm volatile("{\n\t.reg .pred p;\n\tsetp.ne.u32 p, %4, 0;\n\t"
        "tcgen05.mma.cta_group::1.kind::f16 [%0], %1, %2, %3, p;\n\t}"
        :: "r"(d), "l"(ad), "l"(bd), "r"(idesc), "r"(en) : "memory");
}
__device__ __forceinline__ uint64_t mk_desc(uint32_t addr) {
    return ((uint64_t)2 << 61) | ((uint64_t)1 << 46) | ((uint64_t)64 << 32)
         | ((uint64_t)1 << 16) | ((addr >> 4) & 0x3FFF);
}
__device__ __forceinline__ void sts128(uint32_t addr, uint32_t a, uint32_t b,
                                       uint32_t c, uint32_t d) {
    asm volatile("st.shared.v4.b32 [%0], {%1,%2,%3,%4};"
                 :: "r"(addr), "r"(a), "r"(b), "r"(c), "r"(d) : "memory");
}
struct MmaCtx { uint32_t mb, mb_done, tmem, tiles; };
__device__ __forceinline__ MmaCtx mma_begin(char* smem, int ncols) {
    MmaCtx cx;
    uint32_t sbase = smem_u32(smem);
    cx.mb = sbase;
    cx.mb_done = sbase + 24;
    cx.tiles = (sbase + 64 + 1023) & ~1023u;
    if (threadIdx.x == 0) {
        MBAR_INIT(cx.mb + 0, 1);
        MBAR_INIT(cx.mb + 8, 1);
        MBAR_INIT(cx.mb + 16, 1);
        MBAR_INIT(cx.mb_done, 1);
    }
    if (threadIdx.x < 32) { T5_ALLOC(sbase + 32, ncols); T5_RELINQ(); }
    __syncthreads();
    asm volatile("ld.shared.b32 %0, [%1];" : "=r"(cx.tmem) : "r"(sbase + 32));
    return cx;
}
// 12 MMAs (hh, hl, lh) for one K=64 chunk
__device__ __forceinline__ void mma_chunk(uint32_t tmem, uint32_t mbar,
                                          uint64_t ah, uint64_t al,
                                          uint64_t bh, uint64_t bl,
                                          uint32_t idesc, bool first) {
    if (threadIdx.x < 32 && elect1()) {
        #pragma unroll
        for (int q = 0; q < 4; q++)
            mma_f16(tmem, ah + 2*q, bh + 2*q, idesc, (first && q == 0) ? 0u : 1u);
        #pragma unroll
        for (int q = 0; q < 4; q++)
            mma_f16(tmem, ah + 2*q, bl + 2*q, idesc, 1u);
        #pragma unroll
        for (int q = 0; q < 4; q++)
            mma_f16(tmem, al + 2*q, bh + 2*q, idesc, 1u);
        T5_COMMIT(mbar);
    }
}

// ---------------- GEMM mainloop: cp.async 3-deep prefetch ---------------
__device__ __forceinline__ void issue_chunk_cp(
    const __half* const psrc[4], int K, int k0, uint32_t st)
{
    constexpr int T_BYTES = 128 * 128;
    const int tid = threadIdx.x;
    #pragma unroll
    for (int i = 0; i < 16; i++) {
        int u = i * 256 + tid;
        int t = u >> 10, ul = u & 1023;
        int row = ul >> 3, seg = ul & 7;
        uint32_t bofs = row * 128 + seg * 16;
        uint32_t da = st + t * T_BYTES + (bofs ^ ((bofs >> 3) & 0x70));
        CP_ASYNC16(da, psrc[t] + (size_t)row * K + k0 + seg * 8);
    }
    CP_COMMIT();
}

__device__ __forceinline__ MmaCtx gemm_main(
    const __half* Ah, const __half* Al,
    const __half* Bh, const __half* Bl, int K)
{
    constexpr int T_BYTES = 128 * 128;
    constexpr int STAGE = 4 * T_BYTES;
    extern __shared__ char smem[];
    MmaCtx cx = mma_begin(smem, 128);
    const int tid = threadIdx.x;
    const uint32_t idesc = (1u << 4) | (16u << 17) | (8u << 24);
    const int nc = K >> 6;
    const __half* psrc[4] = {Ah, Al, Bh, Bl};

    // prologue: prefetch up to 3 chunks
    const int pre = nc < 3 ? nc : 3;
    for (int c = 0; c < pre; c++)
        issue_chunk_cp(psrc, K, c * 64, cx.tiles + c * STAGE);

    for (int c = 0; c < nc; c++) {
        const int s = c - (c / 3) * 3;
        const uint32_t st = cx.tiles + s * STAGE;
        const int rem = nc - 1 - c;      // groups issued after chunk c
        if (rem >= 2)      CP_WAIT(2);
        else if (rem == 1) CP_WAIT(1);
        else               CP_WAIT(0);
        FENCE_ASYNC();
        __syncthreads();
        mma_chunk(cx.tmem, cx.mb + 8 * s,
                  mk_desc(st), mk_desc(st + T_BYTES),
                  mk_desc(st + 2 * T_BYTES), mk_desc(st + 3 * T_BYTES),
                  idesc, c == 0);
        const int cn = c + 3;
        if (cn < nc) {
            MBAR_WAIT(cx.mb + 8 * s, (c / 3) & 1);   // MMA(c) done -> stage free
            issue_chunk_cp(psrc, K, cn * 64, st);
        }
    }
    if (tid < 32 && elect1()) T5_COMMIT(cx.mb_done);
    MBAR_WAIT(cx.mb_done, 0);
    T5_FENCE_AFTER();
    return cx;
}
#else
// fallback accumulate helper (compile-only on plain targets)
__device__ __forceinline__ float dot_hl(
    const __half* Ah, const __half* Al,
    const __half* Bh, const __half* Bl, int K, int r, int c)
{
    float acc = 0.f;
    for (int k = 0; k < K; k++)
        acc += (__half2float(Ah[(size_t)r*K+k]) + __half2float(Al[(size_t)r*K+k]))
             * (__half2float(Bh[(size_t)c*K+k]) + __half2float(Bl[(size_t)c*K+k]));
    return acc;
}
#endif

// ---------------- producers ----------------
__global__ __launch_bounds__(256) void split_x_kernel(
    const float* __restrict__ x, __half* __restrict__ xh, __half* __restrict__ xl)
{
    size_t i = (size_t)(blockIdx.x * 256 + threadIdx.x) * 4;
    float4 v = *reinterpret_cast<const float4*>(&x[i]);
    uint32_t h0, l0, h1, l1;
    split_pair(v.x, v.y, h0, l0);
    split_pair(v.z, v.w, h1, l1);
    *reinterpret_cast<uint2*>(&xh[i]) = make_uint2(h0, h1);
    *reinterpret_cast<uint2*>(&xl[i]) = make_uint2(l0, l1);
}

struct TSJob { const float* W; __half* H; __half* L; int K; int N; int tile0; };
struct TSJobs { TSJob a[8]; };

__global__ __launch_bounds__(256) void tsplit_all_kernel(TSJobs jobs)
{
    __shared__ float t[32][33];
    int bx = blockIdx.x;
    int ji = 0;
    #pragma unroll
    for (int i = 1; i < 8; i++)
        if (bx >= jobs.a[i].tile0) ji = i;
    TSJob j = jobs.a[ji];
    int tl = bx - j.tile0;
    int ntN = j.N >> 5;
    int n0 = (tl % ntN) * 32, k0 = (tl / ntN) * 32;
    int tx = threadIdx.x & 31, ty = threadIdx.x >> 5;
    #pragma unroll
    for (int i = ty; i < 32; i += 8)
        t[i][tx] = j.W[(size_t)(k0 + i) * j.N + n0 + tx];
    __syncthreads();
    #pragma unroll
    for (int i = ty; i < 32; i += 8) {
        float v = t[tx][i];
        __half h = __float2half_rn(v);
        j.H[(size_t)(n0 + i) * j.K + k0 + tx] = h;
        j.L[(size_t)(n0 + i) * j.K + k0 + tx] = __float2half_rn(v - __half2float(h));
    }
}

// ---------------- xproj: cKV | cQ | KR(+rope) ----------------
__global__ __launch_bounds__(256) void xproj_kernel(
    const __half* __restrict__ xh, const __half* __restrict__ xl,
    const __half* __restrict__ WtH, const __half* __restrict__ WtL,
    const float* __restrict__ freqs,
    float* __restrict__ cKVf, __half* __restrict__ cKVh, __half* __restrict__ cKVl,
    __half* __restrict__ cQh, __half* __restrict__ cQl,
    float* __restrict__ KRo, __half* __restrict__ Krh, __half* __restrict__ Krl)
{
    const int bx = blockIdx.x, bm = blockIdx.y * 128;
#if HAS_TCGEN05
    const __half* Ah = xh + (size_t)bm * DM;
    const __half* Al = xl + (size_t)bm * DM;
    size_t bo = (bx < 4) ? O_DKV + (size_t)(bx * 128) * DM
              : (bx < 12) ? O_DQ + (size_t)((bx - 4) * 128) * DM
              : (size_t)O_KRP;
    MmaCtx cx = gemm_main(Ah, Al, WtH + bo, WtL + bo, DM);

    const int w = threadIdx.x >> 5, l2 = threadIdx.x & 31;
    const int sub = w & 3, halfi = w >> 2;
    const int rowl = sub * 32 + l2;
    const int m = bm + rowl;
    if (bx < 12) {
        for (int b2 = halfi * 2; b2 < halfi * 2 + 2; b2++) {
            uint32_t r[32];
            LDTM_X32(r, cx.tmem + b2 * 32);
            T5_WAIT_LD();
            if (bx < 4) {
                size_t off = (size_t)m * KVL + bx * 128 + b2 * 32;
                #pragma unroll
                for (int j = 0; j < 32; j += 4)
                    *reinterpret_cast<float4*>(&cKVf[off + j]) = make_float4(
                        __uint_as_float(r[j]), __uint_as_float(r[j+1]),
                        __uint_as_float(r[j+2]), __uint_as_float(r[j+3]));
                #pragma unroll
                for (int j = 0; j < 32; j += 8) {
                    uint4 hv, lv;
                    split_pair(__uint_as_float(r[j+0]), __uint_as_float(r[j+1]), hv.x, lv.x);
                    split_pair(__uint_as_float(r[j+2]), __uint_as_float(r[j+3]), hv.y, lv.y);
                    split_pair(__uint_as_float(r[j+4]), __uint_as_float(r[j+5]), hv.z, lv.z);
                    split_pair(__uint_as_float(r[j+6]), __uint_as_float(r[j+7]), hv.w, lv.w);
                    *reinterpret_cast<uint4*>(&cKVh[off + j]) = hv;
                    *reinterpret_cast<uint4*>(&cKVl[off + j]) = lv;
                }
            } else {
                size_t off = (size_t)m * QL + (bx - 4) * 128 + b2 * 32;
                #pragma unroll
                for (int j = 0; j < 32; j += 8) {
                    uint4 hv, lv;
                    split_pair(__uint_as_float(r[j+0]), __uint_as_float(r[j+1]), hv.x, lv.x);
                    split_pair(__uint_as_float(r[j+2]), __uint_as_float(r[j+3]), hv.y, lv.y);
                    split_pair(__uint_as_float(r[j+4]), __uint_as_float(r[j+5]), hv.z, lv.z);
                    split_pair(__uint_as_float(r[j+6]), __uint_as_float(r[j+7]), hv.w, lv.w);
                    *reinterpret_cast<uint4*>(&cQh[off + j]) = hv;
                    *reinterpret_cast<uint4*>(&cQl[off + j]) = lv;
                }
            }
        }
    } else if (halfi == 0) {
        const int t = m & (Tt - 1);
        for (int b2 = 0; b2 < 2; b2++) {
            uint32_t r[32];
            LDTM_X32(r, cx.tmem + b2 * 32);
            T5_WAIT_LD();
            #pragma unroll
            for (int j = 0; j < 32; j += 2) {
                int col = b2 * 32 + j;
                float f = freqs[t * (Rr / 2) + (col >> 1)], s, c;
                sincosf(f, &s, &c);
                float x0 = __uint_as_float(r[j]), x1 = __uint_as_float(r[j + 1]);
                float y0 = x0 * c - x1 * s, y1 = x0 * s + x1 * c;
                size_t off = (size_t)m * Rr + col;
                KRo[off] = y0;
                KRo[off + 1] = y1;
                uint32_t hi, lo;
                split_pair(y0, y1, hi, lo);
                *reinterpret_cast<uint32_t*>(&Krh[off]) = hi;
                *reinterpret_cast<uint32_t*>(&Krl[off]) = lo;
            }
        }
    }
    __syncthreads();
    if (threadIdx.x < 32) T5_DEALLOC(cx.tmem, 128);
#else
    const int tid = threadIdx.x;
    for (int e = tid; e < 128 * 128; e += 256) {
        int rr = e >> 7, cc = e & 127;
        int m = bm + rr;
        if (bx < 4) {
            float acc = dot_hl(xh + (size_t)bm*DM, xl + (size_t)bm*DM,
                               g_WtH + O_DKV + (size_t)(bx*128)*DM,
                               g_WtL + O_DKV + (size_t)(bx*128)*DM, DM, rr, cc);
            size_t off = (size_t)m * KVL + bx * 128 + cc;
            cKVf[off] = acc;
            __half h = __float2half_rn(acc);
            cKVh[off] = h;
            cKVl[off] = __float2half_rn(acc - __half2float(h));
        } else if (bx < 12) {
            float acc = dot_hl(xh + (size_t)bm*DM, xl + (size_t)bm*DM,
                               g_WtH + O_DQ + (size_t)((bx-4)*128)*DM,
                               g_WtL + O_DQ + (size_t)((bx-4)*128)*DM, DM, rr, cc);
            size_t off = (size_t)m * QL + (bx - 4) * 128 + cc;
            __half h = __float2half_rn(acc);
            cQh[off] = h;
            cQl[off] = __float2half_rn(acc - __half2float(h));
        } else if (cc < Rr && (cc & 1) == 0) {
            float x0 = dot_hl(xh + (size_t)bm*DM, xl + (size_t)bm*DM,
                              g_WtH + O_KRP, g_WtL + O_KRP, DM, rr, cc);
            float x1 = dot_hl(xh + (size_t)bm*DM, xl + (size_t)bm*DM,
                              g_WtH + O_KRP, g_WtL + O_KRP, DM, rr, cc + 1);
            int t = m & (Tt - 1);
            float f = freqs[t * (Rr / 2) + (cc >> 1)], s, c;
            sincosf(f, &s, &c);
            float y0 = x0 * c - x1 * s, y1 = x0 * s + x1 * c;
            size_t off = (size_t)m * Rr + cc;
            KRo[off] = y0; KRo[off + 1] = y1;
            __half h0 = __float2half_rn(y0), h1 = __float2half_rn(y1);
            Krh[off] = h0; Krh[off + 1] = h1;
            Krl[off] = __float2half_rn(y0 - __half2float(h0));
            Krl[off + 1] = __float2half_rn(y1 - __half2float(h1));
        }
    }
#endif
}

// ---------------- kvproj: UK -> Kc pairs | UV -> Vt pairs (transposed) ----
__global__ __launch_bounds__(256) void kvproj_kernel(
    const __half* __restrict__ cKVh, const __half* __restrict__ cKVl,
    const __half* __restrict__ WtH, const __half* __restrict__ WtL,
    __half* __restrict__ Kch, __half* __restrict__ Kcl,
    __half* __restrict__ Vth, __half* __restrict__ Vtl)
{
    const int bx = blockIdx.x, bm = blockIdx.y * 128;
#if HAS_TCGEN05
    const __half* Ah = cKVh + (size_t)bm * KVL;
    const __half* Al = cKVl + (size_t)bm * KVL;
    size_t bo = (bx < 16) ? O_UK + (size_t)(bx * 128) * KVL
                          : O_UV + (size_t)((bx - 16) * 128) * KVL;
    MmaCtx cx = gemm_main(Ah, Al, WtH + bo, WtL + bo, KVL);

    const int w = threadIdx.x >> 5, l2 = threadIdx.x & 31;
    const int sub = w & 3, halfi = w >> 2;
    const int rowl = sub * 32 + l2;
    const int m = bm + rowl;
    for (int b2 = halfi * 2; b2 < halfi * 2 + 2; b2++) {
        uint32_t r[32];
        LDTM_X32(r, cx.tmem + b2 * 32);
        T5_WAIT_LD();
        if (bx < 16) {
            size_t off = (size_t)m * HHD + bx * 128 + b2 * 32;
            #pragma unroll
            for (int j = 0; j < 32; j += 8) {
                uint4 hv, lv;
                split_pair(__uint_as_float(r[j+0]), __uint_as_float(r[j+1]), hv.x, lv.x);
                split_pair(__uint_as_float(r[j+2]), __uint_as_float(r[j+3]), hv.y, lv.y);
                split_pair(__uint_as_float(r[j+4]), __uint_as_float(r[j+5]), hv.z, lv.z);
                split_pair(__uint_as_float(r[j+6]), __uint_as_float(r[j+7]), hv.w, lv.w);
                *reinterpret_cast<uint4*>(&Kch[off + j]) = hv;
                *reinterpret_cast<uint4*>(&Kcl[off + j]) = lv;
            }
        } else {
            const int bq = m >> 11, tloc = m & (Tt - 1);
            #pragma unroll
            for (int j = 0; j < 32; j++) {
                int gcol = (bx - 16) * 128 + b2 * 32 + j;
                int hh2 = gcol >> 7, d = gcol & 127;
                float v = __uint_as_float(r[j]);
                __half vh = __float2half_rn(v);
                size_t off = ((size_t)(bq * Hh + hh2) * HD + d) * Tt + tloc;
                Vth[off] = vh;
                Vtl[off] = __float2half_rn(v - __half2float(vh));
            }
        }
    }
    __syncthreads();
    if (threadIdx.x < 32) T5_DEALLOC(cx.tmem, 128);
#else
    const int tid = threadIdx.x;
    for (int e = tid; e < 128 * 128; e += 256) {
        int rr = e >> 7, cc = e & 127;
        int m = bm + rr;
        if (bx < 16) {
            float acc = dot_hl(cKVh + (size_t)bm*KVL, cKVl + (size_t)bm*KVL,
                               g_WtH + O_UK + (size_t)(bx*128)*KVL,
                               g_WtL + O_UK + (size_t)(bx*128)*KVL, KVL, rr, cc);
            size_t off = (size_t)m * HHD + bx * 128 + cc;
            __half h = __float2half_rn(acc);
            Kch[off] = h;
            Kcl[off] = __float2half_rn(acc - __half2float(h));
        } else {
            float acc = dot_hl(cKVh + (size_t)bm*KVL, cKVl + (size_t)bm*KVL,
                               g_WtH + O_UV + (size_t)((bx-16)*128)*KVL,
                               g_WtL + O_UV + (size_t)((bx-16)*128)*KVL, KVL, rr, cc);
            int gcol = (bx - 16) * 128 + cc;
            int hh2 = gcol >> 7, d = gcol & 127;
            int bq = m >> 11, tloc = m & (Tt - 1);
            size_t off = ((size_t)(bq * Hh + hh2) * HD + d) * Tt + tloc;
            __half h = __float2half_rn(acc);
            Vth[off] = h;
            Vtl[off] = __float2half_rn(acc - __half2float(h));
        }
    }
#endif
}

// ---------------- qproj: UQ -> Qc pairs | QR -> Qr (+rope) pairs ----------
__global__ __launch_bounds__(256) void qproj_kernel(
    const __half* __restrict__ cQh, const __half* __restrict__ cQl,
    const __half* __restrict__ WtH, const __half* __restrict__ WtL,
    const float* __restrict__ freqs,
    __half* __restrict__ Qch, __half* __restrict__ Qcl,
    __half* __restrict__ Qrh, __half* __restrict__ Qrl)
{
    const int bx = blockIdx.x, bm = blockIdx.y * 128;
#if HAS_TCGEN05
    const __half* Ah = cQh + (size_t)bm * QL;
    const __half* Al = cQl + (size_t)bm * QL;
    size_t bo = (bx < 16) ? O_UQ + (size_t)(bx * 128) * QL
                          : O_QR + (size_t)((bx - 16) * 128) * QL;
    MmaCtx cx = gemm_main(Ah, Al, WtH + bo, WtL + bo, QL);

    const int w = threadIdx.x >> 5, l2 = threadIdx.x & 31;
    const int sub = w & 3, halfi = w >> 2;
    const int rowl = sub * 32 + l2;
    const int m = bm + rowl;
    const int t = m & (Tt - 1);
    for (int b2 = halfi * 2; b2 < halfi * 2 + 2; b2++) {
        uint32_t r[32];
        LDTM_X32(r, cx.tmem + b2 * 32);
        T5_WAIT_LD();
        if (bx < 16) {
            size_t off = (size_t)m * HHD + bx * 128 + b2 * 32;
            #pragma unroll
            for (int j = 0; j < 32; j += 8) {
                uint4 hv, lv;
                split_pair(__uint_as_float(r[j+0]), __uint_as_float(r[j+1]), hv.x, lv.x);
                split_pair(__uint_as_float(r[j+2]), __uint_as_float(r[j+3]), hv.y, lv.y);
                split_pair(__uint_as_float(r[j+4]), __uint_as_float(r[j+5]), hv.z, lv.z);
                split_pair(__uint_as_float(r[j+6]), __uint_as_float(r[j+7]), hv.w, lv.w);
                *reinterpret_cast<uint4*>(&Qch[off + j]) = hv;
                *reinterpret_cast<uint4*>(&Qcl[off + j]) = lv;
            }
        } else {
            #pragma unroll
            for (int j = 0; j < 32; j += 2) {
                int gcol = (bx - 16) * 128 + b2 * 32 + j;
                float f = freqs[t * (Rr / 2) + ((gcol & 63) >> 1)], s, c;
                sincosf(f, &s, &c);
                float x0 = __uint_as_float(r[j]), x1 = __uint_as_float(r[j + 1]);
                float y0 = x0 * c - x1 * s, y1 = x0 * s + x1 * c;
                uint32_t hi, lo;
                split_pair(y0, y1, hi, lo);
                size_t off = (size_t)m * HRr + gcol;
                *reinterpret_cast<uint32_t*>(&Qrh[off]) = hi;
                *reinterpret_cast<uint32_t*>(&Qrl[off]) = lo;
            }
        }
    }
    __syncthreads();
    if (threadIdx.x < 32) T5_DEALLOC(cx.tmem, 128);
#else
    const int tid = threadIdx.x;
    for (int e = tid; e < 128 * 128; e += 256) {
        int rr = e >> 7, cc = e & 127;
        int m = bm + rr;
        if (bx < 16) {
            float acc = dot_hl(cQh + (size_t)bm*QL, cQl + (size_t)bm*QL,
                               g_WtH + O_UQ + (size_t)(bx*128)*QL,
                               g_WtL + O_UQ + (size_t)(bx*128)*QL, QL, rr, cc);
            size_t off = (size_t)m * HHD + bx * 128 + cc;
            __half h = __float2half_rn(acc);
            Qch[off] = h;
            Qcl[off] = __float2half_rn(acc - __half2float(h));
        } else if ((cc & 1) == 0) {
            float x0 = dot_hl(cQh + (size_t)bm*QL, cQl + (size_t)bm*QL,
                              g_WtH + O_QR + (size_t)((bx-16)*128)*QL,
                              g_WtL + O_QR + (size_t)((bx-16)*128)*QL, QL, rr, cc);
            float x1 = dot_hl(cQh + (size_t)bm*QL, cQl + (size_t)bm*QL,
                              g_WtH + O_QR + (size_t)((bx-16)*128)*QL,
                              g_WtL + O_QR + (size_t)((bx-16)*128)*QL, QL, rr, cc + 1);
            int gcol = (bx - 16) * 128 + cc;
            int t = m & (Tt - 1);
            float f = freqs[t * (Rr / 2) + ((gcol & 63) >> 1)], s, c;
            sincosf(f, &s, &c);
            float y0 = x0 * c - x1 * s, y1 = x0 * s + x1 * c;
            size_t off = (size_t)m * HRr + gcol;
            __half h0 = __float2half_rn(y0), h1 = __float2half_rn(y1);
            Qrh[off] = h0; Qrh[off + 1] = h1;
            Qrl[off] = __float2half_rn(y0 - __half2float(h0));
            Qrl[off + 1] = __float2half_rn(y1 - __half2float(h1));
        }
    }
#endif
}

// ---------------- wo: y = AO @ W_O ----------------
__global__ __launch_bounds__(256) void wo_kernel(
    const __half* __restrict__ AOh, const __half* __restrict__ AOl,
    const __half* __restrict__ WtH, const __half* __restrict__ WtL,
    float* __restrict__ y)
{
    const int bx = blockIdx.x, bm = blockIdx.y * 128;
#if HAS_TCGEN05
    size_t bo = O_O + (size_t)(bx * 128) * HHD;
    MmaCtx cx = gemm_main(AOh + (size_t)bm * HHD, AOl + (size_t)bm * HHD,
                          WtH + bo, WtL + bo, HHD);
    const int w = threadIdx.x >> 5, l2 = threadIdx.x & 31;
    const int sub = w & 3, halfi = w >> 2;
    const int m = bm + sub * 32 + l2;
    for (int b2 = halfi * 2; b2 < halfi * 2 + 2; b2++) {
        uint32_t r[32];
        LDTM_X32(r, cx.tmem + b2 * 32);
        T5_WAIT_LD();
        size_t off = (size_t)m * DM + bx * 128 + b2 * 32;
        #pragma unroll
        for (int j = 0; j < 32; j += 4)
            *reinterpret_cast<float4*>(&y[off + j]) = make_float4(
                __uint_as_float(r[j]), __uint_as_float(r[j+1]),
                __uint_as_float(r[j+2]), __uint_as_float(r[j+3]));
    }
    __syncthreads();
    if (threadIdx.x < 32) T5_DEALLOC(cx.tmem, 128);
#else
    const int tid = threadIdx.x;
    for (int e = tid; e < 128 * 128; e += 256) {
        int rr = e >> 7, cc = e & 127;
        float acc = dot_hl(AOh + (size_t)bm*HHD, AOl + (size_t)bm*HHD,
                           g_WtH + O_O + (size_t)(bx*128)*HHD,
                           g_WtL + O_O + (size_t)(bx*128)*HHD, HHD, rr, cc);
        y[(size_t)(bm + rr) * DM + bx * 128 + cc] = acc;
    }
#endif
}

// ---------------- fused flash attention ----------------
__global__ __launch_bounds__(256) void flash_kernel(
    const __half* __restrict__ Qch, const __half* __restrict__ Qcl,
    const __half* __restrict__ Qrh, const __half* __restrict__ Qrl,
    const __half* __restrict__ Kch, const __half* __restrict__ Kcl,
    const __half* __restrict__ Krh, const __half* __restrict__ Krl,
    const __half* __restrict__ Vth, const __half* __restrict__ Vtl,
    __half* __restrict__ AOh, __half* __restrict__ AOl)
{
    const int qt = 15 - blockIdx.x, bh = blockIdx.y;
    const int tid = threadIdx.x;
    const int b = bh >> 4, h = bh & 15;
    const float scale = 0.07216878364870323f;   // 1/sqrt(192)
#if HAS_TCGEN05
    constexpr int T_BYTES = 16384;
    extern __shared__ char smem[];
    MmaCtx cx = mma_begin(smem, 256);
    const uint32_t qbase  = cx.tiles;
    const uint32_t pbase  = qbase + 6 * T_BYTES;
    const uint32_t redmax = pbase + 2 * T_BYTES;
    const uint32_t redsum = redmax + 1024;
    const uint32_t bufb   = redsum + 1024;
    const uint32_t idesc = (1u << 4) | (16u << 17) | (8u << 24);
    const uint32_t tmemS = cx.tmem, tmemO = cx.tmem + 128;
    const size_t qrow0 = (size_t)(b * Tt + qt * 128);

    {
        const __half* qsrc[6] = {
            Qch + qrow0 * HHD + h * HD,       Qcl + qrow0 * HHD + h * HD,
            Qch + qrow0 * HHD + h * HD + 64,  Qcl + qrow0 * HHD + h * HD + 64,
            Qrh + qrow0 * HRr + h * Rr,       Qrl + qrow0 * HRr + h * Rr };
        const int qstr[6] = {HHD, HHD, HHD, HHD, HRr, HRr};
        #pragma unroll
        for (int i = 0; i < 24; i++) {
            int u = i * 256 + tid;
            int t = u >> 10, ul = u & 1023;
            int row = ul >> 3, seg = ul & 7;
            uint4 v = *reinterpret_cast<const uint4*>(
                qsrc[t] + (size_t)row * qstr[t] + seg * 8);
            uint32_t bo = row * 128 + seg * 16;
            sts128(qbase + t * T_BYTES + (bo ^ ((bo >> 3) & 0x70)),
                   v.x, v.y, v.z, v.w);
        }
    }

    const int w = tid >> 5, l2 = tid & 31, sub = w & 3, halfi = w >> 2;
    const int rowl = sub * 32 + l2;
    const int qglob = qt * 128 + rowl;
    float oacc[64];
    #pragma unroll
    for (int j = 0; j < 64; j++) oacc[j] = 0.f;
    float mrow = -INFINITY, lrow = 0.f;
    int u0 = 0, u1 = 0;

    for (int kt = 0; kt <= qt; kt++) {
        const size_t krow0 = (size_t)(b * Tt + kt * 128);
        for (int c = 0; c < 3; c++) {
            const int bid = c & 1;
            int cnt = bid ? u1 : u0;
            const uint32_t st = bufb + bid * 2 * T_BYTES;
            const __half* kh = (c < 2) ? Kch + krow0 * HHD + h * HD + c * 64
                                       : Krh + krow0 * Rr;
            const __half* kl = (c < 2) ? Kcl + krow0 * HHD + h * HD + c * 64
                                       : Krl + krow0 * Rr;
            const int str = (c < 2) ? HHD : Rr;
            uint4 v[8];
            uint32_t da[8];
            #pragma unroll
            for (int i = 0; i < 8; i++) {
                int u = i * 256 + tid;
                int t = u >> 10, ul = u & 1023;
                int row = ul >> 3, seg = ul & 7;
                const __half* src = t ? kl : kh;
                v[i] = *reinterpret_cast<const uint4*>(
                    src + (size_t)row * str + seg * 8);
                uint32_t bo = row * 128 + seg * 16;
                da[i] = st + t * T_BYTES + (bo ^ ((bo >> 3) & 0x70));
            }
            if (cnt > 0) MBAR_WAIT(cx.mb + 8 * bid, (cnt - 1) & 1);
            #pragma unroll
            for (int i = 0; i < 8; i++)
                sts128(da[i], v[i].x, v[i].y, v[i].z, v[i].w);
            FENCE_ASYNC();
            __syncthreads();
            mma_chunk(tmemS, cx.mb + 8 * bid,
                      mk_desc(qbase + (2 * c) * T_BYTES),
                      mk_desc(qbase + (2 * c + 1) * T_BYTES),
                      mk_desc(st), mk_desc(st + T_BYTES), idesc, c == 0);
            if (bid) u1++; else u0++;
        }
        MBAR_WAIT(cx.mb + 0, (u0 - 1) & 1);
        T5_FENCE_AFTER();

        uint32_t sr[32];
        float sv[64];
        LDTM_X32(sr, tmemS + halfi * 64);
        T5_WAIT_LD();
        #pragma unroll
        for (int j = 0; j < 32; j++) sv[j] = __uint_as_float(sr[j]) * scale;
        LDTM_X32(sr, tmemS + halfi * 64 + 32);
        T5_WAIT_LD();
        #pragma unroll
        for (int j = 0; j < 32; j++) sv[32 + j] = __uint_as_float(sr[j]) * scale;
        T5_FENCE_BEFORE();
        if (kt == qt) {
            int cbase = kt * 128 + halfi * 64;
            #pragma unroll
            for (int j = 0; j < 64; j++)
                if (cbase + j > qglob) sv[j] = -INFINITY;
        }
        float pmax = -INFINITY;
        #pragma unroll
        for (int j = 0; j < 64; j++) pmax = fmaxf(pmax, sv[j]);
        asm volatile("st.shared.f32 [%0], %1;"
                     :: "r"(redmax + (halfi * 128 + rowl) * 4), "f"(pmax) : "memory");
        __syncthreads();
        float omax;
        asm volatile("ld.shared.f32 %0, [%1];"
                     : "=f"(omax) : "r"(redmax + ((1 - halfi) * 128 + rowl) * 4));
        float mnew = fmaxf(mrow, fmaxf(pmax, omax));
        float alpha = __expf(mrow - mnew);
        mrow = mnew;
        float psum = 0.f;
        uint32_t pw[32];
        #pragma unroll
        for (int j = 0; j < 32; j++) {
            float p0 = __expf(sv[2 * j] - mnew);
            float p1 = __expf(sv[2 * j + 1] - mnew);
            psum += p0 + p1;
            pw[j] = ((uint32_t)__half_as_ushort(__float2half_rn(p1)) << 16)
                  | __half_as_ushort(__float2half_rn(p0));
        }
        #pragma unroll
        for (int sgm = 0; sgm < 8; sgm++) {
            uint32_t bo = rowl * 128 + sgm * 16;
            sts128(pbase + halfi * T_BYTES + (bo ^ ((bo >> 3) & 0x70)),
                   pw[sgm * 4], pw[sgm * 4 + 1], pw[sgm * 4 + 2], pw[sgm * 4 + 3]);
        }
        asm volatile("st.shared.f32 [%0], %1;"
                     :: "r"(redsum + (halfi * 128 + rowl) * 4), "f"(psum) : "memory");
        FENCE_ASYNC();
        __syncthreads();
        float osum;
        asm volatile("ld.shared.f32 %0, [%1];"
                     : "=f"(osum) : "r"(redsum + ((1 - halfi) * 128 + rowl) * 4));
        lrow = lrow * alpha + psum + osum;

        for (int c = 0; c < 2; c++) {
            const int bid = c;
            int cnt = bid ? u1 : u0;
            const uint32_t st = bufb + bid * 2 * T_BYTES;
            const __half* vh = Vth + (size_t)bh * HD * Tt + kt * 128 + c * 64;
            const __half* vl = Vtl + (size_t)bh * HD * Tt + kt * 128 + c * 64;
            uint4 v[8];
            uint32_t da[8];
            #pragma unroll
            for (int i = 0; i < 8; i++) {
                int u = i * 256 + tid;
                int t = u >> 10, ul = u & 1023;
                int row = ul >> 3, seg = ul & 7;
                const __half* src = t ? vl : vh;
                v[i] = *reinterpret_cast<const uint4*>(
                    src + (size_t)row * Tt + seg * 8);
                uint32_t bo = row * 128 + seg * 16;
                da[i] = st + t * T_BYTES + (bo ^ ((bo >> 3) & 0x70));
            }
            if (cnt > 0) MBAR_WAIT(cx.mb + 8 * bid, (cnt - 1) & 1);
            #pragma unroll
            for (int i = 0; i < 8; i++)
                sts128(da[i], v[i].x, v[i].y, v[i].z, v[i].w);
            FENCE_ASYNC();
            __syncthreads();
            if (tid < 32 && elect1()) {
                uint64_t pd = mk_desc(pbase + c * T_BYTES);
                uint64_t vhd = mk_desc(st), vld = mk_desc(st + T_BYTES);
                #pragma unroll
                for (int q = 0; q < 4; q++)
                    mma_f16(tmemO, pd + 2 * q, vhd + 2 * q, idesc,
                            (c == 0 && q == 0) ? 0u : 1u);
                #pragma unroll
                for (int q = 0; q < 4; q++)
                    mma_f16(tmemO, pd + 2 * q, vld + 2 * q, idesc, 1u);
                T5_COMMIT(cx.mb + 8 * bid);
            }
            if (bid) u1++; else u0++;
        }
        MBAR_WAIT(cx.mb + 8, (u1 - 1) & 1);
        T5_FENCE_AFTER();
        LDTM_X32(sr, tmemO + halfi * 64);
        T5_WAIT_LD();
        #pragma unroll
        for (int j = 0; j < 32; j++)
            oacc[j] = oacc[j] * alpha + __uint_as_float(sr[j]);
        LDTM_X32(sr, tmemO + halfi * 64 + 32);
        T5_WAIT_LD();
        #pragma unroll
        for (int j = 0; j < 32; j++)
            oacc[32 + j] = oacc[32 + j] * alpha + __uint_as_float(sr[j]);
        T5_FENCE_BEFORE();
        __syncthreads();
    }

    const float invl = 1.0f / lrow;
    const size_t off = (size_t)(b * Tt + qt * 128 + rowl) * HHD + h * HD + halfi * 64;
    #pragma unroll
    for (int j = 0; j < 64; j += 8) {
        uint4 hv, lv;
        split_pair(oacc[j+0] * invl, oacc[j+1] * invl, hv.x, lv.x);
        split_pair(oacc[j+2] * invl, oacc[j+3] * invl, hv.y, lv.y);
        split_pair(oacc[j+4] * invl, oacc[j+5] * invl, hv.z, lv.z);
        split_pair(oacc[j+6] * invl, oacc[j+7] * invl, hv.w, lv.w);
        *reinterpret_cast<uint4*>(&AOh[off + j]) = hv;
        *reinterpret_cast<uint4*>(&AOl[off + j]) = lv;
    }
    __syncthreads();
    if (tid < 32) T5_DEALLOC(cx.tmem, 256);
#else
    for (int e = tid; e < 128 * 128; e += 256) {
        int r = e >> 7, d = e & 127;
        int qg = qt * 128 + r;
        size_t qoC = (size_t)(b * Tt + qg) * HHD + h * HD;
        size_t qoR = (size_t)(b * Tt + qg) * HRr + h * Rr;
        float m = -1e30f;
        for (int k = 0; k <= qg; k++) {
            size_t koC = (size_t)(b * Tt + k) * HHD + h * HD;
            size_t koR = (size_t)(b * Tt + k) * Rr;
            float s = 0.f;
            for (int dd = 0; dd < HD; dd++)
                s += (__half2float(Qch[qoC+dd]) + __half2float(Qcl[qoC+dd]))
                   * (__half2float(Kch[koC+dd]) + __half2float(Kcl[koC+dd]));
            for (int dd = 0; dd < Rr; dd++)
                s += (__half2float(Qrh[qoR+dd]) + __half2float(Qrl[qoR+dd]))
                   * (__half2float(Krh[koR+dd]) + __half2float(Krl[koR+dd]));
            s *= scale;
            if (s > m) m = s;
        }
        float l = 0.f, o = 0.f;
        for (int k = 0; k <= qg; k++) {
            size_t koC = (size_t)(b * Tt + k) * HHD + h * HD;
            size_t koR = (size_t)(b * Tt + k) * Rr;
            float s = 0.f;
            for (int dd = 0; dd < HD; dd++)
                s += (__half2float(Qch[qoC+dd]) + __half2float(Qcl[qoC+dd]))
                   * (__half2float(Kch[koC+dd]) + __half2float(Kcl[koC+dd]));
            for (int dd = 0; dd < Rr; dd++)
                s += (__half2float(Qrh[qoR+dd]) + __half2float(Qrl[qoR+dd]))
                   * (__half2float(Krh[koR+dd]) + __half2float(Krl[koR+dd]));
            float p = expf(s * scale - m);
            l += p;
            o += p * (__half2float(Vth[((size_t)bh*HD + d)*Tt + k])
                    + __half2float(Vtl[((size_t)bh*HD + d)*Tt + k]));
        }
        o /= l;
        size_t off = (size_t)(b * Tt + qg) * HHD + h * HD + d;
        __half hh = __float2half_rn(o);
        AOh[off] = hh;
        AOl[off] = __float2half_rn(o - __half2float(hh));
    }
#endif
}

// ---------------- launch ----------------
#define MMA_SMEM 200704
#define FLASH_SMEM 202752

extern "C" void kernel_launch(void* const* d_in, const int* in_sizes, int n_in,
                              void* d_out, int out_size)
{
    const float* x     = (const float*)d_in[0];
    const float* freqs = (const float*)d_in[1];
    const float* W_DKV = (const float*)d_in[2];
    const float* W_UK  = (const float*)d_in[3];
    const float* W_UV  = (const float*)d_in[4];
    const float* W_KR  = (const float*)d_in[5];
    const float* W_DQ  = (const float*)d_in[6];
    const float* W_UQ  = (const float*)d_in[7];
    const float* W_QR  = (const float*)d_in[8];
    const float* W_O   = (const float*)d_in[9];

    float* y   = (float*)d_out;
    float* cKV = y   + (size_t)Bb * Tt * DM;
    float* KRo = cKV + (size_t)Bb * Tt * KVL;

    __half *pxH, *pxL, *pWtH, *pWtL, *pcKVh, *pcKVl, *pcQh, *pcQl;
    __half *pQch, *pQcl, *pQrh, *pQrl, *pKch, *pKcl, *pKrh, *pKrl;
    __half *pVth, *pVtl, *pAOh, *pAOl;
    cudaGetSymbolAddress((void**)&pxH,  g_xH);
    cudaGetSymbolAddress((void**)&pxL,  g_xL);
    cudaGetSymbolAddress((void**)&pWtH, g_WtH);
    cudaGetSymbolAddress((void**)&pWtL, g_WtL);
    cudaGetSymbolAddress((void**)&pcKVh, g_cKVh);
    cudaGetSymbolAddress((void**)&pcKVl, g_cKVl);
    cudaGetSymbolAddress((void**)&pcQh, g_cQh);
    cudaGetSymbolAddress((void**)&pcQl, g_cQl);
    cudaGetSymbolAddress((void**)&pQch, g_Qch);
    cudaGetSymbolAddress((void**)&pQcl, g_Qcl);
    cudaGetSymbolAddress((void**)&pQrh, g_Qrh);
    cudaGetSymbolAddress((void**)&pQrl, g_Qrl);
    cudaGetSymbolAddress((void**)&pKch, g_Kch);
    cudaGetSymbolAddress((void**)&pKcl, g_Kcl);
    cudaGetSymbolAddress((void**)&pKrh, g_Krh);
    cudaGetSymbolAddress((void**)&pKrl, g_Krl);
    cudaGetSymbolAddress((void**)&pVth, g_Vth);
    cudaGetSymbolAddress((void**)&pVtl, g_Vtl);
    cudaGetSymbolAddress((void**)&pAOh, g_AOh);
    cudaGetSymbolAddress((void**)&pAOl, g_AOl);

    cudaFuncSetAttribute(xproj_kernel,  cudaFuncAttributeMaxDynamicSharedMemorySize, MMA_SMEM);
    cudaFuncSetAttribute(kvproj_kernel, cudaFuncAttributeMaxDynamicSharedMemorySize, MMA_SMEM);
    cudaFuncSetAttribute(qproj_kernel,  cudaFuncAttributeMaxDynamicSharedMemorySize, MMA_SMEM);
    cudaFuncSetAttribute(wo_kernel,     cudaFuncAttributeMaxDynamicSharedMemorySize, MMA_SMEM);
    cudaFuncSetAttribute(flash_kernel,  cudaFuncAttributeMaxDynamicSharedMemorySize, FLASH_SMEM);

    // #1: split x
    split_x_kernel<<<(MROWS * DM / 4) / 256, 256>>>(x, pxH, pxL);

    // #2: all weight transposes (KR padded; pad rows stay zero from static init)
    TSJobs jobs;
    int tiles = 0;
    auto addjob = [&](int i, const float* W, size_t off, int K, int N) {
        jobs.a[i] = {W, pWtH + off, pWtL + off, K, N, tiles};
        tiles += (K / 32) * (N / 32);
    };
    addjob(0, W_DKV, O_DKV, DM, KVL);
    addjob(1, W_UK,  O_UK,  KVL, HHD);
    addjob(2, W_UV,  O_UV,  KVL, HHD);
    addjob(3, W_DQ,  O_DQ,  DM, QL);
    addjob(4, W_UQ,  O_UQ,  QL, HHD);
    addjob(5, W_QR,  O_QR,  QL, HRr);
    addjob(6, W_O,   O_O,   HHD, DM);
    addjob(7, W_KR,  O_KRP, DM, Rr);
    tsplit_all_kernel<<<tiles, 256>>>(jobs);

    // #3: xproj (cKV | cQ | KR+rope)
    xproj_kernel<<<dim3(13, MROWS/128), 256, MMA_SMEM>>>(
        pxH, pxL, pWtH, pWtL, freqs, cKV, pcKVh, pcKVl, pcQh, pcQl,
        KRo, pKrh, pKrl);
    // #4: kvproj (UK -> Kc | UV -> Vt transposed)
    kvproj_kernel<<<dim3(32, MROWS/128), 256, MMA_SMEM>>>(
        pcKVh, pcKVl, pWtH, pWtL, pKch, pKcl, pVth, pVtl);
    // #5: qproj (UQ -> Qc | QR -> Qr roped)
    qproj_kernel<<<dim3(24, MROWS/128), 256, MMA_SMEM>>>(
        pcQh, pcQl, pWtH, pWtL, freqs, pQch, pQcl, pQrh, pQrl);
    // #6: fused flash attention
    flash_kernel<<<dim3(16, BH), 256, FLASH_SMEM>>>(
        pQch, pQcl, pQrh, pQrl, pKch, pKcl, pKrh, pKrl, pVth, pVtl, pAOh, pAOl);
    // #7: y = AO @ W_O
    wo_kernel<<<dim3(16, MROWS/128), 256, MMA_SMEM>>>(pAOh, pAOl, pWtH, pWtL, y);
}